// round 9
// baseline (speedup 1.0000x reference)
#include <cuda_runtime.h>
#include <math.h>

#define BS 128
#define T_STEPS 32
#define DIN 128
#define DH 128
#define NS 512
#define NTHR 1024
#define NWARP_RED 16          // reduction warps for attention (512 active lanes)
#define EPS 1e-8f
#define WLD 656               // repacked streamed-weight row stride (floats)

typedef unsigned long long ull;

// Global scratch (allocation-free rule).
__device__ float g_memU[(size_t)BS * 64 * NS];         // mem rows 64..127
__device__ float g_hr[(size_t)BS * T_STEPS * 2 * DH];  // (h,r) history
__device__ float g_xh[(size_t)BS * T_STEPS * DH];      // x@Wxh + bh
__device__ float g_Wcat[128 * WLD];                    // [Wrh(128) | Wr pad136 | Ww pad392]

// ---- shared memory layout (float offsets) ----
#define OFF_MEM   0                       // 64*512 = 32768
#define OFF_WHH   (OFF_MEM  + 32768)      // 16384
#define OFF_KP    (OFF_WHH  + 16384)      // 256  float4[64]: {kr[m],kr[m+64],kw[m],kw[m+64]}
#define OFF_EA    (OFF_KP   + 256)        // 256  float2[128]: {e[m], a[m]}
#define OFF_BIAS  (OFF_EA   + 256)        // 528
#define OFF_O     (OFF_BIAS + 528)        // 528
#define OFF_H     (OFF_O    + 528)        // 128
#define OFF_R     (OFF_H    + 128)        // 128
#define OFF_P4    (OFF_R    + 128)        // 4224 (1056 float4 partials)
#define OFF_WPRE  (OFF_P4   + 4224)       // 512
#define OFF_WR    (OFF_WPRE + 512)        // 512
#define OFF_WW    (OFF_WR   + 512)        // 512
#define OFF_WTMP  (OFF_WW   + 512)        // 512
#define OFF_REDA  (OFF_WTMP + 512)        // 16
#define OFF_REDB  (OFF_REDA + 16)         // 16
#define OFF_SCAL  (OFF_REDB + 16)         // 2
#define SMEM_FLOATS (OFF_SCAL + 2)        // 57282 floats = 229128 B (< 232448 opt-in)

// ---- f32x2 packed helpers ----
__device__ __forceinline__ ull pack2(float lo, float hi) {
    ull r; asm("mov.b64 %0, {%1, %2};" : "=l"(r) : "f"(lo), "f"(hi)); return r;
}
__device__ __forceinline__ float2 unpack2(ull v) {
    float2 r; asm("mov.b64 {%0, %1}, %2;" : "=f"(r.x), "=f"(r.y) : "l"(v)); return r;
}
__device__ __forceinline__ ull ffma2(ull a, ull b, ull c) {
    ull d; asm("fma.rn.f32x2 %0, %1, %2, %3;" : "=l"(d) : "l"(a), "l"(b), "l"(c)); return d;
}
__device__ __forceinline__ ull fmul2(ull a, ull b) {
    ull d; asm("mul.rn.f32x2 %0, %1, %2;" : "=l"(d) : "l"(a), "l"(b)); return d;
}
__device__ __forceinline__ void ffma2_f4(float4 w, ull hb, ull& a01, ull& a23) {
    a01 = ffma2(pack2(w.x, w.y), hb, a01);
    a23 = ffma2(pack2(w.z, w.w), hb, a23);
}

__device__ __forceinline__ float softplusf_(float x) {
    return x > 20.f ? x : log1pf(expf(x));
}
__device__ __forceinline__ float sigmoidf_(float x) {
    return 1.f / (1.f + expf(-x));
}
__device__ __forceinline__ float wredsum(float v) {
#pragma unroll
    for (int o = 16; o; o >>= 1) v += __shfl_xor_sync(0xffffffffu, v, o);
    return v;
}

// Prep 1: xh[b][t][j] = x_t @ Wxh + bh
__global__ void __launch_bounds__(256) k_xh(
    const float* __restrict__ x, const float* __restrict__ Wxh,
    const float* __restrict__ bh)
{
    const int b = blockIdx.x, tid = threadIdx.x;
    const float* xb = x + (size_t)b * T_STEPS * DIN;
    for (int idx = tid; idx < T_STEPS * DH; idx += 256) {
        int t = idx >> 7, j = idx & 127;
        float acc = bh[j];
        const float* xr = xb + t * DIN;
#pragma unroll 8
        for (int k = 0; k < DIN; k++) acc = fmaf(xr[k], Wxh[k * DH + j], acc);
        g_xh[(size_t)b * T_STEPS * DH + idx] = acc;
    }
}

// Prep 2: init streamed mem rows to 1e-6
__global__ void __launch_bounds__(256) k_minit()
{
    const int b = blockIdx.x, tid = threadIdx.x;
    float4 iv = make_float4(1e-6f, 1e-6f, 1e-6f, 1e-6f);
    float4* gu = reinterpret_cast<float4*>(g_memU + (size_t)b * 64 * NS);
    for (int i = tid; i < 64 * NS / 4; i += 256) gu[i] = iv;
}

// Prep 3: repack streamed weights into padded float4-aligned buffer.
__global__ void __launch_bounds__(256) k_repack(
    const float* __restrict__ Wrh, const float* __restrict__ Wr,
    const float* __restrict__ Ww)
{
    const int k = blockIdx.x, tid = threadIdx.x;
    float* dst = g_Wcat + (size_t)k * WLD;
    for (int c = tid; c < WLD; c += 256) {
        float v;
        if (c < 128)       v = Wrh[(size_t)k * 128 + c];
        else if (c < 264) { int cc = c - 128; v = (cc < 134) ? Wr[(size_t)k * 134 + cc] : 0.f; }
        else              { int cc = c - 264; v = (cc < 390) ? Ww[(size_t)k * 390 + cc] : 0.f; }
        dst[c] = v;
    }
}

__global__ void __launch_bounds__(NTHR, 1) ntm_kernel(
    const float* __restrict__ Whh,
    const float* __restrict__ br, const float* __restrict__ bw)
{
    extern __shared__ float sm[];
    float*  s_mem = sm + OFF_MEM;
    float*  s_Whh = sm + OFF_WHH;
    float4* s_kp  = (float4*)(sm + OFF_KP);
    float2* s_ea  = (float2*)(sm + OFF_EA);
    float*  s_bias= sm + OFF_BIAS;
    float*  s_o   = sm + OFF_O;
    float*  s_h   = sm + OFF_H;
    float*  s_r   = sm + OFF_R;
    float4* s_p4  = (float4*)(sm + OFF_P4);
    float*  s_p4f = sm + OFF_P4;
    float*  s_wpre= sm + OFF_WPRE;
    float*  s_wr  = sm + OFF_WR;
    float*  s_ww  = sm + OFF_WW;
    float*  s_wtmp= sm + OFF_WTMP;
    float*  s_redA= sm + OFF_REDA;
    float*  s_redB= sm + OFF_REDB;
    float*  s_scal= sm + OFF_SCAL;

    const int tid = threadIdx.x;
    const int wid = tid >> 5, lane = tid & 31;
    const int b = blockIdx.x;

    // stage Whh + padded biases
    {
        const float4* src = (const float4*)Whh;
        float4* dst = (float4*)s_Whh;
        for (int i = tid; i < 4096; i += NTHR) dst[i] = src[i];
    }
    if (tid < 528) {
        float v;
        if (tid < 134)       v = br[tid];
        else if (tid < 136)  v = 0.f;
        else if (tid < 526)  v = bw[tid - 136];
        else                 v = 0.f;
        s_bias[tid] = v;
    }
    // init smem-resident mem rows 0..63
    {
        float4 iv = make_float4(1e-6f, 1e-6f, 1e-6f, 1e-6f);
        float4* mb = (float4*)s_mem;
        for (int i = tid; i < 64 * NS / 4; i += NTHR) mb[i] = iv;
    }
    if (tid < DH) { s_h[tid] = 0.f; s_r[tid] = 0.f; }
    if (tid < NS) s_wpre[tid] = 1.f / NS;
    __syncthreads();

    float* mU = g_memU + (size_t)b * 64 * NS;
    const float* xh_b = g_xh + (size_t)b * T_STEPS * DH;
    const unsigned kp_base = (unsigned)__cvta_generic_to_shared(s_kp);

    for (int t = 0; t < T_STEPS; t++) {
        // ======== h-matvec: 1024 tasks = mat(2) x ks(16,k=8) x jq(32) ========
        {
            const int mat = tid >> 9;
            const int rem = tid & 511;
            const int ks  = rem >> 5;        // 0..15
            const int jq  = rem & 31;
            const int k0  = ks * 8;
            ull a01 = 0ull, a23 = 0ull;
            if (mat == 0) {
                const float4* Wq = (const float4*)s_Whh;
#pragma unroll
                for (int k = 0; k < 8; k++) {
                    float hv = s_h[k0 + k];
                    ffma2_f4(Wq[(k0 + k) * 32 + jq], pack2(hv, hv), a01, a23);
                }
            } else {
#pragma unroll
                for (int k = 0; k < 8; k++) {
                    float rv = s_r[k0 + k];
                    float4 w = *(const float4*)(g_Wcat + (size_t)(k0 + k) * WLD + jq * 4);
                    ffma2_f4(w, pack2(rv, rv), a01, a23);
                }
            }
            float2 lo = unpack2(a01), hi = unpack2(a23);
            s_p4[tid] = make_float4(lo.x, lo.y, hi.x, hi.y);
            __syncthreads();
            if (tid < DH) {
                int jq2 = tid >> 2, comp = tid & 3;
                float sum = xh_b[t * DH + tid];
#pragma unroll
                for (int m2 = 0; m2 < 2; m2++)
#pragma unroll
                    for (int k2 = 0; k2 < 16; k2++)
                        sum += s_p4f[(m2 * 512 + k2 * 32 + jq2) * 4 + comp];
                s_h[tid] = tanhf(sum);
            }
            __syncthreads();
        }

        // ======== o-matvec: 528 tasks = quad(132) x ks(4,k=32); LDG.128; 2 chains ========
        if (tid < 528) {
            const int ks = tid / 132;                 // 0..3
            const int q  = tid - ks * 132;
            const int col = 128 + q * 4;
            const int k0 = ks * 32;
            ull a01a = 0ull, a23a = 0ull, a01b = 0ull, a23b = 0ull;
#pragma unroll 8
            for (int k = 0; k < 32; k += 2) {
                float h0 = s_h[k0 + k], h1 = s_h[k0 + k + 1];
                float4 w0 = *(const float4*)(g_Wcat + (size_t)(k0 + k) * WLD + col);
                float4 w1 = *(const float4*)(g_Wcat + (size_t)(k0 + k + 1) * WLD + col);
                ffma2_f4(w0, pack2(h0, h0), a01a, a23a);
                ffma2_f4(w1, pack2(h1, h1), a01b, a23b);
            }
            const ull ONE2 = pack2(1.f, 1.f);
            float2 lo = unpack2(ffma2(a01b, ONE2, a01a));
            float2 hi = unpack2(ffma2(a23b, ONE2, a23a));
            s_p4[tid] = make_float4(lo.x, lo.y, hi.x, hi.y);
        }
        __syncthreads();
        // FIX (R8 bug): cover ALL 528 padded o slots (valid data up to index 525),
        // not 524 — slots 524/525 are a[126], a[127] of the write head.
        if (tid < 528) {
            int quad = tid >> 2, comp = tid & 3;
            float acc = s_bias[tid];
#pragma unroll
            for (int ks = 0; ks < 4; ks++)
                acc += s_p4f[(ks * 132 + quad) * 4 + comp];
            s_o[tid] = acc;
        }
        __syncthreads();

        // ======== keys (packed), (e,a), key norms ========
        if (tid < 64) {
            s_kp[tid] = make_float4(s_o[tid], s_o[tid + 64],
                                    s_o[136 + tid], s_o[200 + tid]);
        } else if (tid < 192) {
            int m = tid - 64;
            s_ea[m] = make_float2(sigmoidf_(s_o[270 + m]), tanhf(s_o[398 + m]));
        }
        if (wid == 30) {
            float v = 0.f;
            for (int i = lane; i < DH; i += 32) { float u = s_o[i]; v = fmaf(u, u, v); }
            v = wredsum(v);
            if (!lane) s_scal[0] = sqrtf(v);
        }
        if (wid == 31) {
            float v = 0.f;
            for (int i = lane; i < DH; i += 32) { float u = s_o[136 + i]; v = fmaf(u, u, v); }
            v = wredsum(v);
            if (!lane) s_scal[1] = sqrtf(v);
        }
        __syncthreads();

        // ======== pass A: 2 threads/slot; each covers 32 packed row-pairs ========
        {
            const int half = tid >> 9;       // 0 or 1
            const int n = tid & 511;
            const int mbase = half * 32;
            ull drP = 0ull, dwP = 0ull, nmP = 0ull;
#pragma unroll 8
            for (int mi = 0; mi < 32; mi++) {
                int m = mbase + mi;
                float v0 = s_mem[m * NS + n];
                float u0 = mU[m * NS + n];
                ull vv = pack2(v0, u0);
                ull kr2, kw2;
                asm("ld.shared.v2.b64 {%0, %1}, [%2];"
                    : "=l"(kr2), "=l"(kw2) : "r"(kp_base + m * 16));
                drP = ffma2(vv, kr2, drP);
                dwP = ffma2(vv, kw2, dwP);
                nmP = ffma2(vv, vv, nmP);
            }
            float2 drp = unpack2(drP), dwp = unpack2(dwP), nmp = unpack2(nmP);
            s_p4[tid] = make_float4(drp.x + drp.y, dwp.x + dwp.y, nmp.x + nmp.y, 0.f);
        }
        __syncthreads();

        // ======== attention (512 active lanes; upper warps cross barriers) ========
        float ev_r, ev_w, wc_r, wc_w, wg_r, w_r, wg_w;
        float g_r, gamma_r, sr0, sr1, sr2, g_w, gamma_w, sw0, sw1, sw2;
        float wraw_r, wraw_w;
        if (tid < 512) {
            float4 pa = s_p4[tid], pb = s_p4[tid + 512];
            float dr = pa.x + pb.x, dw = pa.y + pb.y;
            float nrm = sqrtf(pa.z + pb.z);
            float beta_r = softplusf_(s_o[128]);
            g_r = sigmoidf_(s_o[129]);
            gamma_r = 1.f + softplusf_(s_o[133]);
            {
                float q0 = s_o[130], q1 = s_o[131], q2 = s_o[132];
                float qm = fmaxf(q0, fmaxf(q1, q2));
                float e0 = expf(q0 - qm), e1 = expf(q1 - qm), e2 = expf(q2 - qm);
                float qs = e0 + e1 + e2;
                sr0 = e0 / qs; sr1 = e1 / qs; sr2 = e2 / qs;
            }
            float beta_w = softplusf_(s_o[264]);
            g_w = sigmoidf_(s_o[265]);
            gamma_w = 1.f + softplusf_(s_o[269]);
            {
                float q0 = s_o[266], q1 = s_o[267], q2 = s_o[268];
                float qm = fmaxf(q0, fmaxf(q1, q2));
                float e0 = expf(q0 - qm), e1 = expf(q1 - qm), e2 = expf(q2 - qm);
                float qs = e0 + e1 + e2;
                sw0 = e0 / qs; sw1 = e1 / qs; sw2 = e2 / qs;
            }
            float sc_r = beta_r * dr / (nrm * s_scal[0] + EPS);
            float sc_w = beta_w * dw / (nrm * s_scal[1] + EPS);
            ev_r = __expf(sc_r); ev_w = __expf(sc_w);
            float vr = wredsum(ev_r), vw = wredsum(ev_w);
            if (!lane) { s_redA[wid] = vr; s_redB[wid] = vw; }
        }
        __syncthreads();                                    // B1
        if (tid < 512) {
            float totr = 0.f, totw = 0.f;
#pragma unroll
            for (int i = 0; i < NWARP_RED; i++) { totr += s_redA[i]; totw += s_redB[i]; }
            wc_r = ev_r / totr; wc_w = ev_w / totw;
            wg_r = g_r * wc_r + (1.f - g_r) * s_wpre[tid];
            s_wtmp[tid] = wg_r;
        }
        __syncthreads();                                    // B2
        if (tid < 512) {
            float wt_r = sr0 * s_wtmp[(tid + 1) & (NS - 1)] + sr1 * wg_r
                       + sr2 * s_wtmp[(tid - 1) & (NS - 1)];
            wraw_r = __powf(wt_r, gamma_r);
            float v2 = wredsum(wraw_r);
            if (!lane) s_redA[wid] = v2;
        }
        __syncthreads();                                    // B3
        if (tid < 512) {
            float sumr = 0.f;
#pragma unroll
            for (int i = 0; i < NWARP_RED; i++) sumr += s_redA[i];
            w_r = wraw_r / (sumr + EPS);
            s_wr[tid] = w_r;
            wg_w = g_w * wc_w + (1.f - g_w) * w_r;
            s_wtmp[tid] = wg_w;
        }
        __syncthreads();                                    // B4
        if (tid < 512) {
            float wt_w = sw0 * s_wtmp[(tid + 1) & (NS - 1)] + sw1 * wg_w
                       + sw2 * s_wtmp[(tid - 1) & (NS - 1)];
            wraw_w = __powf(wt_w, gamma_w);
            float v3 = wredsum(wraw_w);
            if (!lane) s_redB[wid] = v3;
        }
        __syncthreads();                                    // B5
        if (tid < 512) {
            float sumw = 0.f;
#pragma unroll
            for (int i = 0; i < NWARP_RED; i++) sumw += s_redB[i];
            float w_w = wraw_w / (sumw + EPS);
            s_ww[tid] = w_w;
            s_wpre[tid] = w_w;                              // carry
        }
        __syncthreads();                                    // B6

        // ======== pass B: 32 warps x (1 smem + 1 global) row pair; f32x2 ========
        {
            ull wr01[4], wr23[4], ww01[4], ww23[4];
            {
                const float4* wrv = (const float4*)s_wr;
                const float4* wwv = (const float4*)s_ww;
#pragma unroll
                for (int c = 0; c < 4; c++) {
                    float4 a = wrv[c * 32 + lane];
                    float4 bq = wwv[c * 32 + lane];
                    wr01[c] = pack2(a.x, a.y);   wr23[c] = pack2(a.z, a.w);
                    ww01[c] = pack2(bq.x, bq.y); ww23[c] = pack2(bq.z, bq.w);
                }
            }
#pragma unroll
            for (int i = 0; i < 2; i++) {
                int ms = wid * 2 + i;
                int mg = 64 + ms;
                float2 eas = s_ea[ms];
                float2 eag = s_ea[mg];
                ull e2ns = pack2(-eas.x, -eas.x), a2s = pack2(eas.y, eas.y);
                ull e2ng = pack2(-eag.x, -eag.x), a2g = pack2(eag.y, eag.y);
                ulonglong2* rs = (ulonglong2*)(s_mem + (size_t)ms * NS);
                ulonglong2* rg = (ulonglong2*)(mU + (size_t)ms * NS);
                ull rac01 = 0ull, rac23 = 0ull;
                ull rbg01 = 0ull, rbg23 = 0ull;
#pragma unroll
                for (int c = 0; c < 4; c++) {
                    ulonglong2 vg = rg[c * 32 + lane];
                    ulonglong2 vs = rs[c * 32 + lane];
                    ull tg01 = fmul2(ww01[c], e2ng);
                    ull tg23 = fmul2(ww23[c], e2ng);
                    rbg01 = ffma2(wr01[c], vg.x, rbg01);
                    rbg23 = ffma2(wr23[c], vg.y, rbg23);
                    ull ng01 = ffma2(vg.x, tg01, vg.x);
                    ull ng23 = ffma2(vg.y, tg23, vg.y);
                    ng01 = ffma2(ww01[c], a2g, ng01);
                    ng23 = ffma2(ww23[c], a2g, ng23);
                    ulonglong2 outg; outg.x = ng01; outg.y = ng23;
                    rg[c * 32 + lane] = outg;
                    ull ts01 = fmul2(ww01[c], e2ns);
                    ull ts23 = fmul2(ww23[c], e2ns);
                    rac01 = ffma2(wr01[c], vs.x, rac01);
                    rac23 = ffma2(wr23[c], vs.y, rac23);
                    ull ns01 = ffma2(vs.x, ts01, vs.x);
                    ull ns23 = ffma2(vs.y, ts23, vs.y);
                    ns01 = ffma2(ww01[c], a2s, ns01);
                    ns23 = ffma2(ww23[c], a2s, ns23);
                    ulonglong2 outs; outs.x = ns01; outs.y = ns23;
                    rs[c * 32 + lane] = outs;
                }
                float2 p0 = unpack2(rac01), p1 = unpack2(rac23);
                float2 q0 = unpack2(rbg01), q1 = unpack2(rbg23);
                float rs_sum = wredsum(p0.x + p0.y + p1.x + p1.y);
                float rg_sum = wredsum(q0.x + q0.y + q1.x + q1.y);
                if (!lane) { s_r[ms] = rs_sum; s_r[mg] = rg_sum; }
            }
            __syncthreads();
        }

        // ---- (h, r) history ----
        if (tid < 2 * DH) {
            size_t row = (size_t)(b * T_STEPS + t);
            g_hr[row * 2 * DH + tid] = (tid < DH) ? s_h[tid] : s_r[tid - DH];
        }
        __syncthreads();
    }
}

// Y = [H | R] @ Wout + bout ; Wout staged in smem.
#define OUT_SMEM_FLOATS (32768 + 8192)
__global__ void __launch_bounds__(256) out_gemm(
    const float* __restrict__ Wout, const float* __restrict__ bout,
    float* __restrict__ out)
{
    extern __shared__ float sh[];
    float* shW = sh;            // 256 x 128
    float* As  = sh + 32768;    // 32 x 256
    const int tid = threadIdx.x, lane = tid & 31, wid = tid >> 5;
    const int rbase = blockIdx.x * 32;

    {
        float4* dst = (float4*)shW;
        const float4* src = (const float4*)Wout;
        for (int i = tid; i < 8192; i += 256) dst[i] = src[i];
        float4* dA = (float4*)As;
        const float4* sA = (const float4*)(g_hr + (size_t)rbase * 256);
        for (int i = tid; i < 2048; i += 256) dA[i] = sA[i];
    }
    __syncthreads();

    float acc[4][4];
#pragma unroll
    for (int i = 0; i < 4; i++)
#pragma unroll
        for (int j = 0; j < 4; j++) acc[i][j] = 0.f;

    const int c0 = lane * 4;
    const int r0 = wid * 4;
#pragma unroll 4
    for (int k = 0; k < 256; k++) {
        float4 wv = ((const float4*)shW)[k * 32 + lane];
#pragma unroll
        for (int i = 0; i < 4; i++) {
            float av = As[(r0 + i) * 256 + k];
            acc[i][0] = fmaf(av, wv.x, acc[i][0]);
            acc[i][1] = fmaf(av, wv.y, acc[i][1]);
            acc[i][2] = fmaf(av, wv.z, acc[i][2]);
            acc[i][3] = fmaf(av, wv.w, acc[i][3]);
        }
    }
    float4 bo = *reinterpret_cast<const float4*>(bout + c0);
#pragma unroll
    for (int i = 0; i < 4; i++) {
        float4 o4 = make_float4(acc[i][0] + bo.x, acc[i][1] + bo.y,
                                acc[i][2] + bo.z, acc[i][3] + bo.w);
        *reinterpret_cast<float4*>(out + (size_t)(rbase + r0 + i) * 128 + c0) = o4;
    }
}

extern "C" void kernel_launch(void* const* d_in, const int* in_sizes, int n_in,
                              void* d_out, int out_size)
{
    const float* x    = (const float*)d_in[0];
    const float* Wxh  = (const float*)d_in[1];
    const float* Whh  = (const float*)d_in[2];
    const float* Wrh  = (const float*)d_in[3];
    const float* bh   = (const float*)d_in[4];
    const float* Wout = (const float*)d_in[5];
    const float* bout = (const float*)d_in[6];
    const float* Wr   = (const float*)d_in[7];
    const float* br   = (const float*)d_in[8];
    const float* Ww   = (const float*)d_in[9];
    const float* bw   = (const float*)d_in[10];
    float* out = (float*)d_out;

    cudaFuncSetAttribute(ntm_kernel, cudaFuncAttributeMaxDynamicSharedMemorySize,
                         SMEM_FLOATS * sizeof(float));
    cudaFuncSetAttribute(out_gemm, cudaFuncAttributeMaxDynamicSharedMemorySize,
                         OUT_SMEM_FLOATS * sizeof(float));

    // ncu profiles absolute launch index 3 == ntm_kernel.
    k_xh<<<BS, 256>>>(x, Wxh, bh);                 // 0
    k_minit<<<BS, 256>>>();                        // 1
    k_repack<<<128, 256>>>(Wrh, Wr, Ww);           // 2
    ntm_kernel<<<BS, NTHR, SMEM_FLOATS * sizeof(float)>>>(Whh, br, bw);  // 3
    out_gemm<<<BS * T_STEPS / 32, 256, OUT_SMEM_FLOATS * sizeof(float)>>>(
        Wout, bout, out);                          // 4
}

// round 10
// speedup vs baseline: 1.0475x; 1.0475x over previous
#include <cuda_runtime.h>
#include <math.h>

#define BS 128
#define T_STEPS 32
#define DIN 128
#define DH 128
#define NS 512
#define NTHR 512
#define NWARP 16
#define EPS 1e-8f
#define WLD 656               // repacked streamed-weight row stride (floats)

typedef unsigned long long ull;

// Global scratch (allocation-free rule).
__device__ float g_memU[(size_t)BS * 64 * NS];         // mem rows 64..127
__device__ float g_hr[(size_t)BS * T_STEPS * 2 * DH];  // (h,r) history
__device__ float g_xh[(size_t)BS * T_STEPS * DH];      // x@Wxh + bh
__device__ float g_Wcat[128 * WLD];                    // [Wrh(128) | Wr pad136 | Ww pad392]

// ---- shared memory layout (float offsets) ----
#define OFF_MEM   0                       // 32768 : mem rows 0..63
#define OFF_WHH   (OFF_MEM  + 32768)      // 16384
#define OFF_KP    (OFF_WHH  + 16384)      // 256  float4[64]: {kr[m],kr[m+64],kw[m],kw[m+64]}
#define OFF_EA    (OFF_KP   + 256)        // 256  float2[128]: {e[m], a[m]}
#define OFF_BIAS  (OFF_EA   + 256)        // 528
#define OFF_O     (OFF_BIAS + 528)        // 528
#define OFF_H     (OFF_O    + 528)        // 128
#define OFF_R     (OFF_H    + 128)        // 128
#define OFF_P4    (OFF_R    + 128)        // 2048 (512 float4 partials)
#define OFF_WPRE  (OFF_P4   + 2048)       // 512
#define OFF_WR    (OFF_WPRE + 512)        // 512
#define OFF_WW    (OFF_WR   + 512)        // 512
#define OFF_WTMP  (OFF_WW   + 512)        // 512
#define OFF_REDA  (OFF_WTMP + 512)        // 16
#define OFF_REDB  (OFF_REDA + 16)         // 16
#define OFF_KNR   (OFF_REDB + 16)         // 16  key-norm partials (read head)
#define OFF_KNW   (OFF_KNR  + 16)         // 16  key-norm partials (write head)
#define OFF_EVR   (OFF_KNW  + 16)         // 512
#define OFF_EVW   (OFF_EVR  + 512)        // 512
#define OFF_NM    (OFF_EVW  + 512)        // 512 slot norms^2
#define SMEM_FLOATS (OFF_NM + 512)        // 56672 floats = 226688 B

// ---- f32x2 packed helpers ----
__device__ __forceinline__ ull pack2(float lo, float hi) {
    ull r; asm("mov.b64 %0, {%1, %2};" : "=l"(r) : "f"(lo), "f"(hi)); return r;
}
__device__ __forceinline__ float2 unpack2(ull v) {
    float2 r; asm("mov.b64 {%0, %1}, %2;" : "=f"(r.x), "=f"(r.y) : "l"(v)); return r;
}
__device__ __forceinline__ ull ffma2(ull a, ull b, ull c) {
    ull d; asm("fma.rn.f32x2 %0, %1, %2, %3;" : "=l"(d) : "l"(a), "l"(b), "l"(c)); return d;
}
__device__ __forceinline__ ull fmul2(ull a, ull b) {
    ull d; asm("mul.rn.f32x2 %0, %1, %2;" : "=l"(d) : "l"(a), "l"(b)); return d;
}
__device__ __forceinline__ void ffma2_f4(float4 w, ull hb, ull& a01, ull& a23) {
    a01 = ffma2(pack2(w.x, w.y), hb, a01);
    a23 = ffma2(pack2(w.z, w.w), hb, a23);
}

__device__ __forceinline__ float softplusf_(float x) {
    return x > 20.f ? x : log1pf(expf(x));
}
__device__ __forceinline__ float sigmoidf_(float x) {
    return 1.f / (1.f + expf(-x));
}
__device__ __forceinline__ float wredsum(float v) {
#pragma unroll
    for (int o = 16; o; o >>= 1) v += __shfl_xor_sync(0xffffffffu, v, o);
    return v;
}

// Prep 1: xh[b][t][j] = x_t @ Wxh + bh
__global__ void __launch_bounds__(256) k_xh(
    const float* __restrict__ x, const float* __restrict__ Wxh,
    const float* __restrict__ bh)
{
    const int b = blockIdx.x, tid = threadIdx.x;
    const float* xb = x + (size_t)b * T_STEPS * DIN;
    for (int idx = tid; idx < T_STEPS * DH; idx += 256) {
        int t = idx >> 7, j = idx & 127;
        float acc = bh[j];
        const float* xr = xb + t * DIN;
#pragma unroll 8
        for (int k = 0; k < DIN; k++) acc = fmaf(xr[k], Wxh[k * DH + j], acc);
        g_xh[(size_t)b * T_STEPS * DH + idx] = acc;
    }
}

// Prep 2: init streamed mem rows to 1e-6
__global__ void __launch_bounds__(256) k_minit()
{
    const int b = blockIdx.x, tid = threadIdx.x;
    float4 iv = make_float4(1e-6f, 1e-6f, 1e-6f, 1e-6f);
    float4* gu = reinterpret_cast<float4*>(g_memU + (size_t)b * 64 * NS);
    for (int i = tid; i < 64 * NS / 4; i += 256) gu[i] = iv;
}

// Prep 3: repack streamed weights into padded float4-aligned buffer.
__global__ void __launch_bounds__(256) k_repack(
    const float* __restrict__ Wrh, const float* __restrict__ Wr,
    const float* __restrict__ Ww)
{
    const int k = blockIdx.x, tid = threadIdx.x;
    float* dst = g_Wcat + (size_t)k * WLD;
    for (int c = tid; c < WLD; c += 256) {
        float v;
        if (c < 128)       v = Wrh[(size_t)k * 128 + c];
        else if (c < 264) { int cc = c - 128; v = (cc < 134) ? Wr[(size_t)k * 134 + cc] : 0.f; }
        else              { int cc = c - 264; v = (cc < 390) ? Ww[(size_t)k * 390 + cc] : 0.f; }
        dst[c] = v;
    }
}

__global__ void __launch_bounds__(NTHR, 1) ntm_kernel(
    const float* __restrict__ Whh,
    const float* __restrict__ br, const float* __restrict__ bw)
{
    extern __shared__ float sm[];
    float*  s_mem = sm + OFF_MEM;
    float*  s_Whh = sm + OFF_WHH;
    float4* s_kp  = (float4*)(sm + OFF_KP);
    float*  s_kpf = sm + OFF_KP;
    float2* s_ea  = (float2*)(sm + OFF_EA);
    float*  s_eaf = sm + OFF_EA;
    float*  s_bias= sm + OFF_BIAS;
    float*  s_o   = sm + OFF_O;
    float*  s_h   = sm + OFF_H;
    float*  s_r   = sm + OFF_R;
    float4* s_p4  = (float4*)(sm + OFF_P4);
    float*  s_p4f = sm + OFF_P4;
    float*  s_wpre= sm + OFF_WPRE;
    float*  s_wr  = sm + OFF_WR;
    float*  s_ww  = sm + OFF_WW;
    float*  s_wtmp= sm + OFF_WTMP;
    float*  s_redA= sm + OFF_REDA;
    float*  s_redB= sm + OFF_REDB;
    float*  s_knr = sm + OFF_KNR;
    float*  s_knw = sm + OFF_KNW;
    float*  s_evr = sm + OFF_EVR;
    float*  s_evw = sm + OFF_EVW;
    float*  s_nm  = sm + OFF_NM;

    const int tid = threadIdx.x;
    const int wid = tid >> 5, lane = tid & 31;
    const int b = blockIdx.x;

    // stage Whh + padded biases
    {
        const float4* src = (const float4*)Whh;
        float4* dst = (float4*)s_Whh;
        for (int i = tid; i < 4096; i += NTHR) dst[i] = src[i];
    }
    if (tid < 528) {
        float v;
        if (tid < 134)       v = br[tid];
        else if (tid < 136)  v = 0.f;
        else if (tid < 526)  v = bw[tid - 136];
        else                 v = 0.f;
        s_bias[tid] = v;
        if (tid + NTHR < 528) {}   // (NTHR=512 covers 512; handle 512..527 below)
    }
    if (tid < 16) s_bias[512 + tid] = (512 + tid < 526) ? bw[512 + tid - 136] : 0.f;
    // init smem-resident mem rows 0..63
    {
        float4 iv = make_float4(1e-6f, 1e-6f, 1e-6f, 1e-6f);
        float4* mb = (float4*)s_mem;
        for (int i = tid; i < 64 * NS / 4; i += NTHR) mb[i] = iv;
    }
    if (tid < DH) { s_h[tid] = 0.f; s_r[tid] = 0.f; }
    s_wpre[tid] = 1.f / NS;
    __syncthreads();

    float* mU = g_memU + (size_t)b * 64 * NS;
    const float* xh_b = g_xh + (size_t)b * T_STEPS * DH;
    const unsigned kp_base = (unsigned)__cvta_generic_to_shared(s_kp);

    for (int t = 0; t < T_STEPS; t++) {
        // ======== phase 1: h-matvec (threads 0-255) || slot norms (256-511) ========
        {
            if (tid < 256) {
                // history store for step t-1 (s_h/s_r stable until phase 2 / pass B)
                if (t > 0) {
                    size_t row = (size_t)(b * T_STEPS + t - 1);
                    g_hr[row * 2 * DH + tid] = (tid < DH) ? s_h[tid] : s_r[tid - DH];
                }
                const int mat = tid >> 7;          // 0: Whh*h (smem), 1: Wrh*r (L2)
                const int ks  = (tid >> 5) & 3;    // 0..3
                const int jq  = tid & 31;
                const int k0  = ks * 32;
                ull a01 = 0ull, a23 = 0ull;
                if (mat == 0) {
                    const float4* Wq = (const float4*)s_Whh;
#pragma unroll 8
                    for (int k = 0; k < 32; k++) {
                        float hv = s_h[k0 + k];
                        ffma2_f4(Wq[(k0 + k) * 32 + jq], pack2(hv, hv), a01, a23);
                    }
                } else {
#pragma unroll 8
                    for (int k = 0; k < 32; k++) {
                        float rv = s_r[k0 + k];
                        float4 w = *(const float4*)(g_Wcat + (size_t)(k0 + k) * WLD + jq * 4);
                        ffma2_f4(w, pack2(rv, rv), a01, a23);
                    }
                }
                float2 lo = unpack2(a01), hi = unpack2(a23);
                s_p4[tid] = make_float4(lo.x, lo.y, hi.x, hi.y);
            } else {
                // slot norms for slots (2p, 2p+1): sum over all 128 feature rows
                const int p2 = (tid - 256) * 2;
                ull nmS = 0ull, nmG = 0ull;
#pragma unroll 8
                for (int m = 0; m < 64; m++) {
                    ull vs = *(const ull*)(s_mem + m * NS + p2);
                    ull vg = *(const ull*)(mU + m * NS + p2);
                    nmS = ffma2(vs, vs, nmS);
                    nmG = ffma2(vg, vg, nmG);
                }
                float2 a = unpack2(nmS), c = unpack2(nmG);
                *(float2*)(s_nm + p2) = make_float2(a.x + c.x, a.y + c.y);
            }
            __syncthreads();
        }

        // ======== phase 2: h-reduce + tanh ========
        if (tid < DH) {
            int jq2 = tid >> 2, comp = tid & 3;
            float sum = xh_b[t * DH + tid];
#pragma unroll
            for (int mat = 0; mat < 2; mat++)
#pragma unroll
                for (int ks = 0; ks < 4; ks++)
                    sum += s_p4f[(mat * 128 + ks * 32 + jq2) * 4 + comp];
            s_h[tid] = tanhf(sum);
        }
        __syncthreads();

        // ======== phase 3: o-matvec (264 tasks; LDG.128; 2 chains) ========
        if (tid < 264) {
            const int q  = (tid < 132) ? tid : tid - 132;
            const int ks = (tid < 132) ? 0 : 1;
            const int col = 128 + q * 4;
            const int k0 = ks * 64;
            ull a01a = 0ull, a23a = 0ull, a01b = 0ull, a23b = 0ull;
#pragma unroll 8
            for (int k = 0; k < 64; k += 2) {
                float h0 = s_h[k0 + k], h1 = s_h[k0 + k + 1];
                float4 w0 = *(const float4*)(g_Wcat + (size_t)(k0 + k) * WLD + col);
                float4 w1 = *(const float4*)(g_Wcat + (size_t)(k0 + k + 1) * WLD + col);
                ffma2_f4(w0, pack2(h0, h0), a01a, a23a);
                ffma2_f4(w1, pack2(h1, h1), a01b, a23b);
            }
            const ull ONE2 = pack2(1.f, 1.f);
            float2 lo = unpack2(ffma2(a01b, ONE2, a01a));
            float2 hi = unpack2(ffma2(a23b, ONE2, a23a));
            s_p4[tid] = make_float4(lo.x, lo.y, hi.x, hi.y);
        }
        __syncthreads();

        // ======== phase 4: o-reduce + fused packing + key-norm partials ========
        {
            float u2r = 0.f, u2w = 0.f;
            // first column: c = tid (0..511)
            {
                const int c = tid;
                int quad = c >> 2, comp = c & 3;
                float val = s_bias[c] + s_p4f[quad * 4 + comp]
                          + s_p4f[(132 + quad) * 4 + comp];
                s_o[c] = val;
                if (c < 128) {
                    s_kpf[(c & 63) * 4 + (c >> 6)] = val;            // kr
                    u2r = val * val;
                } else if (c >= 136 && c < 264) {
                    int m = c - 136;
                    s_kpf[(m & 63) * 4 + 2 + (m >> 6)] = val;        // kw
                    u2w = val * val;
                } else if (c >= 270 && c < 398) {
                    s_eaf[(c - 270) * 2 + 0] = sigmoidf_(val);       // e
                } else if (c >= 398) {
                    s_eaf[(c - 398) * 2 + 1] = tanhf(val);           // a
                }
            }
            // second column: c2 = 512 + tid (512..527) — all in a-range or pad
            if (tid < 16) {
                const int c2 = 512 + tid;
                int quad = c2 >> 2, comp = c2 & 3;
                float val = s_bias[c2] + s_p4f[quad * 4 + comp]
                          + s_p4f[(132 + quad) * 4 + comp];
                s_o[c2] = val;
                if (c2 < 526) s_eaf[(c2 - 398) * 2 + 1] = tanhf(val);
            }
            u2r = wredsum(u2r);
            u2w = wredsum(u2w);
            if (!lane) { s_knr[wid] = u2r; s_knw[wid] = u2w; }
            __syncthreads();
        }

        // ======== phase 5: pass A (dr, dw only) + scalars + attention ========
        ull drP = 0ull, dwP = 0ull;
#pragma unroll 8
        for (int m = 0; m < 64; m++) {
            float v0 = s_mem[m * NS + tid];
            float u0 = mU[m * NS + tid];
            ull vv = pack2(v0, u0);
            ull kr2, kw2;
            asm("ld.shared.v2.b64 {%0, %1}, [%2];"
                : "=l"(kr2), "=l"(kw2) : "r"(kp_base + m * 16));
            drP = ffma2(vv, kr2, drP);
            dwP = ffma2(vv, kw2, dwP);
        }
        float2 drp = unpack2(drP), dwp = unpack2(dwP);
        float dr = drp.x + drp.y, dw = dwp.x + dwp.y;
        float nrm = sqrtf(s_nm[tid]);

        float knr, knw;
        {
            float a = 0.f, c = 0.f;
#pragma unroll
            for (int i = 0; i < NWARP; i++) { a += s_knr[i]; c += s_knw[i]; }
            knr = sqrtf(a); knw = sqrtf(c);
        }

        float beta_r = softplusf_(s_o[128]);
        float g_r = sigmoidf_(s_o[129]);
        float gamma_r = 1.f + softplusf_(s_o[133]);
        float sr0, sr1, sr2;
        {
            float q0 = s_o[130], q1 = s_o[131], q2 = s_o[132];
            float qm = fmaxf(q0, fmaxf(q1, q2));
            float e0 = expf(q0 - qm), e1 = expf(q1 - qm), e2 = expf(q2 - qm);
            float qs = e0 + e1 + e2;
            sr0 = e0 / qs; sr1 = e1 / qs; sr2 = e2 / qs;
        }
        float beta_w = softplusf_(s_o[264]);
        float g_w = sigmoidf_(s_o[265]);
        float gamma_w = 1.f + softplusf_(s_o[269]);
        float sw0, sw1, sw2;
        {
            float q0 = s_o[266], q1 = s_o[267], q2 = s_o[268];
            float qm = fmaxf(q0, fmaxf(q1, q2));
            float e0 = expf(q0 - qm), e1 = expf(q1 - qm), e2 = expf(q2 - qm);
            float qs = e0 + e1 + e2;
            sw0 = e0 / qs; sw1 = e1 / qs; sw2 = e2 / qs;
        }
        float sc_r = beta_r * dr / (nrm * knr + EPS);
        float sc_w = beta_w * dw / (nrm * knw + EPS);

        // ---- attention: 4 barriers, neighbor recompute ----
        float ev_r = __expf(sc_r), ev_w = __expf(sc_w);
        s_evr[tid] = ev_r; s_evw[tid] = ev_w;
        {
            float vr = wredsum(ev_r), vw = wredsum(ev_w);
            if (!lane) { s_redA[wid] = vr; s_redB[wid] = vw; }
        }
        __syncthreads();                                    // B1
        const int np = (tid + 1) & (NS - 1), nm1 = (tid - 1) & (NS - 1);
        float totr = 0.f, totw = 0.f;
#pragma unroll
        for (int i = 0; i < NWARP; i++) { totr += s_redA[i]; totw += s_redB[i]; }
        float inv_tr = 1.f / totr, inv_tw = 1.f / totw;
        float wc_r = ev_r * inv_tr;
        float wg   = g_r * wc_r + (1.f - g_r) * s_wpre[tid];
        float wg_p = g_r * (s_evr[np] * inv_tr) + (1.f - g_r) * s_wpre[np];
        float wg_m = g_r * (s_evr[nm1] * inv_tr) + (1.f - g_r) * s_wpre[nm1];
        float wt_r = sr0 * wg_p + sr1 * wg + sr2 * wg_m;
        float wraw_r = __powf(wt_r, gamma_r);
        s_wtmp[tid] = wraw_r;
        {
            float v = wredsum(wraw_r);
            if (!lane) s_redA[wid] = v;
        }
        __syncthreads();                                    // B2
        float sumr = 0.f;
#pragma unroll
        for (int i = 0; i < NWARP; i++) sumr += s_redA[i];
        float inv_r = 1.f / (sumr + EPS);
        float w_r = wraw_r * inv_r;
        s_wr[tid] = w_r;
        float wr_p = s_wtmp[np] * inv_r, wr_m = s_wtmp[nm1] * inv_r;
        float wc_w  = ev_w * inv_tw;
        float wgw   = g_w * wc_w + (1.f - g_w) * w_r;
        float wgw_p = g_w * (s_evw[np] * inv_tw) + (1.f - g_w) * wr_p;
        float wgw_m = g_w * (s_evw[nm1] * inv_tw) + (1.f - g_w) * wr_m;
        float wt_w = sw0 * wgw_p + sw1 * wgw + sw2 * wgw_m;
        float wraw_w = __powf(wt_w, gamma_w);
        {
            float v = wredsum(wraw_w);
            if (!lane) s_redB[wid] = v;
        }
        __syncthreads();                                    // B3
        float sumw = 0.f;
#pragma unroll
        for (int i = 0; i < NWARP; i++) sumw += s_redB[i];
        float w_w = wraw_w / (sumw + EPS);
        s_ww[tid] = w_w;
        s_wpre[tid] = w_w;                                  // carry
        __syncthreads();                                    // B4

        // ======== pass B: warp-per-row (4 smem + 4 global rows), f32x2 ========
        {
            ull wr01[4], wr23[4], ww01[4], ww23[4];
            {
                const float4* wrv = (const float4*)s_wr;
                const float4* wwv = (const float4*)s_ww;
#pragma unroll
                for (int c = 0; c < 4; c++) {
                    float4 a = wrv[c * 32 + lane];
                    float4 bq = wwv[c * 32 + lane];
                    wr01[c] = pack2(a.x, a.y);   wr23[c] = pack2(a.z, a.w);
                    ww01[c] = pack2(bq.x, bq.y); ww23[c] = pack2(bq.z, bq.w);
                }
            }
#pragma unroll
            for (int i = 0; i < 4; i++) {
                int ms = wid * 4 + i;
                int mg = 64 + ms;
                float2 eas = s_ea[ms];
                float2 eag = s_ea[mg];
                ull e2ns = pack2(-eas.x, -eas.x), a2s = pack2(eas.y, eas.y);
                ull e2ng = pack2(-eag.x, -eag.x), a2g = pack2(eag.y, eag.y);
                ulonglong2* rs = (ulonglong2*)(s_mem + (size_t)ms * NS);
                ulonglong2* rg = (ulonglong2*)(mU + (size_t)ms * NS);
                ull rac01 = 0ull, rac23 = 0ull;
                ull rbg01 = 0ull, rbg23 = 0ull;
#pragma unroll
                for (int c = 0; c < 4; c++) {
                    ulonglong2 vg = rg[c * 32 + lane];
                    ulonglong2 vs = rs[c * 32 + lane];
                    ull tg01 = fmul2(ww01[c], e2ng);
                    ull tg23 = fmul2(ww23[c], e2ng);
                    rbg01 = ffma2(wr01[c], vg.x, rbg01);
                    rbg23 = ffma2(wr23[c], vg.y, rbg23);
                    ull ng01 = ffma2(vg.x, tg01, vg.x);
                    ull ng23 = ffma2(vg.y, tg23, vg.y);
                    ng01 = ffma2(ww01[c], a2g, ng01);
                    ng23 = ffma2(ww23[c], a2g, ng23);
                    ulonglong2 outg; outg.x = ng01; outg.y = ng23;
                    rg[c * 32 + lane] = outg;
                    ull ts01 = fmul2(ww01[c], e2ns);
                    ull ts23 = fmul2(ww23[c], e2ns);
                    rac01 = ffma2(wr01[c], vs.x, rac01);
                    rac23 = ffma2(wr23[c], vs.y, rac23);
                    ull ns01 = ffma2(vs.x, ts01, vs.x);
                    ull ns23 = ffma2(vs.y, ts23, vs.y);
                    ns01 = ffma2(ww01[c], a2s, ns01);
                    ns23 = ffma2(ww23[c], a2s, ns23);
                    ulonglong2 outs; outs.x = ns01; outs.y = ns23;
                    rs[c * 32 + lane] = outs;
                }
                float2 p0 = unpack2(rac01), p1 = unpack2(rac23);
                float2 q0 = unpack2(rbg01), q1 = unpack2(rbg23);
                float rs_sum = wredsum(p0.x + p0.y + p1.x + p1.y);
                float rg_sum = wredsum(q0.x + q0.y + q1.x + q1.y);
                if (!lane) { s_r[ms] = rs_sum; s_r[mg] = rg_sum; }
            }
            __syncthreads();
        }
    }

    // final history store for t = T_STEPS-1
    if (tid < 2 * DH) {
        size_t row = (size_t)(b * T_STEPS + T_STEPS - 1);
        g_hr[row * 2 * DH + tid] = (tid < DH) ? s_h[tid] : s_r[tid - DH];
    }
}

// Y = [H | R] @ Wout + bout ; Wout staged in smem.
#define OUT_SMEM_FLOATS (32768 + 8192)
__global__ void __launch_bounds__(256) out_gemm(
    const float* __restrict__ Wout, const float* __restrict__ bout,
    float* __restrict__ out)
{
    extern __shared__ float sh[];
    float* shW = sh;            // 256 x 128
    float* As  = sh + 32768;    // 32 x 256
    const int tid = threadIdx.x, lane = tid & 31, wid = tid >> 5;
    const int rbase = blockIdx.x * 32;

    {
        float4* dst = (float4*)shW;
        const float4* src = (const float4*)Wout;
        for (int i = tid; i < 8192; i += 256) dst[i] = src[i];
        float4* dA = (float4*)As;
        const float4* sA = (const float4*)(g_hr + (size_t)rbase * 256);
        for (int i = tid; i < 2048; i += 256) dA[i] = sA[i];
    }
    __syncthreads();

    float acc[4][4];
#pragma unroll
    for (int i = 0; i < 4; i++)
#pragma unroll
        for (int j = 0; j < 4; j++) acc[i][j] = 0.f;

    const int c0 = lane * 4;
    const int r0 = wid * 4;
#pragma unroll 4
    for (int k = 0; k < 256; k++) {
        float4 wv = ((const float4*)shW)[k * 32 + lane];
#pragma unroll
        for (int i = 0; i < 4; i++) {
            float av = As[(r0 + i) * 256 + k];
            acc[i][0] = fmaf(av, wv.x, acc[i][0]);
            acc[i][1] = fmaf(av, wv.y, acc[i][1]);
            acc[i][2] = fmaf(av, wv.z, acc[i][2]);
            acc[i][3] = fmaf(av, wv.w, acc[i][3]);
        }
    }
    float4 bo = *reinterpret_cast<const float4*>(bout + c0);
#pragma unroll
    for (int i = 0; i < 4; i++) {
        float4 o4 = make_float4(acc[i][0] + bo.x, acc[i][1] + bo.y,
                                acc[i][2] + bo.z, acc[i][3] + bo.w);
        *reinterpret_cast<float4*>(out + (size_t)(rbase + r0 + i) * 128 + c0) = o4;
    }
}

extern "C" void kernel_launch(void* const* d_in, const int* in_sizes, int n_in,
                              void* d_out, int out_size)
{
    const float* x    = (const float*)d_in[0];
    const float* Wxh  = (const float*)d_in[1];
    const float* Whh  = (const float*)d_in[2];
    const float* Wrh  = (const float*)d_in[3];
    const float* bh   = (const float*)d_in[4];
    const float* Wout = (const float*)d_in[5];
    const float* bout = (const float*)d_in[6];
    const float* Wr   = (const float*)d_in[7];
    const float* br   = (const float*)d_in[8];
    const float* Ww   = (const float*)d_in[9];
    const float* bw   = (const float*)d_in[10];
    float* out = (float*)d_out;

    cudaFuncSetAttribute(ntm_kernel, cudaFuncAttributeMaxDynamicSharedMemorySize,
                         SMEM_FLOATS * sizeof(float));
    cudaFuncSetAttribute(out_gemm, cudaFuncAttributeMaxDynamicSharedMemorySize,
                         OUT_SMEM_FLOATS * sizeof(float));

    // ncu profiles absolute launch index 3 == ntm_kernel.
    k_xh<<<BS, 256>>>(x, Wxh, bh);                 // 0
    k_minit<<<BS, 256>>>();                        // 1
    k_repack<<<128, 256>>>(Wrh, Wr, Ww);           // 2
    ntm_kernel<<<BS, NTHR, SMEM_FLOATS * sizeof(float)>>>(Whh, br, bw);  // 3
    out_gemm<<<BS * T_STEPS / 32, 256, OUT_SMEM_FLOATS * sizeof(float)>>>(
        Wout, bout, out);                          // 4
}

// round 11
// speedup vs baseline: 1.1413x; 1.0895x over previous
#include <cuda_runtime.h>
#include <math.h>

#define BS 128
#define T_STEPS 32
#define DIN 128
#define DH 128
#define NS 512
#define NTHR 512
#define NWARP 16
#define EPS 1e-8f
#define WLD 656               // repacked streamed-weight row stride (floats)

typedef unsigned long long ull;

// Global scratch (allocation-free rule).
__device__ float g_memU[(size_t)BS * 64 * NS];         // mem rows 64..127
__device__ float g_hr[(size_t)BS * T_STEPS * 2 * DH];  // (h,r) history
__device__ float g_xh[(size_t)BS * T_STEPS * DH];      // x@Wxh + bh
__device__ float g_Wcat[128 * WLD];                    // [Wrh(128) | Wr pad136 | Ww pad392]

// ---- shared memory layout (float offsets) ----
#define OFF_MEM   0                       // 32768 : mem rows 0..63
#define OFF_WHH   (OFF_MEM  + 32768)      // 16384
#define OFF_KP    (OFF_WHH  + 16384)      // 256  float4[64]: {kr[m],kr[m+64],kw[m],kw[m+64]}
#define OFF_EA    (OFF_KP   + 256)        // 256  float2[128]: {e[m], a[m]}
#define OFF_BIAS  (OFF_EA   + 256)        // 528
#define OFF_O     (OFF_BIAS + 528)        // 528
#define OFF_H     (OFF_O    + 528)        // 128
#define OFF_R     (OFF_H    + 128)        // 128
#define OFF_P4    (OFF_R    + 128)        // 2048 (512 float4 partials)
#define OFF_WPRE  (OFF_P4   + 2048)       // 512
#define OFF_WR    (OFF_WPRE + 512)        // 512
#define OFF_WW    (OFF_WR   + 512)        // 512
#define OFF_WTMP  (OFF_WW   + 512)        // 512
#define OFF_EVR   (OFF_WTMP + 512)        // 512
#define OFF_EVW   (OFF_EVR  + 512)        // 512
#define OFF_REDA  (OFF_EVW  + 512)        // 16
#define OFF_REDB  (OFF_REDA + 16)         // 16
#define OFF_KNR   (OFF_REDB + 16)         // 16
#define OFF_KNW   (OFF_KNR  + 16)         // 16
#define SMEM_FLOATS (OFF_KNW + 16)        // 56160 floats = 224640 B (< 232448 opt-in)

// ---- f32x2 packed helpers ----
__device__ __forceinline__ ull pack2(float lo, float hi) {
    ull r; asm("mov.b64 %0, {%1, %2};" : "=l"(r) : "f"(lo), "f"(hi)); return r;
}
__device__ __forceinline__ float2 unpack2(ull v) {
    float2 r; asm("mov.b64 {%0, %1}, %2;" : "=f"(r.x), "=f"(r.y) : "l"(v)); return r;
}
__device__ __forceinline__ ull ffma2(ull a, ull b, ull c) {
    ull d; asm("fma.rn.f32x2 %0, %1, %2, %3;" : "=l"(d) : "l"(a), "l"(b), "l"(c)); return d;
}
__device__ __forceinline__ ull fmul2(ull a, ull b) {
    ull d; asm("mul.rn.f32x2 %0, %1, %2;" : "=l"(d) : "l"(a), "l"(b)); return d;
}
__device__ __forceinline__ void ffma2_f4(float4 w, ull hb, ull& a01, ull& a23) {
    a01 = ffma2(pack2(w.x, w.y), hb, a01);
    a23 = ffma2(pack2(w.z, w.w), hb, a23);
}

__device__ __forceinline__ float softplusf_(float x) {
    return x > 20.f ? x : log1pf(expf(x));
}
__device__ __forceinline__ float sigmoidf_(float x) {
    return 1.f / (1.f + expf(-x));
}
__device__ __forceinline__ float wredsum(float v) {
#pragma unroll
    for (int o = 16; o; o >>= 1) v += __shfl_xor_sync(0xffffffffu, v, o);
    return v;
}

// Prep 1: xh[b][t][j] = x_t @ Wxh + bh
__global__ void __launch_bounds__(256) k_xh(
    const float* __restrict__ x, const float* __restrict__ Wxh,
    const float* __restrict__ bh)
{
    const int b = blockIdx.x, tid = threadIdx.x;
    const float* xb = x + (size_t)b * T_STEPS * DIN;
    for (int idx = tid; idx < T_STEPS * DH; idx += 256) {
        int t = idx >> 7, j = idx & 127;
        float acc = bh[j];
        const float* xr = xb + t * DIN;
#pragma unroll 8
        for (int k = 0; k < DIN; k++) acc = fmaf(xr[k], Wxh[k * DH + j], acc);
        g_xh[(size_t)b * T_STEPS * DH + idx] = acc;
    }
}

// Prep 2: init streamed mem rows to 1e-6
__global__ void __launch_bounds__(256) k_minit()
{
    const int b = blockIdx.x, tid = threadIdx.x;
    float4 iv = make_float4(1e-6f, 1e-6f, 1e-6f, 1e-6f);
    float4* gu = reinterpret_cast<float4*>(g_memU + (size_t)b * 64 * NS);
    for (int i = tid; i < 64 * NS / 4; i += 256) gu[i] = iv;
}

// Prep 3: repack streamed weights into padded float4-aligned buffer.
__global__ void __launch_bounds__(256) k_repack(
    const float* __restrict__ Wrh, const float* __restrict__ Wr,
    const float* __restrict__ Ww)
{
    const int k = blockIdx.x, tid = threadIdx.x;
    float* dst = g_Wcat + (size_t)k * WLD;
    for (int c = tid; c < WLD; c += 256) {
        float v;
        if (c < 128)       v = Wrh[(size_t)k * 128 + c];
        else if (c < 264) { int cc = c - 128; v = (cc < 134) ? Wr[(size_t)k * 134 + cc] : 0.f; }
        else              { int cc = c - 264; v = (cc < 390) ? Ww[(size_t)k * 390 + cc] : 0.f; }
        dst[c] = v;
    }
}

__global__ void __launch_bounds__(NTHR, 1) ntm_kernel(
    const float* __restrict__ Whh,
    const float* __restrict__ br, const float* __restrict__ bw)
{
    extern __shared__ float sm[];
    float*  s_mem = sm + OFF_MEM;
    float*  s_Whh = sm + OFF_WHH;
    float4* s_kp  = (float4*)(sm + OFF_KP);
    float*  s_kpf = sm + OFF_KP;
    float2* s_ea  = (float2*)(sm + OFF_EA);
    float*  s_eaf = sm + OFF_EA;
    float*  s_bias= sm + OFF_BIAS;
    float*  s_o   = sm + OFF_O;
    float*  s_h   = sm + OFF_H;
    float*  s_r   = sm + OFF_R;
    float4* s_p4  = (float4*)(sm + OFF_P4);
    float*  s_p4f = sm + OFF_P4;
    float*  s_wpre= sm + OFF_WPRE;
    float*  s_wr  = sm + OFF_WR;
    float*  s_ww  = sm + OFF_WW;
    float*  s_wtmp= sm + OFF_WTMP;
    float*  s_evr = sm + OFF_EVR;
    float*  s_evw = sm + OFF_EVW;
    float*  s_redA= sm + OFF_REDA;
    float*  s_redB= sm + OFF_REDB;
    float*  s_knr = sm + OFF_KNR;
    float*  s_knw = sm + OFF_KNW;

    const int tid = threadIdx.x;
    const int wid = tid >> 5, lane = tid & 31;
    const int b = blockIdx.x;

    // stage Whh + padded biases
    {
        const float4* src = (const float4*)Whh;
        float4* dst = (float4*)s_Whh;
        for (int i = tid; i < 4096; i += NTHR) dst[i] = src[i];
    }
    {
        float v;
        if (tid < 134)       v = br[tid];
        else if (tid < 136)  v = 0.f;
        else                 v = bw[tid - 136];
        s_bias[tid] = v;
        if (tid < 16) s_bias[512 + tid] = (512 + tid < 526) ? bw[512 + tid - 136] : 0.f;
    }
    // init smem-resident mem rows 0..63
    {
        float4 iv = make_float4(1e-6f, 1e-6f, 1e-6f, 1e-6f);
        float4* mb = (float4*)s_mem;
        for (int i = tid; i < 64 * NS / 4; i += NTHR) mb[i] = iv;
    }
    if (tid < DH) { s_h[tid] = 0.f; s_r[tid] = 0.f; }
    s_wpre[tid] = 1.f / NS;
    __syncthreads();

    float* mU = g_memU + (size_t)b * 64 * NS;
    const float* xh_b = g_xh + (size_t)b * T_STEPS * DH;
    const unsigned kp_base = (unsigned)__cvta_generic_to_shared(s_kp);

    for (int t = 0; t < T_STEPS; t++) {
        // ======== P1: h-matvec (512 tasks) + folded history store of t-1 ========
        {
            if (t > 0 && tid < 2 * DH) {
                size_t row = (size_t)(b * T_STEPS + t - 1);
                g_hr[row * 2 * DH + tid] = (tid < DH) ? s_h[tid] : s_r[tid - DH];
            }
            const int mat = tid >> 8;
            const int rem = tid & 255;
            const int ks  = rem >> 5;
            const int jq  = rem & 31;
            const int k0  = ks * 16;
            ull a01 = 0ull, a23 = 0ull;
            if (mat == 0) {
                const float4* Wq = (const float4*)s_Whh;
#pragma unroll
                for (int k = 0; k < 16; k++) {
                    float hv = s_h[k0 + k];
                    ffma2_f4(Wq[(k0 + k) * 32 + jq], pack2(hv, hv), a01, a23);
                }
            } else {
#pragma unroll
                for (int k = 0; k < 16; k++) {
                    float rv = s_r[k0 + k];
                    float4 w = *(const float4*)(g_Wcat + (size_t)(k0 + k) * WLD + jq * 4);
                    ffma2_f4(w, pack2(rv, rv), a01, a23);
                }
            }
            float2 lo = unpack2(a01), hi = unpack2(a23);
            s_p4[tid] = make_float4(lo.x, lo.y, hi.x, hi.y);
            __syncthreads();
            // ======== P2: h-reduce + tanh ========
            if (tid < DH) {
                int jq2 = tid >> 2, comp = tid & 3;
                float sum = xh_b[t * DH + tid];
#pragma unroll
                for (int m2 = 0; m2 < 2; m2++)
#pragma unroll
                    for (int k2 = 0; k2 < 8; k2++)
                        sum += s_p4f[(m2 * 256 + k2 * 32 + jq2) * 4 + comp];
                s_h[tid] = tanhf(sum);
            }
            __syncthreads();
        }

        // ======== P3: o-matvec (264 tasks; LDG.128; interleaved chains) ========
        if (tid < 264) {
            const int q  = (tid < 132) ? tid : tid - 132;
            const int ks = (tid < 132) ? 0 : 1;
            const int col = 128 + q * 4;
            const int k0 = ks * 64;
            ull a01a = 0ull, a23a = 0ull, a01b = 0ull, a23b = 0ull;
#pragma unroll 8
            for (int k = 0; k < 64; k += 2) {
                float h0 = s_h[k0 + k], h1 = s_h[k0 + k + 1];
                float4 w0 = *(const float4*)(g_Wcat + (size_t)(k0 + k) * WLD + col);
                float4 w1 = *(const float4*)(g_Wcat + (size_t)(k0 + k + 1) * WLD + col);
                ffma2_f4(w0, pack2(h0, h0), a01a, a23a);
                ffma2_f4(w1, pack2(h1, h1), a01b, a23b);
            }
            const ull ONE2 = pack2(1.f, 1.f);
            float2 lo = unpack2(ffma2(a01b, ONE2, a01a));
            float2 hi = unpack2(ffma2(a23b, ONE2, a23a));
            s_p4[tid] = make_float4(lo.x, lo.y, hi.x, hi.y);
        }
        __syncthreads();

        // ======== P4: o-reduce + fused packing + key-norm partials ========
        {
            float u2r = 0.f, u2w = 0.f;
            {
                const int c = tid;
                int quad = c >> 2, comp = c & 3;
                float val = s_bias[c] + s_p4f[quad * 4 + comp]
                          + s_p4f[(132 + quad) * 4 + comp];
                s_o[c] = val;
                if (c < 128) {
                    s_kpf[(c & 63) * 4 + (c >> 6)] = val;            // kr
                    u2r = val * val;
                } else if (c >= 136 && c < 264) {
                    int m = c - 136;
                    s_kpf[(m & 63) * 4 + 2 + (m >> 6)] = val;        // kw
                    u2w = val * val;
                } else if (c >= 270 && c < 398) {
                    s_eaf[(c - 270) * 2 + 0] = sigmoidf_(val);       // e
                } else if (c >= 398) {
                    s_eaf[(c - 398) * 2 + 1] = tanhf(val);           // a
                }
            }
            if (tid < 16) {
                const int c2 = 512 + tid;
                int quad = c2 >> 2, comp = c2 & 3;
                float val = s_bias[c2] + s_p4f[quad * 4 + comp]
                          + s_p4f[(132 + quad) * 4 + comp];
                s_o[c2] = val;
                if (c2 < 526) s_eaf[(c2 - 398) * 2 + 1] = tanhf(val);
            }
            u2r = wredsum(u2r);
            u2w = wredsum(u2w);
            if (!lane) { s_knr[wid] = u2r; s_knw[wid] = u2w; }
            __syncthreads();
        }

        // ======== P5: pass A (dr, dw, nm) + scalars + attention (4 barriers) ========
        ull drP = 0ull, dwP = 0ull, nmP = 0ull;
#pragma unroll 8
        for (int m = 0; m < 64; m++) {
            float v0 = s_mem[m * NS + tid];
            float u0 = mU[m * NS + tid];
            ull vv = pack2(v0, u0);
            ull kr2, kw2;
            asm("ld.shared.v2.b64 {%0, %1}, [%2];"
                : "=l"(kr2), "=l"(kw2) : "r"(kp_base + m * 16));
            drP = ffma2(vv, kr2, drP);
            dwP = ffma2(vv, kw2, dwP);
            nmP = ffma2(vv, vv, nmP);
        }
        float2 drp = unpack2(drP), dwp = unpack2(dwP), nmp = unpack2(nmP);
        float dr = drp.x + drp.y, dw = dwp.x + dwp.y;
        float nrm = sqrtf(nmp.x + nmp.y);

        float knr, knw;
        {
            float a = 0.f, c = 0.f;
#pragma unroll
            for (int i = 0; i < NWARP; i++) { a += s_knr[i]; c += s_knw[i]; }
            knr = sqrtf(a); knw = sqrtf(c);
        }

        float beta_r = softplusf_(s_o[128]);
        float g_r = sigmoidf_(s_o[129]);
        float gamma_r = 1.f + softplusf_(s_o[133]);
        float sr0, sr1, sr2;
        {
            float q0 = s_o[130], q1 = s_o[131], q2 = s_o[132];
            float qm = fmaxf(q0, fmaxf(q1, q2));
            float e0 = expf(q0 - qm), e1 = expf(q1 - qm), e2 = expf(q2 - qm);
            float qs = e0 + e1 + e2;
            sr0 = e0 / qs; sr1 = e1 / qs; sr2 = e2 / qs;
        }
        float beta_w = softplusf_(s_o[264]);
        float g_w = sigmoidf_(s_o[265]);
        float gamma_w = 1.f + softplusf_(s_o[269]);
        float sw0, sw1, sw2;
        {
            float q0 = s_o[266], q1 = s_o[267], q2 = s_o[268];
            float qm = fmaxf(q0, fmaxf(q1, q2));
            float e0 = expf(q0 - qm), e1 = expf(q1 - qm), e2 = expf(q2 - qm);
            float qs = e0 + e1 + e2;
            sw0 = e0 / qs; sw1 = e1 / qs; sw2 = e2 / qs;
        }
        float sc_r = beta_r * dr / (nrm * knr + EPS);
        float sc_w = beta_w * dw / (nrm * knw + EPS);

        float ev_r = __expf(sc_r), ev_w = __expf(sc_w);
        s_evr[tid] = ev_r; s_evw[tid] = ev_w;
        {
            float vr = wredsum(ev_r), vw = wredsum(ev_w);
            if (!lane) { s_redA[wid] = vr; s_redB[wid] = vw; }
        }
        __syncthreads();                                    // B1
        const int np = (tid + 1) & (NS - 1), nm1 = (tid - 1) & (NS - 1);
        float totr = 0.f, totw = 0.f;
#pragma unroll
        for (int i = 0; i < NWARP; i++) { totr += s_redA[i]; totw += s_redB[i]; }
        float inv_tr = 1.f / totr, inv_tw = 1.f / totw;
        float wc_r = ev_r * inv_tr;
        float wg   = g_r * wc_r + (1.f - g_r) * s_wpre[tid];
        float wg_p = g_r * (s_evr[np] * inv_tr) + (1.f - g_r) * s_wpre[np];
        float wg_m = g_r * (s_evr[nm1] * inv_tr) + (1.f - g_r) * s_wpre[nm1];
        float wt_r = sr0 * wg_p + sr1 * wg + sr2 * wg_m;
        float wraw_r = __powf(wt_r, gamma_r);
        s_wtmp[tid] = wraw_r;
        {
            float v = wredsum(wraw_r);
            if (!lane) s_redA[wid] = v;
        }
        __syncthreads();                                    // B2
        float sumr = 0.f;
#pragma unroll
        for (int i = 0; i < NWARP; i++) sumr += s_redA[i];
        float inv_r = 1.f / (sumr + EPS);
        float w_r = wraw_r * inv_r;
        s_wr[tid] = w_r;
        float wr_p = s_wtmp[np] * inv_r, wr_m = s_wtmp[nm1] * inv_r;
        float wc_w  = ev_w * inv_tw;
        float wgw   = g_w * wc_w + (1.f - g_w) * w_r;
        float wgw_p = g_w * (s_evw[np] * inv_tw) + (1.f - g_w) * wr_p;
        float wgw_m = g_w * (s_evw[nm1] * inv_tw) + (1.f - g_w) * wr_m;
        float wt_w = sw0 * wgw_p + sw1 * wgw + sw2 * wgw_m;
        float wraw_w = __powf(wt_w, gamma_w);
        {
            float v = wredsum(wraw_w);
            if (!lane) s_redB[wid] = v;
        }
        __syncthreads();                                    // B3
        float sumw = 0.f;
#pragma unroll
        for (int i = 0; i < NWARP; i++) sumw += s_redB[i];
        float w_w = wraw_w / (sumw + EPS);
        s_ww[tid] = w_w;
        s_wpre[tid] = w_w;                                  // carry
        __syncthreads();                                    // B4

        // ======== P6: pass B: warp-per-row (4 smem + 4 global rows), f32x2 ========
        {
            ull wr01[4], wr23[4], ww01[4], ww23[4];
            {
                const float4* wrv = (const float4*)s_wr;
                const float4* wwv = (const float4*)s_ww;
#pragma unroll
                for (int c = 0; c < 4; c++) {
                    float4 a = wrv[c * 32 + lane];
                    float4 bq = wwv[c * 32 + lane];
                    wr01[c] = pack2(a.x, a.y);   wr23[c] = pack2(a.z, a.w);
                    ww01[c] = pack2(bq.x, bq.y); ww23[c] = pack2(bq.z, bq.w);
                }
            }
#pragma unroll
            for (int i = 0; i < 4; i++) {
                int ms = wid * 4 + i;
                int mg = 64 + ms;
                float2 eas = s_ea[ms];
                float2 eag = s_ea[mg];
                ull e2ns = pack2(-eas.x, -eas.x), a2s = pack2(eas.y, eas.y);
                ull e2ng = pack2(-eag.x, -eag.x), a2g = pack2(eag.y, eag.y);
                ulonglong2* rs = (ulonglong2*)(s_mem + (size_t)ms * NS);
                ulonglong2* rg = (ulonglong2*)(mU + (size_t)ms * NS);
                ull rac01 = 0ull, rac23 = 0ull;
                ull rbg01 = 0ull, rbg23 = 0ull;
#pragma unroll
                for (int c = 0; c < 4; c++) {
                    ulonglong2 vg = rg[c * 32 + lane];
                    ulonglong2 vs = rs[c * 32 + lane];
                    ull tg01 = fmul2(ww01[c], e2ng);
                    ull tg23 = fmul2(ww23[c], e2ng);
                    rbg01 = ffma2(wr01[c], vg.x, rbg01);
                    rbg23 = ffma2(wr23[c], vg.y, rbg23);
                    ull ng01 = ffma2(vg.x, tg01, vg.x);
                    ull ng23 = ffma2(vg.y, tg23, vg.y);
                    ng01 = ffma2(ww01[c], a2g, ng01);
                    ng23 = ffma2(ww23[c], a2g, ng23);
                    ulonglong2 outg; outg.x = ng01; outg.y = ng23;
                    rg[c * 32 + lane] = outg;
                    ull ts01 = fmul2(ww01[c], e2ns);
                    ull ts23 = fmul2(ww23[c], e2ns);
                    rac01 = ffma2(wr01[c], vs.x, rac01);
                    rac23 = ffma2(wr23[c], vs.y, rac23);
                    ull ns01 = ffma2(vs.x, ts01, vs.x);
                    ull ns23 = ffma2(vs.y, ts23, vs.y);
                    ns01 = ffma2(ww01[c], a2s, ns01);
                    ns23 = ffma2(ww23[c], a2s, ns23);
                    ulonglong2 outs; outs.x = ns01; outs.y = ns23;
                    rs[c * 32 + lane] = outs;
                }
                float2 p0 = unpack2(rac01), p1 = unpack2(rac23);
                float2 q0 = unpack2(rbg01), q1 = unpack2(rbg23);
                float rs_sum = wredsum(p0.x + p0.y + p1.x + p1.y);
                float rg_sum = wredsum(q0.x + q0.y + q1.x + q1.y);
                if (!lane) { s_r[ms] = rs_sum; s_r[mg] = rg_sum; }
            }
            __syncthreads();
        }
    }

    // final history store for t = T_STEPS-1
    if (tid < 2 * DH) {
        size_t row = (size_t)(b * T_STEPS + T_STEPS - 1);
        g_hr[row * 2 * DH + tid] = (tid < DH) ? s_h[tid] : s_r[tid - DH];
    }
}

// Y = [H | R] @ Wout + bout ; Wout staged in smem.
#define OUT_SMEM_FLOATS (32768 + 8192)
__global__ void __launch_bounds__(256) out_gemm(
    const float* __restrict__ Wout, const float* __restrict__ bout,
    float* __restrict__ out)
{
    extern __shared__ float sh[];
    float* shW = sh;            // 256 x 128
    float* As  = sh + 32768;    // 32 x 256
    const int tid = threadIdx.x, lane = tid & 31, wid = tid >> 5;
    const int rbase = blockIdx.x * 32;

    {
        float4* dst = (float4*)shW;
        const float4* src = (const float4*)Wout;
        for (int i = tid; i < 8192; i += 256) dst[i] = src[i];
        float4* dA = (float4*)As;
        const float4* sA = (const float4*)(g_hr + (size_t)rbase * 256);
        for (int i = tid; i < 2048; i += 256) dA[i] = sA[i];
    }
    __syncthreads();

    float acc[4][4];
#pragma unroll
    for (int i = 0; i < 4; i++)
#pragma unroll
        for (int j = 0; j < 4; j++) acc[i][j] = 0.f;

    const int c0 = lane * 4;
    const int r0 = wid * 4;
#pragma unroll 4
    for (int k = 0; k < 256; k++) {
        float4 wv = ((const float4*)shW)[k * 32 + lane];
#pragma unroll
        for (int i = 0; i < 4; i++) {
            float av = As[(r0 + i) * 256 + k];
            acc[i][0] = fmaf(av, wv.x, acc[i][0]);
            acc[i][1] = fmaf(av, wv.y, acc[i][1]);
            acc[i][2] = fmaf(av, wv.z, acc[i][2]);
            acc[i][3] = fmaf(av, wv.w, acc[i][3]);
        }
    }
    float4 bo = *reinterpret_cast<const float4*>(bout + c0);
#pragma unroll
    for (int i = 0; i < 4; i++) {
        float4 o4 = make_float4(acc[i][0] + bo.x, acc[i][1] + bo.y,
                                acc[i][2] + bo.z, acc[i][3] + bo.w);
        *reinterpret_cast<float4*>(out + (size_t)(rbase + r0 + i) * 128 + c0) = o4;
    }
}

extern "C" void kernel_launch(void* const* d_in, const int* in_sizes, int n_in,
                              void* d_out, int out_size)
{
    const float* x    = (const float*)d_in[0];
    const float* Wxh  = (const float*)d_in[1];
    const float* Whh  = (const float*)d_in[2];
    const float* Wrh  = (const float*)d_in[3];
    const float* bh   = (const float*)d_in[4];
    const float* Wout = (const float*)d_in[5];
    const float* bout = (const float*)d_in[6];
    const float* Wr   = (const float*)d_in[7];
    const float* br   = (const float*)d_in[8];
    const float* Ww   = (const float*)d_in[9];
    const float* bw   = (const float*)d_in[10];
    float* out = (float*)d_out;

    cudaFuncSetAttribute(ntm_kernel, cudaFuncAttributeMaxDynamicSharedMemorySize,
                         SMEM_FLOATS * sizeof(float));
    cudaFuncSetAttribute(out_gemm, cudaFuncAttributeMaxDynamicSharedMemorySize,
                         OUT_SMEM_FLOATS * sizeof(float));

    // ncu profiles absolute launch index 3 == ntm_kernel.
    k_xh<<<BS, 256>>>(x, Wxh, bh);                 // 0
    k_minit<<<BS, 256>>>();                        // 1
    k_repack<<<128, 256>>>(Wrh, Wr, Ww);           // 2
    ntm_kernel<<<BS, NTHR, SMEM_FLOATS * sizeof(float)>>>(Whh, br, bw);  // 3
    out_gemm<<<BS * T_STEPS / 32, 256, OUT_SMEM_FLOATS * sizeof(float)>>>(
        Wout, bout, out);                          // 4
}

// round 12
// speedup vs baseline: 1.1668x; 1.0223x over previous
#include <cuda_runtime.h>
#include <math.h>

#define BS 128
#define T_STEPS 32
#define DIN 128
#define DH 128
#define NS 512
#define NTHR 512
#define NWARP 16
#define EPS 1e-8f
#define WLD 784               // repacked weights: [Whh(128)|Wrh(128)|Wr pad136|Ww pad392]
#define ROWS_S 96             // mem rows in smem
#define ROWS_G 32             // mem rows in L2

typedef unsigned long long ull;

// Global scratch (allocation-free rule).
__device__ float g_memU[(size_t)BS * ROWS_G * NS];     // mem rows 96..127
__device__ float g_hr[(size_t)BS * T_STEPS * 2 * DH];  // (h,r) history
__device__ float g_xh[(size_t)BS * T_STEPS * DH];      // x@Wxh + bh
__device__ float g_Wcat[128 * WLD];

// ---- shared memory layout (float offsets) ----
#define OFF_MEM   0                       // 96*512 = 49152
#define OFF_KP    (OFF_MEM  + 49152)      // 256  float4[64]: {kr[m],kr[m+64],kw[m],kw[m+64]}
#define OFF_EA    (OFF_KP   + 256)        // 256  float2[128]: {e[m], a[m]}
#define OFF_BIAS  (OFF_EA   + 256)        // 528
#define OFF_O     (OFF_BIAS + 528)        // 528
#define OFF_H     (OFF_O    + 528)        // 128
#define OFF_R     (OFF_H    + 128)        // 128
#define OFF_P4    (OFF_R    + 128)        // 2048 (512 float4 partials)
#define OFF_WPRE  (OFF_P4   + 2048)       // 512
#define OFF_WR    (OFF_WPRE + 512)        // 512
#define OFF_WW    (OFF_WR   + 512)        // 512
#define OFF_WTMP  (OFF_WW   + 512)        // 512
#define OFF_EVR   (OFF_WTMP + 512)        // 512
#define OFF_EVW   (OFF_EVR  + 512)        // 512
#define OFF_REDA  (OFF_EVW  + 512)        // 16
#define OFF_REDB  (OFF_REDA + 16)         // 16
#define OFF_KNR   (OFF_REDB + 16)         // 16
#define OFF_KNW   (OFF_KNR  + 16)         // 16
#define SMEM_FLOATS (OFF_KNW + 16)        // 56160 floats = 224640 B

// ---- f32x2 packed helpers ----
__device__ __forceinline__ ull pack2(float lo, float hi) {
    ull r; asm("mov.b64 %0, {%1, %2};" : "=l"(r) : "f"(lo), "f"(hi)); return r;
}
__device__ __forceinline__ float2 unpack2(ull v) {
    float2 r; asm("mov.b64 {%0, %1}, %2;" : "=f"(r.x), "=f"(r.y) : "l"(v)); return r;
}
__device__ __forceinline__ ull ffma2(ull a, ull b, ull c) {
    ull d; asm("fma.rn.f32x2 %0, %1, %2, %3;" : "=l"(d) : "l"(a), "l"(b), "l"(c)); return d;
}
__device__ __forceinline__ ull fmul2(ull a, ull b) {
    ull d; asm("mul.rn.f32x2 %0, %1, %2;" : "=l"(d) : "l"(a), "l"(b)); return d;
}
__device__ __forceinline__ void ffma2_f4(float4 w, ull hb, ull& a01, ull& a23) {
    a01 = ffma2(pack2(w.x, w.y), hb, a01);
    a23 = ffma2(pack2(w.z, w.w), hb, a23);
}

__device__ __forceinline__ float softplusf_(float x) {
    return x > 20.f ? x : log1pf(expf(x));
}
__device__ __forceinline__ float sigmoidf_(float x) {
    return 1.f / (1.f + expf(-x));
}
__device__ __forceinline__ float wredsum(float v) {
#pragma unroll
    for (int o = 16; o; o >>= 1) v += __shfl_xor_sync(0xffffffffu, v, o);
    return v;
}

// Prep 1: xh[b][t][j] = x_t @ Wxh + bh
__global__ void __launch_bounds__(256) k_xh(
    const float* __restrict__ x, const float* __restrict__ Wxh,
    const float* __restrict__ bh)
{
    const int b = blockIdx.x, tid = threadIdx.x;
    const float* xb = x + (size_t)b * T_STEPS * DIN;
    for (int idx = tid; idx < T_STEPS * DH; idx += 256) {
        int t = idx >> 7, j = idx & 127;
        float acc = bh[j];
        const float* xr = xb + t * DIN;
#pragma unroll 8
        for (int k = 0; k < DIN; k++) acc = fmaf(xr[k], Wxh[k * DH + j], acc);
        g_xh[(size_t)b * T_STEPS * DH + idx] = acc;
    }
}

// Prep 2: init streamed mem rows to 1e-6
__global__ void __launch_bounds__(256) k_minit()
{
    const int b = blockIdx.x, tid = threadIdx.x;
    float4 iv = make_float4(1e-6f, 1e-6f, 1e-6f, 1e-6f);
    float4* gu = reinterpret_cast<float4*>(g_memU + (size_t)b * ROWS_G * NS);
    for (int i = tid; i < ROWS_G * NS / 4; i += 256) gu[i] = iv;
}

// Prep 3: repack ALL in-loop weights into one padded float4-aligned buffer.
__global__ void __launch_bounds__(256) k_repack(
    const float* __restrict__ Whh, const float* __restrict__ Wrh,
    const float* __restrict__ Wr,  const float* __restrict__ Ww)
{
    const int k = blockIdx.x, tid = threadIdx.x;
    float* dst = g_Wcat + (size_t)k * WLD;
    for (int c = tid; c < WLD; c += 256) {
        float v;
        if (c < 128)       v = Whh[(size_t)k * 128 + c];
        else if (c < 256)  v = Wrh[(size_t)k * 128 + (c - 128)];
        else if (c < 392) { int cc = c - 256; v = (cc < 134) ? Wr[(size_t)k * 134 + cc] : 0.f; }
        else              { int cc = c - 392; v = (cc < 390) ? Ww[(size_t)k * 390 + cc] : 0.f; }
        dst[c] = v;
    }
}

__global__ void __launch_bounds__(NTHR, 1) ntm_kernel(
    const float* __restrict__ br, const float* __restrict__ bw)
{
    extern __shared__ float sm[];
    float*  s_mem = sm + OFF_MEM;
    float4* s_kp  = (float4*)(sm + OFF_KP);
    float*  s_kpf = sm + OFF_KP;
    float2* s_ea  = (float2*)(sm + OFF_EA);
    float*  s_eaf = sm + OFF_EA;
    float*  s_bias= sm + OFF_BIAS;
    float*  s_o   = sm + OFF_O;
    float*  s_h   = sm + OFF_H;
    float*  s_r   = sm + OFF_R;
    float4* s_p4  = (float4*)(sm + OFF_P4);
    float*  s_p4f = sm + OFF_P4;
    float*  s_wpre= sm + OFF_WPRE;
    float*  s_wr  = sm + OFF_WR;
    float*  s_ww  = sm + OFF_WW;
    float*  s_wtmp= sm + OFF_WTMP;
    float*  s_evr = sm + OFF_EVR;
    float*  s_evw = sm + OFF_EVW;
    float*  s_redA= sm + OFF_REDA;
    float*  s_redB= sm + OFF_REDB;
    float*  s_knr = sm + OFF_KNR;
    float*  s_knw = sm + OFF_KNW;

    const int tid = threadIdx.x;
    const int wid = tid >> 5, lane = tid & 31;
    const int b = blockIdx.x;

    // padded biases
    {
        float v;
        if (tid < 134)       v = br[tid];
        else if (tid < 136)  v = 0.f;
        else                 v = bw[tid - 136];
        s_bias[tid] = v;
        if (tid < 16) s_bias[512 + tid] = (512 + tid < 526) ? bw[512 + tid - 136] : 0.f;
    }
    // init smem-resident mem rows 0..95
    {
        float4 iv = make_float4(1e-6f, 1e-6f, 1e-6f, 1e-6f);
        float4* mb = (float4*)s_mem;
        for (int i = tid; i < ROWS_S * NS / 4; i += NTHR) mb[i] = iv;
    }
    if (tid < DH) { s_h[tid] = 0.f; s_r[tid] = 0.f; }
    s_wpre[tid] = 1.f / NS;
    __syncthreads();

    float* mU = g_memU + (size_t)b * ROWS_G * NS;
    const float* xh_b = g_xh + (size_t)b * T_STEPS * DH;
    const unsigned kp_base = (unsigned)__cvta_generic_to_shared(s_kp);

    for (int t = 0; t < T_STEPS; t++) {
        // ======== P1: h-matvec (512 tasks, all from L2 Wcat) + folded history ========
        {
            if (t > 0 && tid < 2 * DH) {
                size_t row = (size_t)(b * T_STEPS + t - 1);
                g_hr[row * 2 * DH + tid] = (tid < DH) ? s_h[tid] : s_r[tid - DH];
            }
            const int mat = tid >> 8;            // 0: Whh*h (cols 0-127), 1: Wrh*r (128-255)
            const int rem = tid & 255;
            const int ks  = rem >> 5;
            const int jq  = rem & 31;
            const int k0  = ks * 16;
            const int colbase = mat << 7;
            const float* v = mat ? s_r : s_h;
            ull a01 = 0ull, a23 = 0ull;
#pragma unroll
            for (int k = 0; k < 16; k++) {
                float hv = v[k0 + k];
                float4 w = *(const float4*)(g_Wcat + (size_t)(k0 + k) * WLD + colbase + jq * 4);
                ffma2_f4(w, pack2(hv, hv), a01, a23);
            }
            float2 lo = unpack2(a01), hi = unpack2(a23);
            s_p4[tid] = make_float4(lo.x, lo.y, hi.x, hi.y);
            __syncthreads();
            // ======== P2: h-reduce + tanh ========
            if (tid < DH) {
                int jq2 = tid >> 2, comp = tid & 3;
                float sum = xh_b[t * DH + tid];
#pragma unroll
                for (int m2 = 0; m2 < 2; m2++)
#pragma unroll
                    for (int k2 = 0; k2 < 8; k2++)
                        sum += s_p4f[(m2 * 256 + k2 * 32 + jq2) * 4 + comp];
                s_h[tid] = tanhf(sum);
            }
            __syncthreads();
        }

        // ======== P3: o-matvec (264 tasks; LDG.128; interleaved chains) ========
        if (tid < 264) {
            const int q  = (tid < 132) ? tid : tid - 132;
            const int ks = (tid < 132) ? 0 : 1;
            const int col = 256 + q * 4;
            const int k0 = ks * 64;
            ull a01a = 0ull, a23a = 0ull, a01b = 0ull, a23b = 0ull;
#pragma unroll 8
            for (int k = 0; k < 64; k += 2) {
                float h0 = s_h[k0 + k], h1 = s_h[k0 + k + 1];
                float4 w0 = *(const float4*)(g_Wcat + (size_t)(k0 + k) * WLD + col);
                float4 w1 = *(const float4*)(g_Wcat + (size_t)(k0 + k + 1) * WLD + col);
                ffma2_f4(w0, pack2(h0, h0), a01a, a23a);
                ffma2_f4(w1, pack2(h1, h1), a01b, a23b);
            }
            const ull ONE2 = pack2(1.f, 1.f);
            float2 lo = unpack2(ffma2(a01b, ONE2, a01a));
            float2 hi = unpack2(ffma2(a23b, ONE2, a23a));
            s_p4[tid] = make_float4(lo.x, lo.y, hi.x, hi.y);
        }
        __syncthreads();

        // ======== P4: o-reduce + fused packing + key-norm partials ========
        {
            float u2r = 0.f, u2w = 0.f;
            {
                const int c = tid;
                int quad = c >> 2, comp = c & 3;
                float val = s_bias[c] + s_p4f[quad * 4 + comp]
                          + s_p4f[(132 + quad) * 4 + comp];
                s_o[c] = val;
                if (c < 128) {
                    s_kpf[(c & 63) * 4 + (c >> 6)] = val;            // kr
                    u2r = val * val;
                } else if (c >= 136 && c < 264) {
                    int m = c - 136;
                    s_kpf[(m & 63) * 4 + 2 + (m >> 6)] = val;        // kw
                    u2w = val * val;
                } else if (c >= 270 && c < 398) {
                    s_eaf[(c - 270) * 2 + 0] = sigmoidf_(val);       // e
                } else if (c >= 398) {
                    s_eaf[(c - 398) * 2 + 1] = tanhf(val);           // a
                }
            }
            if (tid < 16) {
                const int c2 = 512 + tid;
                int quad = c2 >> 2, comp = c2 & 3;
                float val = s_bias[c2] + s_p4f[quad * 4 + comp]
                          + s_p4f[(132 + quad) * 4 + comp];
                s_o[c2] = val;
                if (c2 < 526) s_eaf[(c2 - 398) * 2 + 1] = tanhf(val);
            }
            u2r = wredsum(u2r);
            u2w = wredsum(u2w);
            if (!lane) { s_knr[wid] = u2r; s_knw[wid] = u2w; }
            __syncthreads();
        }

        // ======== P5: pass A + scalars + attention (4 barriers) ========
        // row pairs (m, m+64): m<32 → both smem; m>=32 → smem + global(mU row m-32)
        ull drP = 0ull, dwP = 0ull, nmP = 0ull;
#pragma unroll 8
        for (int m = 0; m < 32; m++) {
            float v0 = s_mem[m * NS + tid];
            float u0 = s_mem[(m + 64) * NS + tid];
            ull vv = pack2(v0, u0);
            ull kr2, kw2;
            asm("ld.shared.v2.b64 {%0, %1}, [%2];"
                : "=l"(kr2), "=l"(kw2) : "r"(kp_base + m * 16));
            drP = ffma2(vv, kr2, drP);
            dwP = ffma2(vv, kw2, dwP);
            nmP = ffma2(vv, vv, nmP);
        }
#pragma unroll 8
        for (int m = 32; m < 64; m++) {
            float v0 = s_mem[m * NS + tid];
            float u0 = mU[(m - 32) * NS + tid];
            ull vv = pack2(v0, u0);
            ull kr2, kw2;
            asm("ld.shared.v2.b64 {%0, %1}, [%2];"
                : "=l"(kr2), "=l"(kw2) : "r"(kp_base + m * 16));
            drP = ffma2(vv, kr2, drP);
            dwP = ffma2(vv, kw2, dwP);
            nmP = ffma2(vv, vv, nmP);
        }
        float2 drp = unpack2(drP), dwp = unpack2(dwP), nmp = unpack2(nmP);
        float dr = drp.x + drp.y, dw = dwp.x + dwp.y;
        float nrm = sqrtf(nmp.x + nmp.y);

        float knr, knw;
        {
            float a = 0.f, c = 0.f;
#pragma unroll
            for (int i = 0; i < NWARP; i++) { a += s_knr[i]; c += s_knw[i]; }
            knr = sqrtf(a); knw = sqrtf(c);
        }

        float beta_r = softplusf_(s_o[128]);
        float g_r = sigmoidf_(s_o[129]);
        float gamma_r = 1.f + softplusf_(s_o[133]);
        float sr0, sr1, sr2;
        {
            float q0 = s_o[130], q1 = s_o[131], q2 = s_o[132];
            float qm = fmaxf(q0, fmaxf(q1, q2));
            float e0 = expf(q0 - qm), e1 = expf(q1 - qm), e2 = expf(q2 - qm);
            float qs = e0 + e1 + e2;
            sr0 = e0 / qs; sr1 = e1 / qs; sr2 = e2 / qs;
        }
        float beta_w = softplusf_(s_o[264]);
        float g_w = sigmoidf_(s_o[265]);
        float gamma_w = 1.f + softplusf_(s_o[269]);
        float sw0, sw1, sw2;
        {
            float q0 = s_o[266], q1 = s_o[267], q2 = s_o[268];
            float qm = fmaxf(q0, fmaxf(q1, q2));
            float e0 = expf(q0 - qm), e1 = expf(q1 - qm), e2 = expf(q2 - qm);
            float qs = e0 + e1 + e2;
            sw0 = e0 / qs; sw1 = e1 / qs; sw2 = e2 / qs;
        }
        float sc_r = beta_r * dr / (nrm * knr + EPS);
        float sc_w = beta_w * dw / (nrm * knw + EPS);

        float ev_r = __expf(sc_r), ev_w = __expf(sc_w);
        s_evr[tid] = ev_r; s_evw[tid] = ev_w;
        {
            float vr = wredsum(ev_r), vw = wredsum(ev_w);
            if (!lane) { s_redA[wid] = vr; s_redB[wid] = vw; }
        }
        __syncthreads();                                    // B1
        const int np = (tid + 1) & (NS - 1), nm1 = (tid - 1) & (NS - 1);
        float totr = 0.f, totw = 0.f;
#pragma unroll
        for (int i = 0; i < NWARP; i++) { totr += s_redA[i]; totw += s_redB[i]; }
        float inv_tr = 1.f / totr, inv_tw = 1.f / totw;
        float wc_r = ev_r * inv_tr;
        float wg   = g_r * wc_r + (1.f - g_r) * s_wpre[tid];
        float wg_p = g_r * (s_evr[np] * inv_tr) + (1.f - g_r) * s_wpre[np];
        float wg_m = g_r * (s_evr[nm1] * inv_tr) + (1.f - g_r) * s_wpre[nm1];
        float wt_r = sr0 * wg_p + sr1 * wg + sr2 * wg_m;
        float wraw_r = __powf(wt_r, gamma_r);
        s_wtmp[tid] = wraw_r;
        {
            float v = wredsum(wraw_r);
            if (!lane) s_redA[wid] = v;
        }
        __syncthreads();                                    // B2
        float sumr = 0.f;
#pragma unroll
        for (int i = 0; i < NWARP; i++) sumr += s_redA[i];
        float inv_r = 1.f / (sumr + EPS);
        float w_r = wraw_r * inv_r;
        s_wr[tid] = w_r;
        float wr_p = s_wtmp[np] * inv_r, wr_m = s_wtmp[nm1] * inv_r;
        float wc_w  = ev_w * inv_tw;
        float wgw   = g_w * wc_w + (1.f - g_w) * w_r;
        float wgw_p = g_w * (s_evw[np] * inv_tw) + (1.f - g_w) * wr_p;
        float wgw_m = g_w * (s_evw[nm1] * inv_tw) + (1.f - g_w) * wr_m;
        float wt_w = sw0 * wgw_p + sw1 * wgw + sw2 * wgw_m;
        float wraw_w = __powf(wt_w, gamma_w);
        {
            float v = wredsum(wraw_w);
            if (!lane) s_redB[wid] = v;
        }
        __syncthreads();                                    // B3
        float sumw = 0.f;
#pragma unroll
        for (int i = 0; i < NWARP; i++) sumw += s_redB[i];
        float w_w = wraw_w / (sumw + EPS);
        s_ww[tid] = w_w;
        s_wpre[tid] = w_w;                                  // carry
        __syncthreads();                                    // B4

        // ======== P6: pass B: warp gets 2 global rows then 6 smem rows ========
        {
            ull wr01[4], wr23[4], ww01[4], ww23[4];
            {
                const float4* wrv = (const float4*)s_wr;
                const float4* wwv = (const float4*)s_ww;
#pragma unroll
                for (int c = 0; c < 4; c++) {
                    float4 a = wrv[c * 32 + lane];
                    float4 bq = wwv[c * 32 + lane];
                    wr01[c] = pack2(a.x, a.y);   wr23[c] = pack2(a.z, a.w);
                    ww01[c] = pack2(bq.x, bq.y); ww23[c] = pack2(bq.z, bq.w);
                }
            }
#pragma unroll
            for (int rr = 0; rr < 8; rr++) {
                // rr 0-1: global rows (issue LDG early); rr 2-7: smem rows
                int m; ulonglong2* rp;
                if (rr < 2) {
                    m = ROWS_S + wid * 2 + rr;
                    rp = (ulonglong2*)(mU + (size_t)(wid * 2 + rr) * NS);
                } else {
                    m = wid * 6 + (rr - 2);
                    rp = (ulonglong2*)(s_mem + (size_t)m * NS);
                }
                float2 ea = s_ea[m];
                ull e2n = pack2(-ea.x, -ea.x), a2 = pack2(ea.y, ea.y);
                ull r01 = 0ull, r23 = 0ull;
#pragma unroll
                for (int c = 0; c < 4; c++) {
                    ulonglong2 v = rp[c * 32 + lane];
                    r01 = ffma2(wr01[c], v.x, r01);
                    r23 = ffma2(wr23[c], v.y, r23);
                    ull t01 = fmul2(ww01[c], e2n);
                    ull t23 = fmul2(ww23[c], e2n);
                    ull n01 = ffma2(v.x, t01, v.x);
                    ull n23 = ffma2(v.y, t23, v.y);
                    n01 = ffma2(ww01[c], a2, n01);
                    n23 = ffma2(ww23[c], a2, n23);
                    ulonglong2 o2; o2.x = n01; o2.y = n23;
                    rp[c * 32 + lane] = o2;
                }
                float2 p0 = unpack2(r01), p1 = unpack2(r23);
                float sumv = wredsum(p0.x + p0.y + p1.x + p1.y);
                if (!lane) s_r[m] = sumv;
            }
            __syncthreads();
        }
    }

    // final history store for t = T_STEPS-1
    if (tid < 2 * DH) {
        size_t row = (size_t)(b * T_STEPS + T_STEPS - 1);
        g_hr[row * 2 * DH + tid] = (tid < DH) ? s_h[tid] : s_r[tid - DH];
    }
}

// Y = [H | R] @ Wout + bout ; Wout staged in smem.
#define OUT_SMEM_FLOATS (32768 + 8192)
__global__ void __launch_bounds__(256) out_gemm(
    const float* __restrict__ Wout, const float* __restrict__ bout,
    float* __restrict__ out)
{
    extern __shared__ float sh[];
    float* shW = sh;            // 256 x 128
    float* As  = sh + 32768;    // 32 x 256
    const int tid = threadIdx.x, lane = tid & 31, wid = tid >> 5;
    const int rbase = blockIdx.x * 32;

    {
        float4* dst = (float4*)shW;
        const float4* src = (const float4*)Wout;
        for (int i = tid; i < 8192; i += 256) dst[i] = src[i];
        float4* dA = (float4*)As;
        const float4* sA = (const float4*)(g_hr + (size_t)rbase * 256);
        for (int i = tid; i < 2048; i += 256) dA[i] = sA[i];
    }
    __syncthreads();

    float acc[4][4];
#pragma unroll
    for (int i = 0; i < 4; i++)
#pragma unroll
        for (int j = 0; j < 4; j++) acc[i][j] = 0.f;

    const int c0 = lane * 4;
    const int r0 = wid * 4;
#pragma unroll 4
    for (int k = 0; k < 256; k++) {
        float4 wv = ((const float4*)shW)[k * 32 + lane];
#pragma unroll
        for (int i = 0; i < 4; i++) {
            float av = As[(r0 + i) * 256 + k];
            acc[i][0] = fmaf(av, wv.x, acc[i][0]);
            acc[i][1] = fmaf(av, wv.y, acc[i][1]);
            acc[i][2] = fmaf(av, wv.z, acc[i][2]);
            acc[i][3] = fmaf(av, wv.w, acc[i][3]);
        }
    }
    float4 bo = *reinterpret_cast<const float4*>(bout + c0);
#pragma unroll
    for (int i = 0; i < 4; i++) {
        float4 o4 = make_float4(acc[i][0] + bo.x, acc[i][1] + bo.y,
                                acc[i][2] + bo.z, acc[i][3] + bo.w);
        *reinterpret_cast<float4*>(out + (size_t)(rbase + r0 + i) * 128 + c0) = o4;
    }
}

extern "C" void kernel_launch(void* const* d_in, const int* in_sizes, int n_in,
                              void* d_out, int out_size)
{
    const float* x    = (const float*)d_in[0];
    const float* Wxh  = (const float*)d_in[1];
    const float* Whh  = (const float*)d_in[2];
    const float* Wrh  = (const float*)d_in[3];
    const float* bh   = (const float*)d_in[4];
    const float* Wout = (const float*)d_in[5];
    const float* bout = (const float*)d_in[6];
    const float* Wr   = (const float*)d_in[7];
    const float* br   = (const float*)d_in[8];
    const float* Ww   = (const float*)d_in[9];
    const float* bw   = (const float*)d_in[10];
    float* out = (float*)d_out;

    cudaFuncSetAttribute(ntm_kernel, cudaFuncAttributeMaxDynamicSharedMemorySize,
                         SMEM_FLOATS * sizeof(float));
    cudaFuncSetAttribute(out_gemm, cudaFuncAttributeMaxDynamicSharedMemorySize,
                         OUT_SMEM_FLOATS * sizeof(float));

    // ncu profiles absolute launch index 3 == ntm_kernel.
    k_xh<<<BS, 256>>>(x, Wxh, bh);                      // 0
    k_minit<<<BS, 256>>>();                             // 1
    k_repack<<<128, 256>>>(Whh, Wrh, Wr, Ww);           // 2
    ntm_kernel<<<BS, NTHR, SMEM_FLOATS * sizeof(float)>>>(br, bw);  // 3
    out_gemm<<<BS * T_STEPS / 32, 256, OUT_SMEM_FLOATS * sizeof(float)>>>(
        Wout, bout, out);                               // 4
}

// round 13
// speedup vs baseline: 1.1671x; 1.0003x over previous
#include <cuda_runtime.h>
#include <math.h>

#define BS 128
#define T_STEPS 32
#define DIN 128
#define DH 128
#define NS 512
#define NTHR 512
#define NWARP 16
#define EPS 1e-8f
#define WLD 784               // repacked weights: [Whh(128)|Wrh(128)|Wr pad136|Ww pad392]
#define ROWS_S 96             // mem rows in smem
#define ROWS_G 32             // mem rows in L2

typedef unsigned long long ull;

// Global scratch (allocation-free rule).
__device__ float g_memU[(size_t)BS * ROWS_G * NS];     // mem rows 96..127
__device__ float g_hr[(size_t)BS * T_STEPS * 2 * DH];  // (h,r) history
__device__ float g_xh[(size_t)BS * T_STEPS * DH];      // x@Wxh + bh
__device__ float g_Wcat[128 * WLD];

// ---- shared memory layout (float offsets) ----
#define OFF_MEM   0                       // 96*512 = 49152
#define OFF_KP    (OFF_MEM  + 49152)      // 256  float4[64]: {kr[m],kr[m+64],kw[m],kw[m+64]}
#define OFF_EA    (OFF_KP   + 256)        // 256  float2[128]: {e[m], a[m]}
#define OFF_BIAS  (OFF_EA   + 256)        // 528
#define OFF_O     (OFF_BIAS + 528)        // 528
#define OFF_H     (OFF_O    + 528)        // 128
#define OFF_R     (OFF_H    + 128)        // 128
#define OFF_P4    (OFF_R    + 128)        // 2048 (512 float4 partials)
#define OFF_WPRE  (OFF_P4   + 2048)       // 512
#define OFF_WR    (OFF_WPRE + 512)        // 512
#define OFF_WW    (OFF_WR   + 512)        // 512
#define OFF_WTMP  (OFF_WW   + 512)        // 512
#define OFF_EVR   (OFF_WTMP + 512)        // 512
#define OFF_EVW   (OFF_EVR  + 512)        // 512
#define OFF_REDA  (OFF_EVW  + 512)        // 16
#define OFF_REDB  (OFF_REDA + 16)         // 16
#define OFF_KNR   (OFF_REDB + 16)         // 16
#define OFF_KNW   (OFF_KNR  + 16)         // 16
#define SMEM_FLOATS (OFF_KNW + 16)        // 56160 floats = 224640 B

// ---- f32x2 packed helpers ----
__device__ __forceinline__ ull pack2(float lo, float hi) {
    ull r; asm("mov.b64 %0, {%1, %2};" : "=l"(r) : "f"(lo), "f"(hi)); return r;
}
__device__ __forceinline__ float2 unpack2(ull v) {
    float2 r; asm("mov.b64 {%0, %1}, %2;" : "=f"(r.x), "=f"(r.y) : "l"(v)); return r;
}
__device__ __forceinline__ ull ffma2(ull a, ull b, ull c) {
    ull d; asm("fma.rn.f32x2 %0, %1, %2, %3;" : "=l"(d) : "l"(a), "l"(b), "l"(c)); return d;
}
__device__ __forceinline__ ull fmul2(ull a, ull b) {
    ull d; asm("mul.rn.f32x2 %0, %1, %2;" : "=l"(d) : "l"(a), "l"(b)); return d;
}
__device__ __forceinline__ void ffma2_f4(float4 w, ull hb, ull& a01, ull& a23) {
    a01 = ffma2(pack2(w.x, w.y), hb, a01);
    a23 = ffma2(pack2(w.z, w.w), hb, a23);
}

__device__ __forceinline__ float softplusf_(float x) {
    return x > 20.f ? x : log1pf(expf(x));
}
__device__ __forceinline__ float sigmoidf_(float x) {
    return 1.f / (1.f + expf(-x));
}
__device__ __forceinline__ float wredsum(float v) {
#pragma unroll
    for (int o = 16; o; o >>= 1) v += __shfl_xor_sync(0xffffffffu, v, o);
    return v;
}

// Prep 1: xh[b][t][j] = x_t @ Wxh + bh
__global__ void __launch_bounds__(256) k_xh(
    const float* __restrict__ x, const float* __restrict__ Wxh,
    const float* __restrict__ bh)
{
    const int b = blockIdx.x, tid = threadIdx.x;
    const float* xb = x + (size_t)b * T_STEPS * DIN;
    for (int idx = tid; idx < T_STEPS * DH; idx += 256) {
        int t = idx >> 7, j = idx & 127;
        float acc = bh[j];
        const float* xr = xb + t * DIN;
#pragma unroll 8
        for (int k = 0; k < DIN; k++) acc = fmaf(xr[k], Wxh[k * DH + j], acc);
        g_xh[(size_t)b * T_STEPS * DH + idx] = acc;
    }
}

// Prep 2: init streamed mem rows to 1e-6
__global__ void __launch_bounds__(256) k_minit()
{
    const int b = blockIdx.x, tid = threadIdx.x;
    float4 iv = make_float4(1e-6f, 1e-6f, 1e-6f, 1e-6f);
    float4* gu = reinterpret_cast<float4*>(g_memU + (size_t)b * ROWS_G * NS);
    for (int i = tid; i < ROWS_G * NS / 4; i += 256) gu[i] = iv;
}

// Prep 3: repack ALL in-loop weights into one padded float4-aligned buffer.
__global__ void __launch_bounds__(256) k_repack(
    const float* __restrict__ Whh, const float* __restrict__ Wrh,
    const float* __restrict__ Wr,  const float* __restrict__ Ww)
{
    const int k = blockIdx.x, tid = threadIdx.x;
    float* dst = g_Wcat + (size_t)k * WLD;
    for (int c = tid; c < WLD; c += 256) {
        float v;
        if (c < 128)       v = Whh[(size_t)k * 128 + c];
        else if (c < 256)  v = Wrh[(size_t)k * 128 + (c - 128)];
        else if (c < 392) { int cc = c - 256; v = (cc < 134) ? Wr[(size_t)k * 134 + cc] : 0.f; }
        else              { int cc = c - 392; v = (cc < 390) ? Ww[(size_t)k * 390 + cc] : 0.f; }
        dst[c] = v;
    }
}

__global__ void __launch_bounds__(NTHR, 1) ntm_kernel(
    const float* __restrict__ br, const float* __restrict__ bw)
{
    extern __shared__ float sm[];
    float*  s_mem = sm + OFF_MEM;
    float4* s_kp  = (float4*)(sm + OFF_KP);
    float*  s_kpf = sm + OFF_KP;
    float2* s_ea  = (float2*)(sm + OFF_EA);
    float*  s_eaf = sm + OFF_EA;
    float*  s_bias= sm + OFF_BIAS;
    float*  s_o   = sm + OFF_O;
    float*  s_h   = sm + OFF_H;
    float*  s_r   = sm + OFF_R;
    float4* s_p4  = (float4*)(sm + OFF_P4);
    float*  s_p4f = sm + OFF_P4;
    float*  s_wpre= sm + OFF_WPRE;
    float*  s_wr  = sm + OFF_WR;
    float*  s_ww  = sm + OFF_WW;
    float*  s_wtmp= sm + OFF_WTMP;
    float*  s_evr = sm + OFF_EVR;
    float*  s_evw = sm + OFF_EVW;
    float*  s_redA= sm + OFF_REDA;
    float*  s_redB= sm + OFF_REDB;
    float*  s_knr = sm + OFF_KNR;
    float*  s_knw = sm + OFF_KNW;

    const int tid = threadIdx.x;
    const int wid = tid >> 5, lane = tid & 31;
    const int b = blockIdx.x;

    // padded biases
    {
        float v;
        if (tid < 134)       v = br[tid];
        else if (tid < 136)  v = 0.f;
        else                 v = bw[tid - 136];
        s_bias[tid] = v;
        if (tid < 16) s_bias[512 + tid] = (512 + tid < 526) ? bw[512 + tid - 136] : 0.f;
    }
    // init smem-resident mem rows 0..95
    {
        float4 iv = make_float4(1e-6f, 1e-6f, 1e-6f, 1e-6f);
        float4* mb = (float4*)s_mem;
        for (int i = tid; i < ROWS_S * NS / 4; i += NTHR) mb[i] = iv;
    }
    if (tid < DH) { s_h[tid] = 0.f; s_r[tid] = 0.f; }
    s_wpre[tid] = 1.f / NS;
    __syncthreads();

    float* mU = g_memU + (size_t)b * ROWS_G * NS;
    const float* xh_b = g_xh + (size_t)b * T_STEPS * DH;
    const unsigned kp_base = (unsigned)__cvta_generic_to_shared(s_kp);

    for (int t = 0; t < T_STEPS; t++) {
        // ======== P1: h-matvec (512 tasks, all from L2 Wcat) + folded history ========
        {
            if (t > 0 && tid < 2 * DH) {
                size_t row = (size_t)(b * T_STEPS + t - 1);
                g_hr[row * 2 * DH + tid] = (tid < DH) ? s_h[tid] : s_r[tid - DH];
            }
            const int mat = tid >> 8;            // 0: Whh*h (cols 0-127), 1: Wrh*r (128-255)
            const int rem = tid & 255;
            const int ks  = rem >> 5;
            const int jq  = rem & 31;
            const int k0  = ks * 16;
            const int colbase = mat << 7;
            const float* v = mat ? s_r : s_h;
            ull a01 = 0ull, a23 = 0ull;
#pragma unroll
            for (int k = 0; k < 16; k++) {
                float hv = v[k0 + k];
                float4 w = *(const float4*)(g_Wcat + (size_t)(k0 + k) * WLD + colbase + jq * 4);
                ffma2_f4(w, pack2(hv, hv), a01, a23);
            }
            float2 lo = unpack2(a01), hi = unpack2(a23);
            s_p4[tid] = make_float4(lo.x, lo.y, hi.x, hi.y);
            __syncthreads();
            // ======== P2: h-reduce + tanh ========
            if (tid < DH) {
                int jq2 = tid >> 2, comp = tid & 3;
                float sum = xh_b[t * DH + tid];
#pragma unroll
                for (int m2 = 0; m2 < 2; m2++)
#pragma unroll
                    for (int k2 = 0; k2 < 8; k2++)
                        sum += s_p4f[(m2 * 256 + k2 * 32 + jq2) * 4 + comp];
                s_h[tid] = tanhf(sum);
            }
            __syncthreads();
        }

        // ======== P3: o-matvec (264 tasks; LDG.128; interleaved chains) ========
        if (tid < 264) {
            const int q  = (tid < 132) ? tid : tid - 132;
            const int ks = (tid < 132) ? 0 : 1;
            const int col = 256 + q * 4;
            const int k0 = ks * 64;
            ull a01a = 0ull, a23a = 0ull, a01b = 0ull, a23b = 0ull;
#pragma unroll 8
            for (int k = 0; k < 64; k += 2) {
                float h0 = s_h[k0 + k], h1 = s_h[k0 + k + 1];
                float4 w0 = *(const float4*)(g_Wcat + (size_t)(k0 + k) * WLD + col);
                float4 w1 = *(const float4*)(g_Wcat + (size_t)(k0 + k + 1) * WLD + col);
                ffma2_f4(w0, pack2(h0, h0), a01a, a23a);
                ffma2_f4(w1, pack2(h1, h1), a01b, a23b);
            }
            const ull ONE2 = pack2(1.f, 1.f);
            float2 lo = unpack2(ffma2(a01b, ONE2, a01a));
            float2 hi = unpack2(ffma2(a23b, ONE2, a23a));
            s_p4[tid] = make_float4(lo.x, lo.y, hi.x, hi.y);
        }
        __syncthreads();

        // ======== P4: o-reduce + fused packing + key-norm partials ========
        {
            float u2r = 0.f, u2w = 0.f;
            {
                const int c = tid;
                int quad = c >> 2, comp = c & 3;
                float val = s_bias[c] + s_p4f[quad * 4 + comp]
                          + s_p4f[(132 + quad) * 4 + comp];
                s_o[c] = val;
                if (c < 128) {
                    s_kpf[(c & 63) * 4 + (c >> 6)] = val;            // kr
                    u2r = val * val;
                } else if (c >= 136 && c < 264) {
                    int m = c - 136;
                    s_kpf[(m & 63) * 4 + 2 + (m >> 6)] = val;        // kw
                    u2w = val * val;
                } else if (c >= 270 && c < 398) {
                    s_eaf[(c - 270) * 2 + 0] = sigmoidf_(val);       // e
                } else if (c >= 398) {
                    s_eaf[(c - 398) * 2 + 1] = tanhf(val);           // a
                }
            }
            if (tid < 16) {
                const int c2 = 512 + tid;
                int quad = c2 >> 2, comp = c2 & 3;
                float val = s_bias[c2] + s_p4f[quad * 4 + comp]
                          + s_p4f[(132 + quad) * 4 + comp];
                s_o[c2] = val;
                if (c2 < 526) s_eaf[(c2 - 398) * 2 + 1] = tanhf(val);
            }
            u2r = wredsum(u2r);
            u2w = wredsum(u2w);
            if (!lane) { s_knr[wid] = u2r; s_knw[wid] = u2w; }
            __syncthreads();
        }

        // ======== P5: pass A + scalars + attention (4 barriers) ========
        // row pairs (m, m+64): m<32 → both smem; m>=32 → smem + global(mU row m-32)
        ull drP = 0ull, dwP = 0ull, nmP = 0ull;
#pragma unroll 8
        for (int m = 0; m < 32; m++) {
            float v0 = s_mem[m * NS + tid];
            float u0 = s_mem[(m + 64) * NS + tid];
            ull vv = pack2(v0, u0);
            ull kr2, kw2;
            asm("ld.shared.v2.b64 {%0, %1}, [%2];"
                : "=l"(kr2), "=l"(kw2) : "r"(kp_base + m * 16));
            drP = ffma2(vv, kr2, drP);
            dwP = ffma2(vv, kw2, dwP);
            nmP = ffma2(vv, vv, nmP);
        }
#pragma unroll 8
        for (int m = 32; m < 64; m++) {
            float v0 = s_mem[m * NS + tid];
            float u0 = mU[(m - 32) * NS + tid];
            ull vv = pack2(v0, u0);
            ull kr2, kw2;
            asm("ld.shared.v2.b64 {%0, %1}, [%2];"
                : "=l"(kr2), "=l"(kw2) : "r"(kp_base + m * 16));
            drP = ffma2(vv, kr2, drP);
            dwP = ffma2(vv, kw2, dwP);
            nmP = ffma2(vv, vv, nmP);
        }
        float2 drp = unpack2(drP), dwp = unpack2(dwP), nmp = unpack2(nmP);
        float dr = drp.x + drp.y, dw = dwp.x + dwp.y;
        float nrm = sqrtf(nmp.x + nmp.y);

        float knr, knw;
        {
            float a = 0.f, c = 0.f;
#pragma unroll
            for (int i = 0; i < NWARP; i++) { a += s_knr[i]; c += s_knw[i]; }
            knr = sqrtf(a); knw = sqrtf(c);
        }

        float beta_r = softplusf_(s_o[128]);
        float g_r = sigmoidf_(s_o[129]);
        float gamma_r = 1.f + softplusf_(s_o[133]);
        float sr0, sr1, sr2;
        {
            float q0 = s_o[130], q1 = s_o[131], q2 = s_o[132];
            float qm = fmaxf(q0, fmaxf(q1, q2));
            float e0 = expf(q0 - qm), e1 = expf(q1 - qm), e2 = expf(q2 - qm);
            float qs = e0 + e1 + e2;
            sr0 = e0 / qs; sr1 = e1 / qs; sr2 = e2 / qs;
        }
        float beta_w = softplusf_(s_o[264]);
        float g_w = sigmoidf_(s_o[265]);
        float gamma_w = 1.f + softplusf_(s_o[269]);
        float sw0, sw1, sw2;
        {
            float q0 = s_o[266], q1 = s_o[267], q2 = s_o[268];
            float qm = fmaxf(q0, fmaxf(q1, q2));
            float e0 = expf(q0 - qm), e1 = expf(q1 - qm), e2 = expf(q2 - qm);
            float qs = e0 + e1 + e2;
            sw0 = e0 / qs; sw1 = e1 / qs; sw2 = e2 / qs;
        }
        float sc_r = beta_r * dr / (nrm * knr + EPS);
        float sc_w = beta_w * dw / (nrm * knw + EPS);

        float ev_r = __expf(sc_r), ev_w = __expf(sc_w);
        s_evr[tid] = ev_r; s_evw[tid] = ev_w;
        {
            float vr = wredsum(ev_r), vw = wredsum(ev_w);
            if (!lane) { s_redA[wid] = vr; s_redB[wid] = vw; }
        }
        __syncthreads();                                    // B1
        const int np = (tid + 1) & (NS - 1), nm1 = (tid - 1) & (NS - 1);
        float totr = 0.f, totw = 0.f;
#pragma unroll
        for (int i = 0; i < NWARP; i++) { totr += s_redA[i]; totw += s_redB[i]; }
        float inv_tr = 1.f / totr, inv_tw = 1.f / totw;
        float wc_r = ev_r * inv_tr;
        float wg   = g_r * wc_r + (1.f - g_r) * s_wpre[tid];
        float wg_p = g_r * (s_evr[np] * inv_tr) + (1.f - g_r) * s_wpre[np];
        float wg_m = g_r * (s_evr[nm1] * inv_tr) + (1.f - g_r) * s_wpre[nm1];
        float wt_r = sr0 * wg_p + sr1 * wg + sr2 * wg_m;
        float wraw_r = __powf(wt_r, gamma_r);
        s_wtmp[tid] = wraw_r;
        {
            float v = wredsum(wraw_r);
            if (!lane) s_redA[wid] = v;
        }
        __syncthreads();                                    // B2
        float sumr = 0.f;
#pragma unroll
        for (int i = 0; i < NWARP; i++) sumr += s_redA[i];
        float inv_r = 1.f / (sumr + EPS);
        float w_r = wraw_r * inv_r;
        s_wr[tid] = w_r;
        float wr_p = s_wtmp[np] * inv_r, wr_m = s_wtmp[nm1] * inv_r;
        float wc_w  = ev_w * inv_tw;
        float wgw   = g_w * wc_w + (1.f - g_w) * w_r;
        float wgw_p = g_w * (s_evw[np] * inv_tw) + (1.f - g_w) * wr_p;
        float wgw_m = g_w * (s_evw[nm1] * inv_tw) + (1.f - g_w) * wr_m;
        float wt_w = sw0 * wgw_p + sw1 * wgw + sw2 * wgw_m;
        float wraw_w = __powf(wt_w, gamma_w);
        {
            float v = wredsum(wraw_w);
            if (!lane) s_redB[wid] = v;
        }
        __syncthreads();                                    // B3
        float sumw = 0.f;
#pragma unroll
        for (int i = 0; i < NWARP; i++) sumw += s_redB[i];
        float w_w = wraw_w / (sumw + EPS);
        s_ww[tid] = w_w;
        s_wpre[tid] = w_w;                                  // carry
        __syncthreads();                                    // B4

        // ======== P6: pass B: warp gets 2 global rows then 6 smem rows ========
        {
            ull wr01[4], wr23[4], ww01[4], ww23[4];
            {
                const float4* wrv = (const float4*)s_wr;
                const float4* wwv = (const float4*)s_ww;
#pragma unroll
                for (int c = 0; c < 4; c++) {
                    float4 a = wrv[c * 32 + lane];
                    float4 bq = wwv[c * 32 + lane];
                    wr01[c] = pack2(a.x, a.y);   wr23[c] = pack2(a.z, a.w);
                    ww01[c] = pack2(bq.x, bq.y); ww23[c] = pack2(bq.z, bq.w);
                }
            }
#pragma unroll
            for (int rr = 0; rr < 8; rr++) {
                // rr 0-1: global rows (issue LDG early); rr 2-7: smem rows
                int m; ulonglong2* rp;
                if (rr < 2) {
                    m = ROWS_S + wid * 2 + rr;
                    rp = (ulonglong2*)(mU + (size_t)(wid * 2 + rr) * NS);
                } else {
                    m = wid * 6 + (rr - 2);
                    rp = (ulonglong2*)(s_mem + (size_t)m * NS);
                }
                float2 ea = s_ea[m];
                ull e2n = pack2(-ea.x, -ea.x), a2 = pack2(ea.y, ea.y);
                ull r01 = 0ull, r23 = 0ull;
#pragma unroll
                for (int c = 0; c < 4; c++) {
                    ulonglong2 v = rp[c * 32 + lane];
                    r01 = ffma2(wr01[c], v.x, r01);
                    r23 = ffma2(wr23[c], v.y, r23);
                    ull t01 = fmul2(ww01[c], e2n);
                    ull t23 = fmul2(ww23[c], e2n);
                    ull n01 = ffma2(v.x, t01, v.x);
                    ull n23 = ffma2(v.y, t23, v.y);
                    n01 = ffma2(ww01[c], a2, n01);
                    n23 = ffma2(ww23[c], a2, n23);
                    ulonglong2 o2; o2.x = n01; o2.y = n23;
                    rp[c * 32 + lane] = o2;
                }
                float2 p0 = unpack2(r01), p1 = unpack2(r23);
                float sumv = wredsum(p0.x + p0.y + p1.x + p1.y);
                if (!lane) s_r[m] = sumv;
            }
            __syncthreads();
        }
    }

    // final history store for t = T_STEPS-1
    if (tid < 2 * DH) {
        size_t row = (size_t)(b * T_STEPS + T_STEPS - 1);
        g_hr[row * 2 * DH + tid] = (tid < DH) ? s_h[tid] : s_r[tid - DH];
    }
}

// Y = [H | R] @ Wout + bout ; Wout staged in smem.
#define OUT_SMEM_FLOATS (32768 + 8192)
__global__ void __launch_bounds__(256) out_gemm(
    const float* __restrict__ Wout, const float* __restrict__ bout,
    float* __restrict__ out)
{
    extern __shared__ float sh[];
    float* shW = sh;            // 256 x 128
    float* As  = sh + 32768;    // 32 x 256
    const int tid = threadIdx.x, lane = tid & 31, wid = tid >> 5;
    const int rbase = blockIdx.x * 32;

    {
        float4* dst = (float4*)shW;
        const float4* src = (const float4*)Wout;
        for (int i = tid; i < 8192; i += 256) dst[i] = src[i];
        float4* dA = (float4*)As;
        const float4* sA = (const float4*)(g_hr + (size_t)rbase * 256);
        for (int i = tid; i < 2048; i += 256) dA[i] = sA[i];
    }
    __syncthreads();

    float acc[4][4];
#pragma unroll
    for (int i = 0; i < 4; i++)
#pragma unroll
        for (int j = 0; j < 4; j++) acc[i][j] = 0.f;

    const int c0 = lane * 4;
    const int r0 = wid * 4;
#pragma unroll 4
    for (int k = 0; k < 256; k++) {
        float4 wv = ((const float4*)shW)[k * 32 + lane];
#pragma unroll
        for (int i = 0; i < 4; i++) {
            float av = As[(r0 + i) * 256 + k];
            acc[i][0] = fmaf(av, wv.x, acc[i][0]);
            acc[i][1] = fmaf(av, wv.y, acc[i][1]);
            acc[i][2] = fmaf(av, wv.z, acc[i][2]);
            acc[i][3] = fmaf(av, wv.w, acc[i][3]);
        }
    }
    float4 bo = *reinterpret_cast<const float4*>(bout + c0);
#pragma unroll
    for (int i = 0; i < 4; i++) {
        float4 o4 = make_float4(acc[i][0] + bo.x, acc[i][1] + bo.y,
                                acc[i][2] + bo.z, acc[i][3] + bo.w);
        *reinterpret_cast<float4*>(out + (size_t)(rbase + r0 + i) * 128 + c0) = o4;
    }
}

extern "C" void kernel_launch(void* const* d_in, const int* in_sizes, int n_in,
                              void* d_out, int out_size)
{
    const float* x    = (const float*)d_in[0];
    const float* Wxh  = (const float*)d_in[1];
    const float* Whh  = (const float*)d_in[2];
    const float* Wrh  = (const float*)d_in[3];
    const float* bh   = (const float*)d_in[4];
    const float* Wout = (const float*)d_in[5];
    const float* bout = (const float*)d_in[6];
    const float* Wr   = (const float*)d_in[7];
    const float* br   = (const float*)d_in[8];
    const float* Ww   = (const float*)d_in[9];
    const float* bw   = (const float*)d_in[10];
    float* out = (float*)d_out;

    cudaFuncSetAttribute(ntm_kernel, cudaFuncAttributeMaxDynamicSharedMemorySize,
                         SMEM_FLOATS * sizeof(float));
    cudaFuncSetAttribute(out_gemm, cudaFuncAttributeMaxDynamicSharedMemorySize,
                         OUT_SMEM_FLOATS * sizeof(float));

    // ncu profiles absolute launch index 3 == ntm_kernel.
    k_xh<<<BS, 256>>>(x, Wxh, bh);                      // 0
    k_minit<<<BS, 256>>>();                             // 1
    k_repack<<<128, 256>>>(Whh, Wrh, Wr, Ww);           // 2
    ntm_kernel<<<BS, NTHR, SMEM_FLOATS * sizeof(float)>>>(br, bw);  // 3
    out_gemm<<<BS * T_STEPS / 32, 256, OUT_SMEM_FLOATS * sizeof(float)>>>(
        Wout, bout, out);                               // 4
}

// round 14
// speedup vs baseline: 1.1783x; 1.0096x over previous
#include <cuda_runtime.h>
#include <math.h>

#define BS 128
#define T_STEPS 32
#define DIN 128
#define DH 128
#define NS 512
#define NTHR 512
#define NWARP 16
#define EPS 1e-8f
#define WLD 784               // [Whh(128)|Wrh(128)|o-cols 528]
#define ROWS_S 96
#define ROWS_G 32

typedef unsigned long long ull;

__device__ float g_memU[(size_t)BS * ROWS_G * NS];
__device__ float g_hr[(size_t)BS * T_STEPS * 2 * DH];
__device__ float g_xh[(size_t)BS * T_STEPS * DH];
__device__ float g_Wcat[128 * WLD];

#define OFF_MEM   0
#define OFF_KP    (OFF_MEM  + 49152)
#define OFF_EA    (OFF_KP   + 256)
#define OFF_BIAS  (OFF_EA   + 256)
#define OFF_O     (OFF_BIAS + 528)
#define OFF_H     (OFF_O    + 528)
#define OFF_R     (OFF_H    + 128)
#define OFF_P4    (OFF_R    + 128)
#define OFF_WPRE  (OFF_P4   + 2176)      // 544 float4 partials
#define OFF_WR    (OFF_WPRE + 512)
#define OFF_WW    (OFF_WR   + 512)
#define OFF_WTMP  (OFF_WW   + 512)
#define OFF_EVR   (OFF_WTMP + 512)
#define OFF_EVW   (OFF_EVR  + 512)
#define OFF_REDA  (OFF_EVW  + 512)
#define OFF_REDB  (OFF_REDA + 16)
#define OFF_KNR   (OFF_REDB + 16)
#define OFF_KNW   (OFF_KNR  + 16)
#define SMEM_FLOATS (OFF_KNW + 16)       // 56288 floats = 225152 B

__device__ __forceinline__ ull pack2(float lo, float hi) {
    ull r; asm("mov.b64 %0, {%1, %2};" : "=l"(r) : "f"(lo), "f"(hi)); return r;
}
__device__ __forceinline__ float2 unpack2(ull v) {
    float2 r; asm("mov.b64 {%0, %1}, %2;" : "=f"(r.x), "=f"(r.y) : "l"(v)); return r;
}
__device__ __forceinline__ ull ffma2(ull a, ull b, ull c) {
    ull d; asm("fma.rn.f32x2 %0, %1, %2, %3;" : "=l"(d) : "l"(a), "l"(b), "l"(c)); return d;
}
__device__ __forceinline__ ull fmul2(ull a, ull b) {
    ull d; asm("mul.rn.f32x2 %0, %1, %2;" : "=l"(d) : "l"(a), "l"(b)); return d;
}
__device__ __forceinline__ void ffma2_f4(float4 w, ull hb, ull& a01, ull& a23) {
    a01 = ffma2(pack2(w.x, w.y), hb, a01);
    a23 = ffma2(pack2(w.z, w.w), hb, a23);
}
__device__ __forceinline__ float softplusf_(float x) {
    return x > 20.f ? x : log1pf(expf(x));
}
__device__ __forceinline__ float sigmoidf_(float x) {
    return 1.f / (1.f + expf(-x));
}
__device__ __forceinline__ float wredsum(float v) {
#pragma unroll
    for (int o = 16; o; o >>= 1) v += __shfl_xor_sync(0xffffffffu, v, o);
    return v;
}

__global__ void __launch_bounds__(256) k_xh(
    const float* __restrict__ x, const float* __restrict__ Wxh,
    const float* __restrict__ bh)
{
    const int b = blockIdx.x, tid = threadIdx.x;
    const float* xb = x + (size_t)b * T_STEPS * DIN;
    for (int idx = tid; idx < T_STEPS * DH; idx += 256) {
        int t = idx >> 7, j = idx & 127;
        float acc = bh[j];
        const float* xr = xb + t * DIN;
#pragma unroll 8
        for (int k = 0; k < DIN; k++) acc = fmaf(xr[k], Wxh[k * DH + j], acc);
        g_xh[(size_t)b * T_STEPS * DH + idx] = acc;
    }
}

__global__ void __launch_bounds__(256) k_minit()
{
    const int b = blockIdx.x, tid = threadIdx.x;
    float4 iv = make_float4(1e-6f, 1e-6f, 1e-6f, 1e-6f);
    float4* gu = reinterpret_cast<float4*>(g_memU + (size_t)b * ROWS_G * NS);
    for (int i = tid; i < ROWS_G * NS / 4; i += 256) gu[i] = iv;
}

__global__ void __launch_bounds__(256) k_repack(
    const float* __restrict__ Whh, const float* __restrict__ Wrh,
    const float* __restrict__ Wr,  const float* __restrict__ Ww)
{
    const int k = blockIdx.x, tid = threadIdx.x;
    float* dst = g_Wcat + (size_t)k * WLD;
    for (int c = tid; c < WLD; c += 256) {
        float v;
        if (c < 128)       v = Whh[(size_t)k * 128 + c];
        else if (c < 256)  v = Wrh[(size_t)k * 128 + (c - 128)];
        else if (c < 392) { int cc = c - 256; v = (cc < 134) ? Wr[(size_t)k * 134 + cc] : 0.f; }
        else              { int cc = c - 392; v = (cc < 390) ? Ww[(size_t)k * 390 + cc] : 0.f; }
        dst[c] = v;
    }
}

__global__ void __launch_bounds__(NTHR, 1) ntm_kernel(
    const float* __restrict__ br, const float* __restrict__ bw)
{
    extern __shared__ float sm[];
    float*  s_mem = sm + OFF_MEM;
    float4* s_kp  = (float4*)(sm + OFF_KP);
    float*  s_kpf = sm + OFF_KP;
    float2* s_ea  = (float2*)(sm + OFF_EA);
    float*  s_eaf = sm + OFF_EA;
    float*  s_bias= sm + OFF_BIAS;
    float*  s_o   = sm + OFF_O;
    float*  s_h   = sm + OFF_H;
    float*  s_r   = sm + OFF_R;
    float4* s_p4  = (float4*)(sm + OFF_P4);
    float*  s_p4f = sm + OFF_P4;
    float*  s_wpre= sm + OFF_WPRE;
    float*  s_wr  = sm + OFF_WR;
    float*  s_ww  = sm + OFF_WW;
    float*  s_wtmp= sm + OFF_WTMP;
    float*  s_evr = sm + OFF_EVR;
    float*  s_evw = sm + OFF_EVW;
    float*  s_redA= sm + OFF_REDA;
    float*  s_redB= sm + OFF_REDB;
    float*  s_knr = sm + OFF_KNR;
    float*  s_knw = sm + OFF_KNW;

    const int tid = threadIdx.x;
    const int wid = tid >> 5, lane = tid & 31;
    const int b = blockIdx.x;

    {
        float v;
        if (tid < 134)       v = br[tid];
        else if (tid < 136)  v = 0.f;
        else                 v = bw[tid - 136];
        s_bias[tid] = v;
        if (tid < 16) s_bias[512 + tid] = (512 + tid < 526) ? bw[512 + tid - 136] : 0.f;
    }
    {
        float4 iv = make_float4(1e-6f, 1e-6f, 1e-6f, 1e-6f);
        float4* mb = (float4*)s_mem;
        for (int i = tid; i < ROWS_S * NS / 4; i += NTHR) mb[i] = iv;
    }
    if (tid < DH) { s_h[tid] = 0.f; s_r[tid] = 0.f; }
    s_wpre[tid] = 1.f / NS;
    __syncthreads();

    float* mU = g_memU + (size_t)b * ROWS_G * NS;
    const float* xh_b = g_xh + (size_t)b * T_STEPS * DH;
    const unsigned kp_base = (unsigned)__cvta_generic_to_shared(s_kp);

    for (int t = 0; t < T_STEPS; t++) {
        // ==== P1: h-matvec + xh prefetch + folded history store ====
        float xh_val = 0.f;
        {
            if (tid < DH) xh_val = xh_b[t * DH + tid];   // hoisted L2 load
            if (t > 0 && tid < 2 * DH) {
                size_t row = (size_t)(b * T_STEPS + t - 1);
                g_hr[row * 2 * DH + tid] = (tid < DH) ? s_h[tid] : s_r[tid - DH];
            }
            const int mat = tid >> 8;
            const int rem = tid & 255;
            const int ks  = rem >> 5;
            const int jq  = rem & 31;
            const int k0  = ks * 16;
            const int colbase = mat << 7;
            const float* v = mat ? s_r : s_h;
            ull a01 = 0ull, a23 = 0ull;
#pragma unroll
            for (int k = 0; k < 16; k++) {
                float hv = v[k0 + k];
                float4 w = *(const float4*)(g_Wcat + (size_t)(k0 + k) * WLD + colbase + jq * 4);
                ffma2_f4(w, pack2(hv, hv), a01, a23);
            }
            float2 lo = unpack2(a01), hi = unpack2(a23);
            s_p4[tid] = make_float4(lo.x, lo.y, hi.x, hi.y);
            __syncthreads();
            // ==== P2: h-reduce + tanh ====
            if (tid < DH) {
                int jq2 = tid >> 2, comp = tid & 3;
                float sum = xh_val;
#pragma unroll
                for (int m2 = 0; m2 < 2; m2++)
#pragma unroll
                    for (int k2 = 0; k2 < 8; k2++)
                        sum += s_p4f[(m2 * 256 + k2 * 32 + jq2) * 4 + comp];
                s_h[tid] = tanhf(sum);
            }
            __syncthreads();
        }

        // ==== P3: o-matvec, 512 main tasks (k=32) + 32 tail tasks on warp 15 ====
        {
            const int q  = tid & 127;
            const int ks = tid >> 7;
            const int col = 256 + q * 4;
            const int k0 = ks * 32;
            ull a01a = 0ull, a23a = 0ull, a01b = 0ull, a23b = 0ull;
#pragma unroll 8
            for (int k = 0; k < 32; k += 2) {
                float h0 = s_h[k0 + k], h1 = s_h[k0 + k + 1];
                float4 w0 = *(const float4*)(g_Wcat + (size_t)(k0 + k) * WLD + col);
                float4 w1 = *(const float4*)(g_Wcat + (size_t)(k0 + k + 1) * WLD + col);
                ffma2_f4(w0, pack2(h0, h0), a01a, a23a);
                ffma2_f4(w1, pack2(h1, h1), a01b, a23b);
            }
            const ull ONE2 = pack2(1.f, 1.f);
            float2 lo = unpack2(ffma2(a01b, ONE2, a01a));
            float2 hi = unpack2(ffma2(a23b, ONE2, a23a));
            s_p4[ks * 128 + q] = make_float4(lo.x, lo.y, hi.x, hi.y);

            if (tid >= 480) {                 // tail: o-cols 512..527
                int t2 = tid - 480;
                int qt = t2 >> 3;             // 0..3
                int kst = t2 & 7;             // 0..7
                int colt = 256 + (128 + qt) * 4;
                int k0t = kst * 16;
                ull b01a = 0ull, b23a = 0ull, b01b = 0ull, b23b = 0ull;
#pragma unroll
                for (int k = 0; k < 16; k += 2) {
                    float h0 = s_h[k0t + k], h1 = s_h[k0t + k + 1];
                    float4 w0 = *(const float4*)(g_Wcat + (size_t)(k0t + k) * WLD + colt);
                    float4 w1 = *(const float4*)(g_Wcat + (size_t)(k0t + k + 1) * WLD + colt);
                    ffma2_f4(w0, pack2(h0, h0), b01a, b23a);
                    ffma2_f4(w1, pack2(h1, h1), b01b, b23b);
                }
                float2 tl = unpack2(ffma2(b01b, ONE2, b01a));
                float2 th = unpack2(ffma2(b23b, ONE2, b23a));
                s_p4[512 + t2] = make_float4(tl.x, tl.y, th.x, th.y);
            }
        }
        __syncthreads();

        // ==== P4: o-reduce + fused packing + key-norm partials ====
        {
            float u2r = 0.f, u2w = 0.f;
            {
                const int c = tid;
                int quad = c >> 2, comp = c & 3;
                float val = s_bias[c];
#pragma unroll
                for (int ks = 0; ks < 4; ks++)
                    val += s_p4f[(ks * 128 + quad) * 4 + comp];
                if ((c >= 128 && c < 134) || (c >= 264 && c < 270)) s_o[c] = val;
                if (c < 128) {
                    s_kpf[(c & 63) * 4 + (c >> 6)] = val;
                    u2r = val * val;
                } else if (c >= 136 && c < 264) {
                    int m = c - 136;
                    s_kpf[(m & 63) * 4 + 2 + (m >> 6)] = val;
                    u2w = val * val;
                } else if (c >= 270 && c < 398) {
                    s_eaf[(c - 270) * 2 + 0] = sigmoidf_(val);
                } else if (c >= 398) {
                    s_eaf[(c - 398) * 2 + 1] = tanhf(val);
                }
            }
            if (tid < 16) {
                const int c2 = 512 + tid;
                int qt = tid >> 2, comp = c2 & 3;
                float val = s_bias[c2];
#pragma unroll
                for (int kst = 0; kst < 8; kst++)
                    val += s_p4f[(512 + qt * 8 + kst) * 4 + comp];
                if (c2 < 526) s_eaf[(c2 - 398) * 2 + 1] = tanhf(val);
            }
            u2r = wredsum(u2r);
            u2w = wredsum(u2w);
            if (!lane) { s_knr[wid] = u2r; s_knw[wid] = u2w; }
            __syncthreads();
        }

        // ==== P5: scalars first (MUFU overlaps pass A loads), then pass A, attention ====
        float knr, knw;
        {
            float a = 0.f, c = 0.f;
#pragma unroll
            for (int i = 0; i < NWARP; i++) { a += s_knr[i]; c += s_knw[i]; }
            knr = sqrtf(a); knw = sqrtf(c);
        }
        float beta_r = softplusf_(s_o[128]);
        float g_r = sigmoidf_(s_o[129]);
        float gamma_r = 1.f + softplusf_(s_o[133]);
        float sr0, sr1, sr2;
        {
            float q0 = s_o[130], q1 = s_o[131], q2 = s_o[132];
            float qm = fmaxf(q0, fmaxf(q1, q2));
            float e0 = expf(q0 - qm), e1 = expf(q1 - qm), e2 = expf(q2 - qm);
            float qs = e0 + e1 + e2;
            sr0 = e0 / qs; sr1 = e1 / qs; sr2 = e2 / qs;
        }
        float beta_w = softplusf_(s_o[264]);
        float g_w = sigmoidf_(s_o[265]);
        float gamma_w = 1.f + softplusf_(s_o[269]);
        float sw0, sw1, sw2;
        {
            float q0 = s_o[266], q1 = s_o[267], q2 = s_o[268];
            float qm = fmaxf(q0, fmaxf(q1, q2));
            float e0 = expf(q0 - qm), e1 = expf(q1 - qm), e2 = expf(q2 - qm);
            float qs = e0 + e1 + e2;
            sw0 = e0 / qs; sw1 = e1 / qs; sw2 = e2 / qs;
        }

        ull drP = 0ull, dwP = 0ull, nmP = 0ull;
#pragma unroll 8
        for (int m = 0; m < 32; m++) {
            float v0 = s_mem[m * NS + tid];
            float u0 = s_mem[(m + 64) * NS + tid];
            ull vv = pack2(v0, u0);
            ull kr2, kw2;
            asm("ld.shared.v2.b64 {%0, %1}, [%2];"
                : "=l"(kr2), "=l"(kw2) : "r"(kp_base + m * 16));
            drP = ffma2(vv, kr2, drP);
            dwP = ffma2(vv, kw2, dwP);
            nmP = ffma2(vv, vv, nmP);
        }
#pragma unroll 8
        for (int m = 32; m < 64; m++) {
            float v0 = s_mem[m * NS + tid];
            float u0 = mU[(m - 32) * NS + tid];
            ull vv = pack2(v0, u0);
            ull kr2, kw2;
            asm("ld.shared.v2.b64 {%0, %1}, [%2];"
                : "=l"(kr2), "=l"(kw2) : "r"(kp_base + m * 16));
            drP = ffma2(vv, kr2, drP);
            dwP = ffma2(vv, kw2, dwP);
            nmP = ffma2(vv, vv, nmP);
        }
        float2 drp = unpack2(drP), dwp = unpack2(dwP), nmp = unpack2(nmP);
        float dr = drp.x + drp.y, dw = dwp.x + dwp.y;
        float nrm = sqrtf(nmp.x + nmp.y);

        float sc_r = beta_r * dr / (nrm * knr + EPS);
        float sc_w = beta_w * dw / (nrm * knw + EPS);

        float ev_r = __expf(sc_r), ev_w = __expf(sc_w);
        s_evr[tid] = ev_r; s_evw[tid] = ev_w;
        {
            float vr = wredsum(ev_r), vw = wredsum(ev_w);
            if (!lane) { s_redA[wid] = vr; s_redB[wid] = vw; }
        }
        __syncthreads();                                    // B1
        const int np = (tid + 1) & (NS - 1), nm1 = (tid - 1) & (NS - 1);
        float totr = 0.f, totw = 0.f;
#pragma unroll
        for (int i = 0; i < NWARP; i++) { totr += s_redA[i]; totw += s_redB[i]; }
        float inv_tr = 1.f / totr, inv_tw = 1.f / totw;
        float wc_r = ev_r * inv_tr;
        float wg   = g_r * wc_r + (1.f - g_r) * s_wpre[tid];
        float wg_p = g_r * (s_evr[np] * inv_tr) + (1.f - g_r) * s_wpre[np];
        float wg_m = g_r * (s_evr[nm1] * inv_tr) + (1.f - g_r) * s_wpre[nm1];
        float wt_r = sr0 * wg_p + sr1 * wg + sr2 * wg_m;
        float wraw_r = __powf(wt_r, gamma_r);
        s_wtmp[tid] = wraw_r;
        {
            float v = wredsum(wraw_r);
            if (!lane) s_redA[wid] = v;
        }
        __syncthreads();                                    // B2
        float sumr = 0.f;
#pragma unroll
        for (int i = 0; i < NWARP; i++) sumr += s_redA[i];
        float inv_r = 1.f / (sumr + EPS);
        float w_r = wraw_r * inv_r;
        s_wr[tid] = w_r;
        float wr_p = s_wtmp[np] * inv_r, wr_m = s_wtmp[nm1] * inv_r;
        float wc_w  = ev_w * inv_tw;
        float wgw   = g_w * wc_w + (1.f - g_w) * w_r;
        float wgw_p = g_w * (s_evw[np] * inv_tw) + (1.f - g_w) * wr_p;
        float wgw_m = g_w * (s_evw[nm1] * inv_tw) + (1.f - g_w) * wr_m;
        float wt_w = sw0 * wgw_p + sw1 * wgw + sw2 * wgw_m;
        float wraw_w = __powf(wt_w, gamma_w);
        {
            float v = wredsum(wraw_w);
            if (!lane) s_redB[wid] = v;
        }
        __syncthreads();                                    // B3
        float sumw = 0.f;
#pragma unroll
        for (int i = 0; i < NWARP; i++) sumw += s_redB[i];
        float w_w = wraw_w / (sumw + EPS);
        s_ww[tid] = w_w;
        s_wpre[tid] = w_w;
        __syncthreads();                                    // B4

        // ==== P6: pass B: 2 global rows then 6 smem rows per warp ====
        {
            ull wr01[4], wr23[4], ww01[4], ww23[4];
            {
                const float4* wrv = (const float4*)s_wr;
                const float4* wwv = (const float4*)s_ww;
#pragma unroll
                for (int c = 0; c < 4; c++) {
                    float4 a = wrv[c * 32 + lane];
                    float4 bq = wwv[c * 32 + lane];
                    wr01[c] = pack2(a.x, a.y);   wr23[c] = pack2(a.z, a.w);
                    ww01[c] = pack2(bq.x, bq.y); ww23[c] = pack2(bq.z, bq.w);
                }
            }
#pragma unroll
            for (int rr = 0; rr < 8; rr++) {
                int m; ulonglong2* rp;
                if (rr < 2) {
                    m = ROWS_S + wid * 2 + rr;
                    rp = (ulonglong2*)(mU + (size_t)(wid * 2 + rr) * NS);
                } else {
                    m = wid * 6 + (rr - 2);
                    rp = (ulonglong2*)(s_mem + (size_t)m * NS);
                }
                float2 ea = s_ea[m];
                ull e2n = pack2(-ea.x, -ea.x), a2 = pack2(ea.y, ea.y);
                ull r01 = 0ull, r23 = 0ull;
#pragma unroll
                for (int c = 0; c < 4; c++) {
                    ulonglong2 v = rp[c * 32 + lane];
                    r01 = ffma2(wr01[c], v.x, r01);
                    r23 = ffma2(wr23[c], v.y, r23);
                    ull t01 = fmul2(ww01[c], e2n);
                    ull t23 = fmul2(ww23[c], e2n);
                    ull n01 = ffma2(v.x, t01, v.x);
                    ull n23 = ffma2(v.y, t23, v.y);
                    n01 = ffma2(ww01[c], a2, n01);
                    n23 = ffma2(ww23[c], a2, n23);
                    ulonglong2 o2; o2.x = n01; o2.y = n23;
                    rp[c * 32 + lane] = o2;
                }
                float2 p0 = unpack2(r01), p1 = unpack2(r23);
                float sumv = wredsum(p0.x + p0.y + p1.x + p1.y);
                if (!lane) s_r[m] = sumv;
            }
            __syncthreads();
        }
    }

    if (tid < 2 * DH) {
        size_t row = (size_t)(b * T_STEPS + T_STEPS - 1);
        g_hr[row * 2 * DH + tid] = (tid < DH) ? s_h[tid] : s_r[tid - DH];
    }
}

#define OUT_SMEM_FLOATS (32768 + 8192)
__global__ void __launch_bounds__(256) out_gemm(
    const float* __restrict__ Wout, const float* __restrict__ bout,
    float* __restrict__ out)
{
    extern __shared__ float sh[];
    float* shW = sh;
    float* As  = sh + 32768;
    const int tid = threadIdx.x, lane = tid & 31, wid = tid >> 5;
    const int rbase = blockIdx.x * 32;

    {
        float4* dst = (float4*)shW;
        const float4* src = (const float4*)Wout;
        for (int i = tid; i < 8192; i += 256) dst[i] = src[i];
        float4* dA = (float4*)As;
        const float4* sA = (const float4*)(g_hr + (size_t)rbase * 256);
        for (int i = tid; i < 2048; i += 256) dA[i] = sA[i];
    }
    __syncthreads();

    float acc[4][4];
#pragma unroll
    for (int i = 0; i < 4; i++)
#pragma unroll
        for (int j = 0; j < 4; j++) acc[i][j] = 0.f;

    const int c0 = lane * 4;
    const int r0 = wid * 4;
#pragma unroll 4
    for (int k = 0; k < 256; k++) {
        float4 wv = ((const float4*)shW)[k * 32 + lane];
#pragma unroll
        for (int i = 0; i < 4; i++) {
            float av = As[(r0 + i) * 256 + k];
            acc[i][0] = fmaf(av, wv.x, acc[i][0]);
            acc[i][1] = fmaf(av, wv.y, acc[i][1]);
            acc[i][2] = fmaf(av, wv.z, acc[i][2]);
            acc[i][3] = fmaf(av, wv.w, acc[i][3]);
        }
    }
    float4 bo = *reinterpret_cast<const float4*>(bout + c0);
#pragma unroll
    for (int i = 0; i < 4; i++) {
        float4 o4 = make_float4(acc[i][0] + bo.x, acc[i][1] + bo.y,
                                acc[i][2] + bo.z, acc[i][3] + bo.w);
        *reinterpret_cast<float4*>(out + (size_t)(rbase + r0 + i) * 128 + c0) = o4;
    }
}

extern "C" void kernel_launch(void* const* d_in, const int* in_sizes, int n_in,
                              void* d_out, int out_size)
{
    const float* x    = (const float*)d_in[0];
    const float* Wxh  = (const float*)d_in[1];
    const float* Whh  = (const float*)d_in[2];
    const float* Wrh  = (const float*)d_in[3];
    const float* bh   = (const float*)d_in[4];
    const float* Wout = (const float*)d_in[5];
    const float* bout = (const float*)d_in[6];
    const float* Wr   = (const float*)d_in[7];
    const float* br   = (const float*)d_in[8];
    const float* Ww   = (const float*)d_in[9];
    const float* bw   = (const float*)d_in[10];
    float* out = (float*)d_out;

    cudaFuncSetAttribute(ntm_kernel, cudaFuncAttributeMaxDynamicSharedMemorySize,
                         SMEM_FLOATS * sizeof(float));
    cudaFuncSetAttribute(out_gemm, cudaFuncAttributeMaxDynamicSharedMemorySize,
                         OUT_SMEM_FLOATS * sizeof(float));

    k_xh<<<BS, 256>>>(x, Wxh, bh);                      // 0
    k_minit<<<BS, 256>>>();                             // 1
    k_repack<<<128, 256>>>(Whh, Wrh, Wr, Ww);           // 2
    ntm_kernel<<<BS, NTHR, SMEM_FLOATS * sizeof(float)>>>(br, bw);  // 3 (ncu)
    out_gemm<<<BS * T_STEPS / 32, 256, OUT_SMEM_FLOATS * sizeof(float)>>>(
        Wout, bout, out);                               // 4
}

// round 15
// speedup vs baseline: 1.2043x; 1.0221x over previous
#include <cuda_runtime.h>
#include <math.h>

#define BS 128
#define T_STEPS 32
#define DIN 128
#define DH 128
#define NS 512
#define NTHR 512
#define NWARP 16
#define EPS 1e-8f
#define WLD 784               // [Whh(128)|Wrh(128)|o-cols 528]
#define ROWS_S 96
#define ROWS_G 32

typedef unsigned long long ull;

__device__ float g_memU[(size_t)BS * ROWS_G * NS];
__device__ float g_hr[(size_t)BS * T_STEPS * 2 * DH];
__device__ float g_xh[(size_t)BS * T_STEPS * DH];
__device__ float g_Wcat[128 * WLD];

#define OFF_MEM   0
#define OFF_KP    (OFF_MEM  + 49152)
#define OFF_EA    (OFF_KP   + 256)
#define OFF_BIAS  (OFF_EA   + 256)
#define OFF_O     (OFF_BIAS + 528)
#define OFF_H     (OFF_O    + 528)
#define OFF_R     (OFF_H    + 128)
#define OFF_P4    (OFF_R    + 128)       // 800 float4 = 3200 floats
#define OFF_WPRE  (OFF_P4   + 3200)
#define OFF_WR    (OFF_WPRE + 512)
#define OFF_WW    (OFF_WR   + 512)
#define OFF_WTMP  (OFF_WW   + 512)
#define OFF_EVR   (OFF_WTMP + 512)
#define OFF_EVW   (OFF_EVR  + 512)
#define OFF_REDA  (OFF_EVW  + 512)
#define OFF_REDB  (OFF_REDA + 16)
#define OFF_KNR   (OFF_REDB + 16)
#define OFF_KNW   (OFF_KNR  + 16)
#define SMEM_FLOATS (OFF_KNW + 16)       // 57312 floats = 229248 B (< 232448)

__device__ __forceinline__ ull pack2(float lo, float hi) {
    ull r; asm("mov.b64 %0, {%1, %2};" : "=l"(r) : "f"(lo), "f"(hi)); return r;
}
__device__ __forceinline__ float2 unpack2(ull v) {
    float2 r; asm("mov.b64 {%0, %1}, %2;" : "=f"(r.x), "=f"(r.y) : "l"(v)); return r;
}
__device__ __forceinline__ ull ffma2(ull a, ull b, ull c) {
    ull d; asm("fma.rn.f32x2 %0, %1, %2, %3;" : "=l"(d) : "l"(a), "l"(b), "l"(c)); return d;
}
__device__ __forceinline__ ull fmul2(ull a, ull b) {
    ull d; asm("mul.rn.f32x2 %0, %1, %2;" : "=l"(d) : "l"(a), "l"(b)); return d;
}
__device__ __forceinline__ void ffma2_f4(float4 w, ull hb, ull& a01, ull& a23) {
    a01 = ffma2(pack2(w.x, w.y), hb, a01);
    a23 = ffma2(pack2(w.z, w.w), hb, a23);
}
__device__ __forceinline__ float softplusf_(float x) {
    return x > 20.f ? x : log1pf(expf(x));
}
__device__ __forceinline__ float sigmoidf_(float x) {
    return 1.f / (1.f + expf(-x));
}
__device__ __forceinline__ float wredsum(float v) {
#pragma unroll
    for (int o = 16; o; o >>= 1) v += __shfl_xor_sync(0xffffffffu, v, o);
    return v;
}
#define BAR_ATTN() asm volatile("bar.sync 1, 256;" ::: "memory")

__global__ void __launch_bounds__(256) k_xh(
    const float* __restrict__ x, const float* __restrict__ Wxh,
    const float* __restrict__ bh)
{
    const int b = blockIdx.x, tid = threadIdx.x;
    const float* xb = x + (size_t)b * T_STEPS * DIN;
    for (int idx = tid; idx < T_STEPS * DH; idx += 256) {
        int t = idx >> 7, j = idx & 127;
        float acc = bh[j];
        const float* xr = xb + t * DIN;
#pragma unroll 8
        for (int k = 0; k < DIN; k++) acc = fmaf(xr[k], Wxh[k * DH + j], acc);
        g_xh[(size_t)b * T_STEPS * DH + idx] = acc;
    }
}

__global__ void __launch_bounds__(256) k_minit()
{
    const int b = blockIdx.x, tid = threadIdx.x;
    float4 iv = make_float4(1e-6f, 1e-6f, 1e-6f, 1e-6f);
    float4* gu = reinterpret_cast<float4*>(g_memU + (size_t)b * ROWS_G * NS);
    for (int i = tid; i < ROWS_G * NS / 4; i += 256) gu[i] = iv;
}

__global__ void __launch_bounds__(256) k_repack(
    const float* __restrict__ Whh, const float* __restrict__ Wrh,
    const float* __restrict__ Wr,  const float* __restrict__ Ww)
{
    const int k = blockIdx.x, tid = threadIdx.x;
    float* dst = g_Wcat + (size_t)k * WLD;
    for (int c = tid; c < WLD; c += 256) {
        float v;
        if (c < 128)       v = Whh[(size_t)k * 128 + c];
        else if (c < 256)  v = Wrh[(size_t)k * 128 + (c - 128)];
        else if (c < 392) { int cc = c - 256; v = (cc < 134) ? Wr[(size_t)k * 134 + cc] : 0.f; }
        else              { int cc = c - 392; v = (cc < 390) ? Ww[(size_t)k * 390 + cc] : 0.f; }
        dst[c] = v;
    }
}

__global__ void __launch_bounds__(NTHR, 1) ntm_kernel(
    const float* __restrict__ br, const float* __restrict__ bw)
{
    extern __shared__ float sm[];
    float*  s_mem = sm + OFF_MEM;
    float4* s_kp  = (float4*)(sm + OFF_KP);
    float*  s_kpf = sm + OFF_KP;
    float2* s_ea  = (float2*)(sm + OFF_EA);
    float*  s_eaf = sm + OFF_EA;
    float*  s_bias= sm + OFF_BIAS;
    float*  s_o   = sm + OFF_O;
    float*  s_h   = sm + OFF_H;
    float*  s_r   = sm + OFF_R;
    float4* s_p4  = (float4*)(sm + OFF_P4);
    float*  s_p4f = sm + OFF_P4;
    float*  s_wpre= sm + OFF_WPRE;
    float*  s_wr  = sm + OFF_WR;
    float*  s_ww  = sm + OFF_WW;
    float*  s_wtmp= sm + OFF_WTMP;
    float*  s_evr = sm + OFF_EVR;
    float*  s_evw = sm + OFF_EVW;
    float*  s_redA= sm + OFF_REDA;
    float*  s_redB= sm + OFF_REDB;
    float*  s_knr = sm + OFF_KNR;
    float*  s_knw = sm + OFF_KNW;

    const int tid = threadIdx.x;
    const int wid = tid >> 5, lane = tid & 31;
    const int b = blockIdx.x;

    {
        float v;
        if (tid < 134)       v = br[tid];
        else if (tid < 136)  v = 0.f;
        else                 v = bw[tid - 136];
        s_bias[tid] = v;
        if (tid < 16) s_bias[512 + tid] = (512 + tid < 526) ? bw[512 + tid - 136] : 0.f;
    }
    {
        float4 iv = make_float4(1e-6f, 1e-6f, 1e-6f, 1e-6f);
        float4* mb = (float4*)s_mem;
        for (int i = tid; i < ROWS_S * NS / 4; i += NTHR) mb[i] = iv;
    }
    if (tid < DH) { s_h[tid] = 0.f; s_r[tid] = 0.f; }
    if (tid < 256) s_p4[544 + tid] = make_float4(0.f, 0.f, 0.f, 0.f); // Whh·h0 = 0
    s_wpre[tid] = 1.f / NS;
    __syncthreads();

    float* mU = g_memU + (size_t)b * ROWS_G * NS;
    const float* xh_b = g_xh + (size_t)b * T_STEPS * DH;
    const unsigned kp_base = (unsigned)__cvta_generic_to_shared(s_kp);

    for (int t = 0; t < T_STEPS; t++) {
        // ==== P1: Wrh-only matvec (512 tasks, k=8) + xh prefetch + history ====
        float xh_val = 0.f;
        {
            if (tid < DH) xh_val = xh_b[t * DH + tid];
            if (t > 0 && tid < 2 * DH) {
                size_t row = (size_t)(b * T_STEPS + t - 1);
                g_hr[row * 2 * DH + tid] = (tid < DH) ? s_h[tid] : s_r[tid - DH];
            }
            const int ks = tid >> 5;          // 0..15
            const int jq = tid & 31;
            const int k0 = ks * 8;
            ull a01 = 0ull, a23 = 0ull;
#pragma unroll
            for (int k = 0; k < 8; k++) {
                float rv = s_r[k0 + k];
                float4 w = *(const float4*)(g_Wcat + (size_t)(k0 + k) * WLD + 128 + jq * 4);
                ffma2_f4(w, pack2(rv, rv), a01, a23);
            }
            float2 lo = unpack2(a01), hi = unpack2(a23);
            s_p4[tid] = make_float4(lo.x, lo.y, hi.x, hi.y);
            __syncthreads();
            // ==== P2: h-reduce (Wrh fresh + Whh precomputed) + tanh ====
            if (tid < DH) {
                int jq2 = tid >> 2, comp = tid & 3;
                float sum = xh_val;
#pragma unroll
                for (int ks2 = 0; ks2 < 16; ks2++)
                    sum += s_p4f[(ks2 * 32 + jq2) * 4 + comp];
#pragma unroll
                for (int k8 = 0; k8 < 8; k8++)
                    sum += s_p4f[(544 + k8 * 32 + jq2) * 4 + comp];
                s_h[tid] = tanhf(sum);
            }
            __syncthreads();
        }

        // ==== P3: o-matvec (512 main k=32 + 32 tail on warp 15) ====
        {
            const int q  = tid & 127;
            const int ks = tid >> 7;
            const int col = 256 + q * 4;
            const int k0 = ks * 32;
            ull a01a = 0ull, a23a = 0ull, a01b = 0ull, a23b = 0ull;
#pragma unroll 8
            for (int k = 0; k < 32; k += 2) {
                float h0 = s_h[k0 + k], h1 = s_h[k0 + k + 1];
                float4 w0 = *(const float4*)(g_Wcat + (size_t)(k0 + k) * WLD + col);
                float4 w1 = *(const float4*)(g_Wcat + (size_t)(k0 + k + 1) * WLD + col);
                ffma2_f4(w0, pack2(h0, h0), a01a, a23a);
                ffma2_f4(w1, pack2(h1, h1), a01b, a23b);
            }
            const ull ONE2 = pack2(1.f, 1.f);
            float2 lo = unpack2(ffma2(a01b, ONE2, a01a));
            float2 hi = unpack2(ffma2(a23b, ONE2, a23a));
            s_p4[ks * 128 + q] = make_float4(lo.x, lo.y, hi.x, hi.y);

            if (tid >= 480) {
                int t2 = tid - 480;
                int qt = t2 >> 3, kst = t2 & 7;
                int colt = 256 + (128 + qt) * 4;
                int k0t = kst * 16;
                ull b01a = 0ull, b23a = 0ull, b01b = 0ull, b23b = 0ull;
#pragma unroll
                for (int k = 0; k < 16; k += 2) {
                    float h0 = s_h[k0t + k], h1 = s_h[k0t + k + 1];
                    float4 w0 = *(const float4*)(g_Wcat + (size_t)(k0t + k) * WLD + colt);
                    float4 w1 = *(const float4*)(g_Wcat + (size_t)(k0t + k + 1) * WLD + colt);
                    ffma2_f4(w0, pack2(h0, h0), b01a, b23a);
                    ffma2_f4(w1, pack2(h1, h1), b01b, b23b);
                }
                float2 tl = unpack2(ffma2(b01b, ONE2, b01a));
                float2 th = unpack2(ffma2(b23b, ONE2, b23a));
                s_p4[512 + t2] = make_float4(tl.x, tl.y, th.x, th.y);
            }
        }
        __syncthreads();

        // ==== P4: o-reduce + packing + key-norm partials ====
        {
            float u2r = 0.f, u2w = 0.f;
            {
                const int c = tid;
                int quad = c >> 2, comp = c & 3;
                float val = s_bias[c];
#pragma unroll
                for (int ks = 0; ks < 4; ks++)
                    val += s_p4f[(ks * 128 + quad) * 4 + comp];
                if ((c >= 128 && c < 134) || (c >= 264 && c < 270)) s_o[c] = val;
                if (c < 128) {
                    s_kpf[(c & 63) * 4 + (c >> 6)] = val;
                    u2r = val * val;
                } else if (c >= 136 && c < 264) {
                    int m = c - 136;
                    s_kpf[(m & 63) * 4 + 2 + (m >> 6)] = val;
                    u2w = val * val;
                } else if (c >= 270 && c < 398) {
                    s_eaf[(c - 270) * 2 + 0] = sigmoidf_(val);
                } else if (c >= 398) {
                    s_eaf[(c - 398) * 2 + 1] = tanhf(val);
                }
            }
            if (tid < 16) {
                const int c2 = 512 + tid;
                int qt = tid >> 2, comp = c2 & 3;
                float val = s_bias[c2];
#pragma unroll
                for (int kst = 0; kst < 8; kst++)
                    val += s_p4f[(512 + qt * 8 + kst) * 4 + comp];
                if (c2 < 526) s_eaf[(c2 - 398) * 2 + 1] = tanhf(val);
            }
            u2r = wredsum(u2r);
            u2w = wredsum(u2w);
            if (!lane) { s_knr[wid] = u2r; s_knw[wid] = u2w; }
            __syncthreads();
        }

        // ==== pass A (all 512 threads, slot=tid): global half first ====
        {
            ull drP = 0ull, dwP = 0ull, nmP = 0ull;
#pragma unroll 8
            for (int m = 32; m < 64; m++) {
                float u0 = mU[(m - 32) * NS + tid];
                float v0 = s_mem[m * NS + tid];
                ull vv = pack2(v0, u0);
                ull kr2, kw2;
                asm("ld.shared.v2.b64 {%0, %1}, [%2];"
                    : "=l"(kr2), "=l"(kw2) : "r"(kp_base + m * 16));
                drP = ffma2(vv, kr2, drP);
                dwP = ffma2(vv, kw2, dwP);
                nmP = ffma2(vv, vv, nmP);
            }
#pragma unroll 8
            for (int m = 0; m < 32; m++) {
                float v0 = s_mem[m * NS + tid];
                float u0 = s_mem[(m + 64) * NS + tid];
                ull vv = pack2(v0, u0);
                ull kr2, kw2;
                asm("ld.shared.v2.b64 {%0, %1}, [%2];"
                    : "=l"(kr2), "=l"(kw2) : "r"(kp_base + m * 16));
                drP = ffma2(vv, kr2, drP);
                dwP = ffma2(vv, kw2, dwP);
                nmP = ffma2(vv, vv, nmP);
            }
            float2 drp = unpack2(drP), dwp = unpack2(dwP), nmp = unpack2(nmP);
            s_p4[tid] = make_float4(drp.x + drp.y, dwp.x + dwp.y, nmp.x + nmp.y, 0.f);
        }
        __syncthreads();                                    // B0

        // ==== P5: warps 0-7 attention (2 slots/thread) || warps 8-15 Whh·h_t ====
        if (wid < 8) {
            const int s0 = tid << 1, s1 = s0 + 1;
            float4 pa = s_p4[s0], pb = s_p4[s1];
            float knr, knw;
            {
                float a = 0.f, c = 0.f;
#pragma unroll
                for (int i = 0; i < NWARP; i++) { a += s_knr[i]; c += s_knw[i]; }
                knr = sqrtf(a); knw = sqrtf(c);
            }
            float beta_r = softplusf_(s_o[128]);
            float g_r = sigmoidf_(s_o[129]);
            float gamma_r = 1.f + softplusf_(s_o[133]);
            float sr0, sr1, sr2;
            {
                float q0 = s_o[130], q1 = s_o[131], q2 = s_o[132];
                float qm = fmaxf(q0, fmaxf(q1, q2));
                float e0 = expf(q0 - qm), e1 = expf(q1 - qm), e2 = expf(q2 - qm);
                float qs = e0 + e1 + e2;
                sr0 = e0 / qs; sr1 = e1 / qs; sr2 = e2 / qs;
            }
            float beta_w = softplusf_(s_o[264]);
            float g_w = sigmoidf_(s_o[265]);
            float gamma_w = 1.f + softplusf_(s_o[269]);
            float sw0, sw1, sw2;
            {
                float q0 = s_o[266], q1 = s_o[267], q2 = s_o[268];
                float qm = fmaxf(q0, fmaxf(q1, q2));
                float e0 = expf(q0 - qm), e1 = expf(q1 - qm), e2 = expf(q2 - qm);
                float qs = e0 + e1 + e2;
                sw0 = e0 / qs; sw1 = e1 / qs; sw2 = e2 / qs;
            }
            float nrm0 = sqrtf(pa.z), nrm1 = sqrtf(pb.z);
            float ev_r0 = __expf(beta_r * pa.x / (nrm0 * knr + EPS));
            float ev_r1 = __expf(beta_r * pb.x / (nrm1 * knr + EPS));
            float ev_w0 = __expf(beta_w * pa.y / (nrm0 * knw + EPS));
            float ev_w1 = __expf(beta_w * pb.y / (nrm1 * knw + EPS));
            s_evr[s0] = ev_r0; s_evr[s1] = ev_r1;
            s_evw[s0] = ev_w0; s_evw[s1] = ev_w1;
            {
                float vr = wredsum(ev_r0 + ev_r1), vw = wredsum(ev_w0 + ev_w1);
                if (!lane) { s_redA[wid] = vr; s_redB[wid] = vw; }
            }
            BAR_ATTN();                                     // B1
            float totr = 0.f, totw = 0.f;
#pragma unroll
            for (int i = 0; i < 8; i++) { totr += s_redA[i]; totw += s_redB[i]; }
            float inv_tr = 1.f / totr, inv_tw = 1.f / totw;
            const int sm1 = (s0 - 1) & (NS - 1), sp1 = (s1 + 1) & (NS - 1);
            float wpre0 = s_wpre[s0], wpre1 = s_wpre[s1];
            float wg0 = g_r * (ev_r0 * inv_tr) + (1.f - g_r) * wpre0;
            float wg1 = g_r * (ev_r1 * inv_tr) + (1.f - g_r) * wpre1;
            float wg_m = g_r * (s_evr[sm1] * inv_tr) + (1.f - g_r) * s_wpre[sm1];
            float wg_p = g_r * (s_evr[sp1] * inv_tr) + (1.f - g_r) * s_wpre[sp1];
            float wraw0 = __powf(sr0 * wg1 + sr1 * wg0 + sr2 * wg_m, gamma_r);
            float wraw1 = __powf(sr0 * wg_p + sr1 * wg1 + sr2 * wg0, gamma_r);
            s_wtmp[s0] = wraw0; s_wtmp[s1] = wraw1;
            {
                float v = wredsum(wraw0 + wraw1);
                if (!lane) s_knr[wid] = v;                  // knr partials dead now
            }
            BAR_ATTN();                                     // B2
            float sumr = 0.f;
#pragma unroll
            for (int i = 0; i < 8; i++) sumr += s_knr[i];
            float inv_r = 1.f / (sumr + EPS);
            float w_r0 = wraw0 * inv_r, w_r1 = wraw1 * inv_r;
            s_wr[s0] = w_r0; s_wr[s1] = w_r1;
            float wr_m = s_wtmp[sm1] * inv_r, wr_p = s_wtmp[sp1] * inv_r;
            float wgw0 = g_w * (ev_w0 * inv_tw) + (1.f - g_w) * w_r0;
            float wgw1 = g_w * (ev_w1 * inv_tw) + (1.f - g_w) * w_r1;
            float wgw_m = g_w * (s_evw[sm1] * inv_tw) + (1.f - g_w) * wr_m;
            float wgw_p = g_w * (s_evw[sp1] * inv_tw) + (1.f - g_w) * wr_p;
            float wraww0 = __powf(sw0 * wgw1 + sw1 * wgw0 + sw2 * wgw_m, gamma_w);
            float wraww1 = __powf(sw0 * wgw_p + sw1 * wgw1 + sw2 * wgw0, gamma_w);
            {
                float v = wredsum(wraww0 + wraww1);
                if (!lane) s_knw[wid] = v;
            }
            BAR_ATTN();                                     // B3
            float sumw = 0.f;
#pragma unroll
            for (int i = 0; i < 8; i++) sumw += s_knw[i];
            float w_w0 = wraww0 / (sumw + EPS), w_w1 = wraww1 / (sumw + EPS);
            s_ww[s0] = w_w0; s_ww[s1] = w_w1;
            s_wpre[s0] = w_w0; s_wpre[s1] = w_w1;
        } else {
            // Whh · h_t precompute for step t+1 (h_t stable in s_h)
            const int idx = tid - 256;        // 0..255
            const int k8 = idx >> 5, jq = idx & 31;
            const int k0 = k8 * 16;
            ull a01 = 0ull, a23 = 0ull;
#pragma unroll
            for (int k = 0; k < 16; k++) {
                float hv = s_h[k0 + k];
                float4 w = *(const float4*)(g_Wcat + (size_t)(k0 + k) * WLD + jq * 4);
                ffma2_f4(w, pack2(hv, hv), a01, a23);
            }
            float2 lo = unpack2(a01), hi = unpack2(a23);
            s_p4[544 + idx] = make_float4(lo.x, lo.y, hi.x, hi.y);
        }
        __syncthreads();                                    // B4

        // ==== P6: pass B — 2 global rows (batched loads), then 6 smem rows ====
        {
            ull wr01[4], wr23[4], ww01[4], ww23[4];
            {
                const float4* wrv = (const float4*)s_wr;
                const float4* wwv = (const float4*)s_ww;
#pragma unroll
                for (int c = 0; c < 4; c++) {
                    float4 a = wrv[c * 32 + lane];
                    float4 bq = wwv[c * 32 + lane];
                    wr01[c] = pack2(a.x, a.y);   wr23[c] = pack2(a.z, a.w);
                    ww01[c] = pack2(bq.x, bq.y); ww23[c] = pack2(bq.z, bq.w);
                }
            }
            // global rows, all 8 loads issued first
            {
                int g0 = wid * 2, g1 = g0 + 1;
                ulonglong2* rp0 = (ulonglong2*)(mU + (size_t)g0 * NS);
                ulonglong2* rp1 = (ulonglong2*)(mU + (size_t)g1 * NS);
                ulonglong2 vA[4], vB[4];
#pragma unroll
                for (int c = 0; c < 4; c++) { vA[c] = rp0[c * 32 + lane]; }
#pragma unroll
                for (int c = 0; c < 4; c++) { vB[c] = rp1[c * 32 + lane]; }
#pragma unroll
                for (int rr = 0; rr < 2; rr++) {
                    int m = ROWS_S + (rr ? g1 : g0);
                    ulonglong2* rp = rr ? rp1 : rp0;
                    ulonglong2* vv = rr ? vB : vA;
                    float2 ea = s_ea[m];
                    ull e2n = pack2(-ea.x, -ea.x), a2 = pack2(ea.y, ea.y);
                    ull r01 = 0ull, r23 = 0ull;
#pragma unroll
                    for (int c = 0; c < 4; c++) {
                        ulonglong2 v = vv[c];
                        r01 = ffma2(wr01[c], v.x, r01);
                        r23 = ffma2(wr23[c], v.y, r23);
                        ull t01 = fmul2(ww01[c], e2n);
                        ull t23 = fmul2(ww23[c], e2n);
                        ull n01 = ffma2(v.x, t01, v.x);
                        ull n23 = ffma2(v.y, t23, v.y);
                        n01 = ffma2(ww01[c], a2, n01);
                        n23 = ffma2(ww23[c], a2, n23);
                        ulonglong2 o2; o2.x = n01; o2.y = n23;
                        rp[c * 32 + lane] = o2;
                    }
                    float2 p0 = unpack2(r01), p1 = unpack2(r23);
                    float sumv = wredsum(p0.x + p0.y + p1.x + p1.y);
                    if (!lane) s_r[m] = sumv;
                }
            }
#pragma unroll
            for (int rr = 0; rr < 6; rr++) {
                int m = wid * 6 + rr;
                ulonglong2* rp = (ulonglong2*)(s_mem + (size_t)m * NS);
                float2 ea = s_ea[m];
                ull e2n = pack2(-ea.x, -ea.x), a2 = pack2(ea.y, ea.y);
                ull r01 = 0ull, r23 = 0ull;
#pragma unroll
                for (int c = 0; c < 4; c++) {
                    ulonglong2 v = rp[c * 32 + lane];
                    r01 = ffma2(wr01[c], v.x, r01);
                    r23 = ffma2(wr23[c], v.y, r23);
                    ull t01 = fmul2(ww01[c], e2n);
                    ull t23 = fmul2(ww23[c], e2n);
                    ull n01 = ffma2(v.x, t01, v.x);
                    ull n23 = ffma2(v.y, t23, v.y);
                    n01 = ffma2(ww01[c], a2, n01);
                    n23 = ffma2(ww23[c], a2, n23);
                    ulonglong2 o2; o2.x = n01; o2.y = n23;
                    rp[c * 32 + lane] = o2;
                }
                float2 p0 = unpack2(r01), p1 = unpack2(r23);
                float sumv = wredsum(p0.x + p0.y + p1.x + p1.y);
                if (!lane) s_r[m] = sumv;
            }
            __syncthreads();
        }
    }

    if (tid < 2 * DH) {
        size_t row = (size_t)(b * T_STEPS + T_STEPS - 1);
        g_hr[row * 2 * DH + tid] = (tid < DH) ? s_h[tid] : s_r[tid - DH];
    }
}

#define OUT_SMEM_FLOATS (32768 + 8192)
__global__ void __launch_bounds__(256) out_gemm(
    const float* __restrict__ Wout, const float* __restrict__ bout,
    float* __restrict__ out)
{
    extern __shared__ float sh[];
    float* shW = sh;
    float* As  = sh + 32768;
    const int tid = threadIdx.x, lane = tid & 31, wid = tid >> 5;
    const int rbase = blockIdx.x * 32;

    {
        float4* dst = (float4*)shW;
        const float4* src = (const float4*)Wout;
        for (int i = tid; i < 8192; i += 256) dst[i] = src[i];
        float4* dA = (float4*)As;
        const float4* sA = (const float4*)(g_hr + (size_t)rbase * 256);
        for (int i = tid; i < 2048; i += 256) dA[i] = sA[i];
    }
    __syncthreads();

    float acc[4][4];
#pragma unroll
    for (int i = 0; i < 4; i++)
#pragma unroll
        for (int j = 0; j < 4; j++) acc[i][j] = 0.f;

    const int c0 = lane * 4;
    const int r0 = wid * 4;
#pragma unroll 4
    for (int k = 0; k < 256; k++) {
        float4 wv = ((const float4*)shW)[k * 32 + lane];
#pragma unroll
        for (int i = 0; i < 4; i++) {
            float av = As[(r0 + i) * 256 + k];
            acc[i][0] = fmaf(av, wv.x, acc[i][0]);
            acc[i][1] = fmaf(av, wv.y, acc[i][1]);
            acc[i][2] = fmaf(av, wv.z, acc[i][2]);
            acc[i][3] = fmaf(av, wv.w, acc[i][3]);
        }
    }
    float4 bo = *reinterpret_cast<const float4*>(bout + c0);
#pragma unroll
    for (int i = 0; i < 4; i++) {
        float4 o4 = make_float4(acc[i][0] + bo.x, acc[i][1] + bo.y,
                                acc[i][2] + bo.z, acc[i][3] + bo.w);
        *reinterpret_cast<float4*>(out + (size_t)(rbase + r0 + i) * 128 + c0) = o4;
    }
}

extern "C" void kernel_launch(void* const* d_in, const int* in_sizes, int n_in,
                              void* d_out, int out_size)
{
    const float* x    = (const float*)d_in[0];
    const float* Wxh  = (const float*)d_in[1];
    const float* Whh  = (const float*)d_in[2];
    const float* Wrh  = (const float*)d_in[3];
    const float* bh   = (const float*)d_in[4];
    const float* Wout = (const float*)d_in[5];
    const float* bout = (const float*)d_in[6];
    const float* Wr   = (const float*)d_in[7];
    const float* br   = (const float*)d_in[8];
    const float* Ww   = (const float*)d_in[9];
    const float* bw   = (const float*)d_in[10];
    float* out = (float*)d_out;

    cudaFuncSetAttribute(ntm_kernel, cudaFuncAttributeMaxDynamicSharedMemorySize,
                         SMEM_FLOATS * sizeof(float));
    cudaFuncSetAttribute(out_gemm, cudaFuncAttributeMaxDynamicSharedMemorySize,
                         OUT_SMEM_FLOATS * sizeof(float));

    k_xh<<<BS, 256>>>(x, Wxh, bh);                      // 0
    k_minit<<<BS, 256>>>();                             // 1
    k_repack<<<128, 256>>>(Whh, Wrh, Wr, Ww);           // 2
    ntm_kernel<<<BS, NTHR, SMEM_FLOATS * sizeof(float)>>>(br, bw);  // 3 (ncu)
    out_gemm<<<BS * T_STEPS / 32, 256, OUT_SMEM_FLOATS * sizeof(float)>>>(
        Wout, bout, out);                               // 4
}

// round 17
// speedup vs baseline: 1.2741x; 1.0580x over previous
#include <cuda_runtime.h>
#include <math.h>

#define BS 128
#define T_STEPS 32
#define DIN 128
#define DH 128
#define NS 512
#define NTHR 512
#define NWARP 16
#define EPS 1e-8f
#define WLD 784               // [Whh(128)|Wrh(128)|o-cols 528]
#define ROWS_S 96
#define ROWS_G 32

typedef unsigned long long ull;

__device__ float g_memU[(size_t)BS * ROWS_G * NS];
__device__ float g_hr[(size_t)BS * T_STEPS * 2 * DH];
__device__ float g_xh[(size_t)BS * T_STEPS * DH];
__device__ float g_Wcat[128 * WLD];

#define OFF_MEM   0
#define OFF_KP    (OFF_MEM  + 49152)
#define OFF_EA    (OFF_KP   + 256)
#define OFF_BIAS  (OFF_EA   + 256)
#define OFF_O     (OFF_BIAS + 528)
#define OFF_H     (OFF_O    + 528)
#define OFF_R     (OFF_H    + 128)
#define OFF_P4    (OFF_R    + 128)       // 800 float4 = 3200 floats
#define OFF_WPRE  (OFF_P4   + 3200)
#define OFF_WR    (OFF_WPRE + 512)
#define OFF_WW    (OFF_WR   + 512)
#define OFF_WTMP  (OFF_WW   + 512)
#define OFF_EVR   (OFF_WTMP + 512)
#define OFF_EVW   (OFF_EVR  + 512)
#define OFF_REDA  (OFF_EVW  + 512)
#define OFF_REDB  (OFF_REDA + 16)
#define OFF_KNR   (OFF_REDB + 16)
#define OFF_KNW   (OFF_KNR  + 16)
#define SMEM_FLOATS (OFF_KNW + 16)       // 57312 floats = 229248 B

__device__ __forceinline__ ull pack2(float lo, float hi) {
    ull r; asm("mov.b64 %0, {%1, %2};" : "=l"(r) : "f"(lo), "f"(hi)); return r;
}
__device__ __forceinline__ float2 unpack2(ull v) {
    float2 r; asm("mov.b64 {%0, %1}, %2;" : "=f"(r.x), "=f"(r.y) : "l"(v)); return r;
}
__device__ __forceinline__ ull ffma2(ull a, ull b, ull c) {
    ull d; asm("fma.rn.f32x2 %0, %1, %2, %3;" : "=l"(d) : "l"(a), "l"(b), "l"(c)); return d;
}
__device__ __forceinline__ ull fmul2(ull a, ull b) {
    ull d; asm("mul.rn.f32x2 %0, %1, %2;" : "=l"(d) : "l"(a), "l"(b)); return d;
}
__device__ __forceinline__ void ffma2_f4(float4 w, ull hb, ull& a01, ull& a23) {
    a01 = ffma2(pack2(w.x, w.y), hb, a01);
    a23 = ffma2(pack2(w.z, w.w), hb, a23);
}
__device__ __forceinline__ float softplusf_(float x) {
    return x > 20.f ? x : log1pf(expf(x));
}
__device__ __forceinline__ float sigmoidf_(float x) {
    return 1.f / (1.f + expf(-x));
}
__device__ __forceinline__ float wredsum(float v) {
#pragma unroll
    for (int o = 16; o; o >>= 1) v += __shfl_xor_sync(0xffffffffu, v, o);
    return v;
}
#define BAR_ATTN() asm volatile("bar.sync 1, 256;" ::: "memory")

// Prep 1 (v2): 512 threads, x staged in smem, f32x2 weight pairs, 4x t-reuse.
__global__ void __launch_bounds__(512) k_xh(
    const float* __restrict__ x, const float* __restrict__ Wxh,
    const float* __restrict__ bh)
{
    __shared__ float s_x[T_STEPS * DIN];
    const int b = blockIdx.x, tid = threadIdx.x;
    const float* xb = x + (size_t)b * T_STEPS * DIN;
    for (int i = tid; i < T_STEPS * DIN; i += 512) s_x[i] = xb[i];
    __syncthreads();
    const int j2 = tid & 63, tg = tid >> 6;     // col-pair, t-group of 4
    ull acc[4] = {0ull, 0ull, 0ull, 0ull};
#pragma unroll 4
    for (int k = 0; k < DIN; k++) {
        ull w2 = *(const ull*)(Wxh + (size_t)k * DH + j2 * 2);
#pragma unroll
        for (int i = 0; i < 4; i++) {
            float xv = s_x[(tg * 4 + i) * DIN + k];
            acc[i] = ffma2(w2, pack2(xv, xv), acc[i]);
        }
    }
    float b0 = bh[j2 * 2], b1 = bh[j2 * 2 + 1];
#pragma unroll
    for (int i = 0; i < 4; i++) {
        float2 v = unpack2(acc[i]);
        int t = tg * 4 + i;
        g_xh[(size_t)b * T_STEPS * DH + t * DH + j2 * 2]     = v.x + b0;
        g_xh[(size_t)b * T_STEPS * DH + t * DH + j2 * 2 + 1] = v.y + b1;
    }
}

__global__ void __launch_bounds__(256) k_minit()
{
    const int b = blockIdx.x, tid = threadIdx.x;
    float4 iv = make_float4(1e-6f, 1e-6f, 1e-6f, 1e-6f);
    float4* gu = reinterpret_cast<float4*>(g_memU + (size_t)b * ROWS_G * NS);
    for (int i = tid; i < ROWS_G * NS / 4; i += 256) gu[i] = iv;
}

__global__ void __launch_bounds__(256) k_repack(
    const float* __restrict__ Whh, const float* __restrict__ Wrh,
    const float* __restrict__ Wr,  const float* __restrict__ Ww)
{
    const int k = blockIdx.x, tid = threadIdx.x;
    float* dst = g_Wcat + (size_t)k * WLD;
    for (int c = tid; c < WLD; c += 256) {
        float v;
        if (c < 128)       v = Whh[(size_t)k * 128 + c];
        else if (c < 256)  v = Wrh[(size_t)k * 128 + (c - 128)];
        else if (c < 392) { int cc = c - 256; v = (cc < 134) ? Wr[(size_t)k * 134 + cc] : 0.f; }
        else              { int cc = c - 392; v = (cc < 390) ? Ww[(size_t)k * 390 + cc] : 0.f; }
        dst[c] = v;
    }
}

__global__ void __launch_bounds__(NTHR, 1) ntm_kernel(
    const float* __restrict__ br, const float* __restrict__ bw)
{
    extern __shared__ float sm[];
    float*  s_mem = sm + OFF_MEM;
    float4* s_kp  = (float4*)(sm + OFF_KP);
    float*  s_kpf = sm + OFF_KP;
    float2* s_ea  = (float2*)(sm + OFF_EA);
    float*  s_eaf = sm + OFF_EA;
    float*  s_bias= sm + OFF_BIAS;
    float*  s_o   = sm + OFF_O;
    float*  s_h   = sm + OFF_H;
    float*  s_r   = sm + OFF_R;
    float4* s_p4  = (float4*)(sm + OFF_P4);
    float*  s_p4f = sm + OFF_P4;
    float*  s_wpre= sm + OFF_WPRE;
    float*  s_wr  = sm + OFF_WR;
    float*  s_ww  = sm + OFF_WW;
    float*  s_wtmp= sm + OFF_WTMP;
    float*  s_evr = sm + OFF_EVR;
    float*  s_evw = sm + OFF_EVW;
    float*  s_redA= sm + OFF_REDA;
    float*  s_redB= sm + OFF_REDB;
    float*  s_knr = sm + OFF_KNR;
    float*  s_knw = sm + OFF_KNW;

    const int tid = threadIdx.x;
    const int wid = tid >> 5, lane = tid & 31;
    const int b = blockIdx.x;

    {
        float v;
        if (tid < 134)       v = br[tid];
        else if (tid < 136)  v = 0.f;
        else                 v = bw[tid - 136];
        s_bias[tid] = v;
        if (tid < 16) s_bias[512 + tid] = (512 + tid < 526) ? bw[512 + tid - 136] : 0.f;
    }
    {
        float4 iv = make_float4(1e-6f, 1e-6f, 1e-6f, 1e-6f);
        float4* mb = (float4*)s_mem;
        for (int i = tid; i < ROWS_S * NS / 4; i += NTHR) mb[i] = iv;
    }
    if (tid < DH) { s_h[tid] = 0.f; s_r[tid] = 0.f; }
    if (tid < 256) s_p4[544 + tid] = make_float4(0.f, 0.f, 0.f, 0.f); // Whh·h0 = 0
    s_wpre[tid] = 1.f / NS;
    __syncthreads();

    float* mU = g_memU + (size_t)b * ROWS_G * NS;
    const float* xh_b = g_xh + (size_t)b * T_STEPS * DH;
    const unsigned kp_base = (unsigned)__cvta_generic_to_shared(s_kp);

    for (int t = 0; t < T_STEPS; t++) {
        float4 w0p, w1p;    // P3 prefetch (weight addresses are h-independent)
        // ==== P1: Wrh-only matvec (512 tasks, k=8) + xh prefetch + history ====
        float xh_val = 0.f;
        {
            if (tid < DH) xh_val = xh_b[t * DH + tid];
            if (t > 0 && tid < 2 * DH) {
                size_t row = (size_t)(b * T_STEPS + t - 1);
                g_hr[row * 2 * DH + tid] = (tid < DH) ? s_h[tid] : s_r[tid - DH];
            }
            const int ks = tid >> 5;
            const int jq = tid & 31;
            const int k0 = ks * 8;
            ull a01 = 0ull, a23 = 0ull;
#pragma unroll
            for (int k = 0; k < 8; k++) {
                float rv = s_r[k0 + k];
                float4 w = *(const float4*)(g_Wcat + (size_t)(k0 + k) * WLD + 128 + jq * 4);
                ffma2_f4(w, pack2(rv, rv), a01, a23);
            }
            float2 lo = unpack2(a01), hi = unpack2(a23);
            s_p4[tid] = make_float4(lo.x, lo.y, hi.x, hi.y);
            // prefetch P3's first two weight rows for this thread's task
            {
                const int q3 = tid & 127, ks3 = tid >> 7;
                const float* wp = g_Wcat + (size_t)(ks3 * 32) * WLD + 256 + q3 * 4;
                w0p = *(const float4*)wp;
                w1p = *(const float4*)(wp + WLD);
            }
            __syncthreads();
            // ==== P2: h-reduce (Wrh fresh + Whh precomputed) + tanh ====
            if (tid < DH) {
                int jq2 = tid >> 2, comp = tid & 3;
                float sum = xh_val;
#pragma unroll
                for (int ks2 = 0; ks2 < 16; ks2++)
                    sum += s_p4f[(ks2 * 32 + jq2) * 4 + comp];
#pragma unroll
                for (int k8 = 0; k8 < 8; k8++)
                    sum += s_p4f[(544 + k8 * 32 + jq2) * 4 + comp];
                s_h[tid] = tanhf(sum);
            }
            __syncthreads();
        }

        // ==== P3: o-matvec (512 main k=32, first 2 rows prefetched; +32 tail) ====
        {
            const int q  = tid & 127;
            const int ks = tid >> 7;
            const int col = 256 + q * 4;
            const int k0 = ks * 32;
            ull a01a = 0ull, a23a = 0ull, a01b = 0ull, a23b = 0ull;
            {
                float h0 = s_h[k0], h1 = s_h[k0 + 1];
                ffma2_f4(w0p, pack2(h0, h0), a01a, a23a);
                ffma2_f4(w1p, pack2(h1, h1), a01b, a23b);
            }
#pragma unroll 5
            for (int k = 2; k < 32; k += 2) {
                float h0 = s_h[k0 + k], h1 = s_h[k0 + k + 1];
                float4 w0 = *(const float4*)(g_Wcat + (size_t)(k0 + k) * WLD + col);
                float4 w1 = *(const float4*)(g_Wcat + (size_t)(k0 + k + 1) * WLD + col);
                ffma2_f4(w0, pack2(h0, h0), a01a, a23a);
                ffma2_f4(w1, pack2(h1, h1), a01b, a23b);
            }
            const ull ONE2 = pack2(1.f, 1.f);
            float2 lo = unpack2(ffma2(a01b, ONE2, a01a));
            float2 hi = unpack2(ffma2(a23b, ONE2, a23a));
            s_p4[ks * 128 + q] = make_float4(lo.x, lo.y, hi.x, hi.y);

            if (tid >= 480) {
                int t2 = tid - 480;
                int qt = t2 >> 3, kst = t2 & 7;
                int colt = 256 + (128 + qt) * 4;
                int k0t = kst * 16;
                ull b01a = 0ull, b23a = 0ull, b01b = 0ull, b23b = 0ull;
#pragma unroll
                for (int k = 0; k < 16; k += 2) {
                    float h0 = s_h[k0t + k], h1 = s_h[k0t + k + 1];
                    float4 w0 = *(const float4*)(g_Wcat + (size_t)(k0t + k) * WLD + colt);
                    float4 w1 = *(const float4*)(g_Wcat + (size_t)(k0t + k + 1) * WLD + colt);
                    ffma2_f4(w0, pack2(h0, h0), b01a, b23a);
                    ffma2_f4(w1, pack2(h1, h1), b01b, b23b);
                }
                float2 tl = unpack2(ffma2(b01b, ONE2, b01a));
                float2 th = unpack2(ffma2(b23b, ONE2, b23a));
                s_p4[512 + t2] = make_float4(tl.x, tl.y, th.x, th.y);
            }
        }
        __syncthreads();

        // ==== P4: o-reduce + packing + key-norm partials ====
        {
            float u2r = 0.f, u2w = 0.f;
            {
                const int c = tid;
                int quad = c >> 2, comp = c & 3;
                float val = s_bias[c];
#pragma unroll
                for (int ks = 0; ks < 4; ks++)
                    val += s_p4f[(ks * 128 + quad) * 4 + comp];
                if ((c >= 128 && c < 134) || (c >= 264 && c < 270)) s_o[c] = val;
                if (c < 128) {
                    s_kpf[(c & 63) * 4 + (c >> 6)] = val;
                    u2r = val * val;
                } else if (c >= 136 && c < 264) {
                    int m = c - 136;
                    s_kpf[(m & 63) * 4 + 2 + (m >> 6)] = val;
                    u2w = val * val;
                } else if (c >= 270 && c < 398) {
                    s_eaf[(c - 270) * 2 + 0] = sigmoidf_(val);
                } else if (c >= 398) {
                    s_eaf[(c - 398) * 2 + 1] = tanhf(val);
                }
            }
            if (tid < 16) {
                const int c2 = 512 + tid;
                int qt = tid >> 2, comp = c2 & 3;
                float val = s_bias[c2];
#pragma unroll
                for (int kst = 0; kst < 8; kst++)
                    val += s_p4f[(512 + qt * 8 + kst) * 4 + comp];
                if (c2 < 526) s_eaf[(c2 - 398) * 2 + 1] = tanhf(val);
            }
            u2r = wredsum(u2r);
            u2w = wredsum(u2w);
            if (!lane) { s_knr[wid] = u2r; s_knw[wid] = u2w; }
            __syncthreads();
        }

        // ==== pass A (all 512 threads, slot=tid): global half first ====
        {
            ull drP = 0ull, dwP = 0ull, nmP = 0ull;
#pragma unroll 8
            for (int m = 32; m < 64; m++) {
                float u0 = mU[(m - 32) * NS + tid];
                float v0 = s_mem[m * NS + tid];
                ull vv = pack2(v0, u0);
                ull kr2, kw2;
                asm("ld.shared.v2.b64 {%0, %1}, [%2];"
                    : "=l"(kr2), "=l"(kw2) : "r"(kp_base + m * 16));
                drP = ffma2(vv, kr2, drP);
                dwP = ffma2(vv, kw2, dwP);
                nmP = ffma2(vv, vv, nmP);
            }
#pragma unroll 8
            for (int m = 0; m < 32; m++) {
                float v0 = s_mem[m * NS + tid];
                float u0 = s_mem[(m + 64) * NS + tid];
                ull vv = pack2(v0, u0);
                ull kr2, kw2;
                asm("ld.shared.v2.b64 {%0, %1}, [%2];"
                    : "=l"(kr2), "=l"(kw2) : "r"(kp_base + m * 16));
                drP = ffma2(vv, kr2, drP);
                dwP = ffma2(vv, kw2, dwP);
                nmP = ffma2(vv, vv, nmP);
            }
            float2 drp = unpack2(drP), dwp = unpack2(dwP), nmp = unpack2(nmP);
            s_p4[tid] = make_float4(drp.x + drp.y, dwp.x + dwp.y, nmp.x + nmp.y, 0.f);
        }
        __syncthreads();                                    // B0

        // ==== P5: warps 0-7 attention (2 slots/thread) || warps 8-15 Whh·h_t ====
        if (wid < 8) {
            const int s0 = tid << 1, s1 = s0 + 1;
            float4 pa = s_p4[s0], pb = s_p4[s1];
            float knr, knw;
            {
                float a = 0.f, c = 0.f;
#pragma unroll
                for (int i = 0; i < NWARP; i++) { a += s_knr[i]; c += s_knw[i]; }
                knr = sqrtf(a); knw = sqrtf(c);
            }
            float beta_r = softplusf_(s_o[128]);
            float g_r = sigmoidf_(s_o[129]);
            float gamma_r = 1.f + softplusf_(s_o[133]);
            float sr0, sr1, sr2;
            {
                float q0 = s_o[130], q1 = s_o[131], q2 = s_o[132];
                float qm = fmaxf(q0, fmaxf(q1, q2));
                float e0 = expf(q0 - qm), e1 = expf(q1 - qm), e2 = expf(q2 - qm);
                float qs = e0 + e1 + e2;
                sr0 = e0 / qs; sr1 = e1 / qs; sr2 = e2 / qs;
            }
            float beta_w = softplusf_(s_o[264]);
            float g_w = sigmoidf_(s_o[265]);
            float gamma_w = 1.f + softplusf_(s_o[269]);
            float sw0, sw1, sw2;
            {
                float q0 = s_o[266], q1 = s_o[267], q2 = s_o[268];
                float qm = fmaxf(q0, fmaxf(q1, q2));
                float e0 = expf(q0 - qm), e1 = expf(q1 - qm), e2 = expf(q2 - qm);
                float qs = e0 + e1 + e2;
                sw0 = e0 / qs; sw1 = e1 / qs; sw2 = e2 / qs;
            }
            float nrm0 = sqrtf(pa.z), nrm1 = sqrtf(pb.z);
            float ev_r0 = __expf(beta_r * pa.x / (nrm0 * knr + EPS));
            float ev_r1 = __expf(beta_r * pb.x / (nrm1 * knr + EPS));
            float ev_w0 = __expf(beta_w * pa.y / (nrm0 * knw + EPS));
            float ev_w1 = __expf(beta_w * pb.y / (nrm1 * knw + EPS));
            s_evr[s0] = ev_r0; s_evr[s1] = ev_r1;
            s_evw[s0] = ev_w0; s_evw[s1] = ev_w1;
            {
                float vr = wredsum(ev_r0 + ev_r1), vw = wredsum(ev_w0 + ev_w1);
                if (!lane) { s_redA[wid] = vr; s_redB[wid] = vw; }
            }
            BAR_ATTN();                                     // B1
            float totr = 0.f, totw = 0.f;
#pragma unroll
            for (int i = 0; i < 8; i++) { totr += s_redA[i]; totw += s_redB[i]; }
            float inv_tr = 1.f / totr, inv_tw = 1.f / totw;
            const int sm1 = (s0 - 1) & (NS - 1), sp1 = (s1 + 1) & (NS - 1);
            float wpre0 = s_wpre[s0], wpre1 = s_wpre[s1];
            float wg0 = g_r * (ev_r0 * inv_tr) + (1.f - g_r) * wpre0;
            float wg1 = g_r * (ev_r1 * inv_tr) + (1.f - g_r) * wpre1;
            float wg_m = g_r * (s_evr[sm1] * inv_tr) + (1.f - g_r) * s_wpre[sm1];
            float wg_p = g_r * (s_evr[sp1] * inv_tr) + (1.f - g_r) * s_wpre[sp1];
            float wraw0 = __powf(sr0 * wg1 + sr1 * wg0 + sr2 * wg_m, gamma_r);
            float wraw1 = __powf(sr0 * wg_p + sr1 * wg1 + sr2 * wg0, gamma_r);
            s_wtmp[s0] = wraw0; s_wtmp[s1] = wraw1;
            {
                float v = wredsum(wraw0 + wraw1);
                if (!lane) s_knr[wid] = v;
            }
            BAR_ATTN();                                     // B2
            float sumr = 0.f;
#pragma unroll
            for (int i = 0; i < 8; i++) sumr += s_knr[i];
            float inv_r = 1.f / (sumr + EPS);
            float w_r0 = wraw0 * inv_r, w_r1 = wraw1 * inv_r;
            s_wr[s0] = w_r0; s_wr[s1] = w_r1;
            float wr_m = s_wtmp[sm1] * inv_r, wr_p = s_wtmp[sp1] * inv_r;
            float wgw0 = g_w * (ev_w0 * inv_tw) + (1.f - g_w) * w_r0;
            float wgw1 = g_w * (ev_w1 * inv_tw) + (1.f - g_w) * w_r1;
            float wgw_m = g_w * (s_evw[sm1] * inv_tw) + (1.f - g_w) * wr_m;
            float wgw_p = g_w * (s_evw[sp1] * inv_tw) + (1.f - g_w) * wr_p;
            float wraww0 = __powf(sw0 * wgw1 + sw1 * wgw0 + sw2 * wgw_m, gamma_w);
            float wraww1 = __powf(sw0 * wgw_p + sw1 * wgw1 + sw2 * wgw0, gamma_w);
            {
                float v = wredsum(wraww0 + wraww1);
                if (!lane) s_knw[wid] = v;
            }
            BAR_ATTN();                                     // B3
            float sumw = 0.f;
#pragma unroll
            for (int i = 0; i < 8; i++) sumw += s_knw[i];
            float w_w0 = wraww0 / (sumw + EPS), w_w1 = wraww1 / (sumw + EPS);
            s_ww[s0] = w_w0; s_ww[s1] = w_w1;
            s_wpre[s0] = w_w0; s_wpre[s1] = w_w1;
        } else {
            const int idx = tid - 256;
            const int k8 = idx >> 5, jq = idx & 31;
            const int k0 = k8 * 16;
            ull a01 = 0ull, a23 = 0ull;
#pragma unroll
            for (int k = 0; k < 16; k++) {
                float hv = s_h[k0 + k];
                float4 w = *(const float4*)(g_Wcat + (size_t)(k0 + k) * WLD + jq * 4);
                ffma2_f4(w, pack2(hv, hv), a01, a23);
            }
            float2 lo = unpack2(a01), hi = unpack2(a23);
            s_p4[544 + idx] = make_float4(lo.x, lo.y, hi.x, hi.y);
        }
        __syncthreads();                                    // B4

        // ==== P6: pass B — 2 global rows (batched loads), then 6 smem rows ====
        {
            ull wr01[4], wr23[4], ww01[4], ww23[4];
            {
                const float4* wrv = (const float4*)s_wr;
                const float4* wwv = (const float4*)s_ww;
#pragma unroll
                for (int c = 0; c < 4; c++) {
                    float4 a = wrv[c * 32 + lane];
                    float4 bq = wwv[c * 32 + lane];
                    wr01[c] = pack2(a.x, a.y);   wr23[c] = pack2(a.z, a.w);
                    ww01[c] = pack2(bq.x, bq.y); ww23[c] = pack2(bq.z, bq.w);
                }
            }
            {
                int g0 = wid * 2, g1 = g0 + 1;
                ulonglong2* rp0 = (ulonglong2*)(mU + (size_t)g0 * NS);
                ulonglong2* rp1 = (ulonglong2*)(mU + (size_t)g1 * NS);
                ulonglong2 vA[4], vB[4];
#pragma unroll
                for (int c = 0; c < 4; c++) { vA[c] = rp0[c * 32 + lane]; }
#pragma unroll
                for (int c = 0; c < 4; c++) { vB[c] = rp1[c * 32 + lane]; }
#pragma unroll
                for (int rr = 0; rr < 2; rr++) {
                    int m = ROWS_S + (rr ? g1 : g0);
                    ulonglong2* rp = rr ? rp1 : rp0;
                    ulonglong2* vv = rr ? vB : vA;
                    float2 ea = s_ea[m];
                    ull e2n = pack2(-ea.x, -ea.x), a2 = pack2(ea.y, ea.y);
                    ull r01 = 0ull, r23 = 0ull;
#pragma unroll
                    for (int c = 0; c < 4; c++) {
                        ulonglong2 v = vv[c];
                        r01 = ffma2(wr01[c], v.x, r01);
                        r23 = ffma2(wr23[c], v.y, r23);
                        ull t01 = fmul2(ww01[c], e2n);
                        ull t23 = fmul2(ww23[c], e2n);
                        ull n01 = ffma2(v.x, t01, v.x);
                        ull n23 = ffma2(v.y, t23, v.y);
                        n01 = ffma2(ww01[c], a2, n01);
                        n23 = ffma2(ww23[c], a2, n23);
                        ulonglong2 o2; o2.x = n01; o2.y = n23;
                        rp[c * 32 + lane] = o2;
                    }
                    float2 p0 = unpack2(r01), p1 = unpack2(r23);
                    float sumv = wredsum(p0.x + p0.y + p1.x + p1.y);
                    if (!lane) s_r[m] = sumv;
                }
            }
#pragma unroll
            for (int rr = 0; rr < 6; rr++) {
                int m = wid * 6 + rr;
                ulonglong2* rp = (ulonglong2*)(s_mem + (size_t)m * NS);
                float2 ea = s_ea[m];
                ull e2n = pack2(-ea.x, -ea.x), a2 = pack2(ea.y, ea.y);
                ull r01 = 0ull, r23 = 0ull;
#pragma unroll
                for (int c = 0; c < 4; c++) {
                    ulonglong2 v = rp[c * 32 + lane];
                    r01 = ffma2(wr01[c], v.x, r01);
                    r23 = ffma2(wr23[c], v.y, r23);
                    ull t01 = fmul2(ww01[c], e2n);
                    ull t23 = fmul2(ww23[c], e2n);
                    ull n01 = ffma2(v.x, t01, v.x);
                    ull n23 = ffma2(v.y, t23, v.y);
                    n01 = ffma2(ww01[c], a2, n01);
                    n23 = ffma2(ww23[c], a2, n23);
                    ulonglong2 o2; o2.x = n01; o2.y = n23;
                    rp[c * 32 + lane] = o2;
                }
                float2 p0 = unpack2(r01), p1 = unpack2(r23);
                float sumv = wredsum(p0.x + p0.y + p1.x + p1.y);
                if (!lane) s_r[m] = sumv;
            }
            __syncthreads();
        }
    }

    if (tid < 2 * DH) {
        size_t row = (size_t)(b * T_STEPS + T_STEPS - 1);
        g_hr[row * 2 * DH + tid] = (tid < DH) ? s_h[tid] : s_r[tid - DH];
    }
}

// out_gemm v2: 512 threads, f32x2 accumulators (FMA floor halved).
#define OUT_SMEM_FLOATS (32768 + 8192)
__global__ void __launch_bounds__(512) out_gemm(
    const float* __restrict__ Wout, const float* __restrict__ bout,
    float* __restrict__ out)
{
    extern __shared__ float sh[];
    float* shW = sh;            // 256 x 128
    float* As  = sh + 32768;    // 32 x 256
    const int tid = threadIdx.x, lane = tid & 31, wid = tid >> 5;
    const int rbase = blockIdx.x * 32;

    {
        float4* dst = (float4*)shW;
        const float4* src = (const float4*)Wout;
        for (int i = tid; i < 8192; i += 512) dst[i] = src[i];
        float4* dA = (float4*)As;
        const float4* sA = (const float4*)(g_hr + (size_t)rbase * 256);
        for (int i = tid; i < 2048; i += 512) dA[i] = sA[i];
    }
    __syncthreads();

    ull acc00 = 0ull, acc01 = 0ull, acc10 = 0ull, acc11 = 0ull;
    const int c0 = lane * 4;
    const int r0 = wid * 2;
#pragma unroll 4
    for (int k = 0; k < 256; k++) {
        float4 wv = ((const float4*)shW)[k * 32 + lane];
        ull w01 = pack2(wv.x, wv.y), w23 = pack2(wv.z, wv.w);
        float a0 = As[r0 * 256 + k], a1 = As[(r0 + 1) * 256 + k];
        ull a0b = pack2(a0, a0), a1b = pack2(a1, a1);
        acc00 = ffma2(w01, a0b, acc00);
        acc01 = ffma2(w23, a0b, acc01);
        acc10 = ffma2(w01, a1b, acc10);
        acc11 = ffma2(w23, a1b, acc11);
    }
    float4 bo = *(const float4*)(bout + c0);
    {
        float2 lo = unpack2(acc00), hi = unpack2(acc01);
        float4 o4 = make_float4(lo.x + bo.x, lo.y + bo.y, hi.x + bo.z, hi.y + bo.w);
        *(float4*)(out + (size_t)(rbase + r0) * 128 + c0) = o4;
        lo = unpack2(acc10); hi = unpack2(acc11);
        o4 = make_float4(lo.x + bo.x, lo.y + bo.y, hi.x + bo.z, hi.y + bo.w);
        *(float4*)(out + (size_t)(rbase + r0 + 1) * 128 + c0) = o4;
    }
}

extern "C" void kernel_launch(void* const* d_in, const int* in_sizes, int n_in,
                              void* d_out, int out_size)
{
    const float* x    = (const float*)d_in[0];
    const float* Wxh  = (const float*)d_in[1];
    const float* Whh  = (const float*)d_in[2];
    const float* Wrh  = (const float*)d_in[3];
    const float* bh   = (const float*)d_in[4];
    const float* Wout = (const float*)d_in[5];
    const float* bout = (const float*)d_in[6];
    const float* Wr   = (const float*)d_in[7];
    const float* br   = (const float*)d_in[8];
    const float* Ww   = (const float*)d_in[9];
    const float* bw   = (const float*)d_in[10];
    float* out = (float*)d_out;

    cudaFuncSetAttribute(ntm_kernel, cudaFuncAttributeMaxDynamicSharedMemorySize,
                         SMEM_FLOATS * sizeof(float));
    cudaFuncSetAttribute(out_gemm, cudaFuncAttributeMaxDynamicSharedMemorySize,
                         OUT_SMEM_FLOATS * sizeof(float));

    k_xh<<<BS, 512>>>(x, Wxh, bh);                      // 0
    k_minit<<<BS, 256>>>();                             // 1
    k_repack<<<128, 256>>>(Whh, Wrh, Wr, Ww);           // 2
    ntm_kernel<<<BS, NTHR, SMEM_FLOATS * sizeof(float)>>>(br, bw);  // 3 (ncu)
    out_gemm<<<BS * T_STEPS / 32, 512, OUT_SMEM_FLOATS * sizeof(float)>>>(
        Wout, bout, out);                               // 4
}